// round 1
// baseline (speedup 1.0000x reference)
#include <cuda_runtime.h>
#include <math.h>
#include <stdint.h>

// Problem constants
#define LQ 4096     // sequence length (both tensors)
#define CC 256      // channels
#define NH 8        // heads
#define HD 32       // head dim
#define CM 512      // concat / mlp dim

// ---------------------------------------------------------------------------
// Scratch (static __device__ globals; no runtime allocation)
// ---------------------------------------------------------------------------
static __device__ float g_P0[LQ * CM];                 // proj(x0) [l, 512]
static __device__ float g_P1[LQ * CM];                 // proj(x1)
static __device__ float g_SIM[(size_t)NH * LQ * LQ];   // 512 MB similarity
static __device__ float g_RMAX[NH * LQ];               // row softmax stats (over s)
static __device__ float g_RINV[NH * LQ];
static __device__ float g_CMAX[NH * LQ];               // col softmax stats (over l)
static __device__ float g_CINV[NH * LQ];
static __device__ float g_M0[LQ * CC];                 // attn out 0 [l, f*32+d]
static __device__ float g_M1[LQ * CC];                 // attn out 1
static __device__ float g_MM0[LQ * CC];                // merged 0
static __device__ float g_MM1[LQ * CC];
static __device__ float g_Y0[LQ * CM];                 // concat [x0 | ln(m0)]
static __device__ float g_Y1[LQ * CM];
static __device__ float g_G0[LQ * CM];                 // gelu(lin(Y))
static __device__ float g_G1[LQ * CM];
static __device__ float g_CV0[LQ * CC];                // conv out
static __device__ float g_CV1[LQ * CC];
static __device__ float g_WR[9 * CC * CM];             // repacked conv weights [k9][o][i]

// ---------------------------------------------------------------------------
// Generic fp32 tiled GEMM: C = scale*(A @ B^T) + bias, optional exact GELU.
// A: [M,K] row-major (lda), B: [N,K] row-major (ldb), C: [M,N] (ldc).
// Tiles 64x64x16, 256 threads, 4x4 micro-tile. M,N mult of 64; K mult of 16.
// blockIdx.z batches with element strides aS/bS/cS.
// ---------------------------------------------------------------------------
template <int GELU>
__global__ void gemm_abt(const float* __restrict__ A, int lda, long aS,
                         const float* __restrict__ B, int ldb, long bS,
                         float* __restrict__ C, int ldc, long cS,
                         int K, const float* __restrict__ bias, float scale) {
    __shared__ __align__(16) float As[16][64];
    __shared__ __align__(16) float Bs[16][64];
    A += (long)blockIdx.z * aS;
    B += (long)blockIdx.z * bS;
    C += (long)blockIdx.z * cS;
    const int m0 = blockIdx.y * 64;
    const int n0 = blockIdx.x * 64;
    const int t = threadIdx.x;
    const int tx = t % 16, ty = t / 16;
    const int lr = t / 4, lq = t % 4;  // loader: row in tile, float4 quad in k

    float acc[4][4] = {};
    for (int k0 = 0; k0 < K; k0 += 16) {
        float4 av = *(const float4*)(A + (size_t)(m0 + lr) * lda + k0 + lq * 4);
        As[lq * 4 + 0][lr] = av.x; As[lq * 4 + 1][lr] = av.y;
        As[lq * 4 + 2][lr] = av.z; As[lq * 4 + 3][lr] = av.w;
        float4 bv = *(const float4*)(B + (size_t)(n0 + lr) * ldb + k0 + lq * 4);
        Bs[lq * 4 + 0][lr] = bv.x; Bs[lq * 4 + 1][lr] = bv.y;
        Bs[lq * 4 + 2][lr] = bv.z; Bs[lq * 4 + 3][lr] = bv.w;
        __syncthreads();
#pragma unroll
        for (int kk = 0; kk < 16; kk++) {
            const float4 a4 = *(const float4*)&As[kk][ty * 4];
            const float4 b4 = *(const float4*)&Bs[kk][tx * 4];
            const float a[4] = {a4.x, a4.y, a4.z, a4.w};
            const float b[4] = {b4.x, b4.y, b4.z, b4.w};
#pragma unroll
            for (int i = 0; i < 4; i++)
#pragma unroll
                for (int j = 0; j < 4; j++) acc[i][j] += a[i] * b[j];
        }
        __syncthreads();
    }
#pragma unroll
    for (int i = 0; i < 4; i++) {
#pragma unroll
        for (int j = 0; j < 4; j++) {
            int n = n0 + tx * 4 + j;
            float v = acc[i][j] * scale;
            if (bias) v += bias[n];
            if (GELU) v = 0.5f * v * (1.0f + erff(v * 0.70710678118f));
            C[(size_t)(m0 + ty * 4 + i) * ldc + n] = v;
        }
    }
}

// ---------------------------------------------------------------------------
// Softmax stats over rows of SIM (axis s): one warp per (head,l) row.
// grid = NH*LQ/8 blocks, 256 threads.
// ---------------------------------------------------------------------------
__global__ void row_stats_kernel() {
    const int warp = threadIdx.x >> 5, lane = threadIdx.x & 31;
    const int row = blockIdx.x * 8 + warp;  // f*LQ + l
    const float* s = g_SIM + (size_t)row * LQ;
    float m = -1e30f, sum = 0.f;
    for (int i = lane; i < LQ; i += 32) {
        float x = s[i];
        if (x > m) { sum *= __expf(m - x); m = x; }
        sum += __expf(x - m);
    }
#pragma unroll
    for (int o = 16; o > 0; o >>= 1) {
        float mo = __shfl_xor_sync(0xffffffffu, m, o);
        float so = __shfl_xor_sync(0xffffffffu, sum, o);
        float M = fmaxf(m, mo);
        sum = sum * __expf(m - M) + so * __expf(mo - M);
        m = M;
    }
    if (lane == 0) { g_RMAX[row] = m; g_RINV[row] = 1.0f / sum; }
}

// Softmax stats over cols of SIM (axis l): one thread per (head,s) column.
// grid = (LQ/256, NH), 256 threads.
__global__ void col_stats_kernel() {
    const int col = blockIdx.x * 256 + threadIdx.x;
    const int f = blockIdx.y;
    const float* base = g_SIM + (size_t)f * LQ * LQ + col;
    float m = -1e30f, sum = 0.f;
    for (int l = 0; l < LQ; l++) {
        float x = base[(size_t)l * LQ];
        if (x > m) { sum *= __expf(m - x); m = x; }
        sum += __expf(x - m);
    }
    g_CMAX[f * LQ + col] = m;
    g_CINV[f * LQ + col] = 1.0f / sum;
}

// ---------------------------------------------------------------------------
// Attention AV: OUT[m, f*32+d] = sum_k softmax(sim)[m,k] * V[k, voff+f*32+d]
// TRANS=0: m=l, k=s, sim[m,k], stats=row stats, V = g_P1 (v1) -> g_M0
// TRANS=1: m=s, k=l, sim[k,m], stats=col stats, V = g_P0 (v0) -> g_M1
// Tiles: BM=64, BN=32(=HD), BK=32. 256 threads, 2x4 micro-tile.
// grid = (LQ/64, NH)
// ---------------------------------------------------------------------------
template <int TRANS>
__global__ void attn_av_kernel() {
    __shared__ __align__(16) float As[32][64];
    __shared__ __align__(16) float Bs[32][32];
    __shared__ float sM[64], sI[64];
    const int f = blockIdx.y;
    const int m0 = blockIdx.x * 64;
    const float* sim = g_SIM + (size_t)f * LQ * LQ;
    const float* V = (TRANS ? g_P0 : g_P1) + 256 + f * HD;  // v half, this head
    const float* SMAX = TRANS ? g_CMAX : g_RMAX;
    const float* SINV = TRANS ? g_CINV : g_RINV;
    float* OUT = TRANS ? g_M1 : g_M0;

    const int t = threadIdx.x;
    if (t < 64) {
        sM[t] = SMAX[f * LQ + m0 + t];
        sI[t] = SINV[f * LQ + m0 + t];
    }
    __syncthreads();

    const int tx = t % 8, ty = t / 8;  // ty 0..31
    float acc[2][4] = {};
    for (int k0 = 0; k0 < LQ; k0 += 32) {
#pragma unroll
        for (int i = 0; i < 8; i++) {
            int idx = t + i * 256;
            int mm, kk;
            float x;
            if (!TRANS) {
                mm = idx / 32; kk = idx % 32;
                x = sim[(size_t)(m0 + mm) * LQ + k0 + kk];
            } else {
                kk = idx / 64; mm = idx % 64;
                x = sim[(size_t)(k0 + kk) * LQ + m0 + mm];
            }
            As[kk][mm] = __expf(x - sM[mm]) * sI[mm];
        }
#pragma unroll
        for (int i = 0; i < 4; i++) {
            int idx = t + i * 256;
            int kk = idx / 32, d = idx % 32;
            Bs[kk][d] = V[(size_t)(k0 + kk) * CM + d];
        }
        __syncthreads();
#pragma unroll
        for (int kk = 0; kk < 32; kk++) {
            const float4 b4 = *(const float4*)&Bs[kk][tx * 4];
            const float b[4] = {b4.x, b4.y, b4.z, b4.w};
#pragma unroll
            for (int r = 0; r < 2; r++) {
                float a = As[kk][ty * 2 + r];
#pragma unroll
                for (int j = 0; j < 4; j++) acc[r][j] += a * b[j];
            }
        }
        __syncthreads();
    }
#pragma unroll
    for (int r = 0; r < 2; r++)
#pragma unroll
        for (int j = 0; j < 4; j++)
            OUT[(size_t)(m0 + ty * 2 + r) * CC + f * HD + tx * 4 + j] = acc[r][j];
}

// ---------------------------------------------------------------------------
// Conv weight repack: OIHW [256,512,3,3] -> [k9][o][i] for coalesced loads.
// ---------------------------------------------------------------------------
__global__ void repack_kernel(const float* __restrict__ w) {
    int i = blockIdx.x * 256 + threadIdx.x;  // total 256*512*9
    int o = i / (CM * 9);
    int rem = i % (CM * 9);
    int ci = rem / 9;
    int k9 = rem % 9;
    g_WR[(size_t)k9 * CC * CM + (size_t)o * CM + ci] = w[i];
}

// ---------------------------------------------------------------------------
// 3x3 SAME conv over [64,64,CM] -> [64,64,CC], implicit GEMM.
// Block: one image row (64 px) x 64 out channels. 256 threads, 4x4 micro.
// grid = (CC/64, 64)
// ---------------------------------------------------------------------------
__global__ void conv3_kernel(const float* __restrict__ Gin,
                             const float* __restrict__ bias,
                             float* __restrict__ Out) {
    __shared__ __align__(16) float As[32][64];
    __shared__ __align__(16) float Bs[32][64];
    const int row = blockIdx.y;
    const int n0 = blockIdx.x * 64;
    const int t = threadIdx.x;
    const int tx = t % 16, ty = t / 16;
    float acc[4][4] = {};

    for (int ky = 0; ky < 3; ky++) {
        const int ry = row + ky - 1;
        const bool rv = (ry >= 0 && ry < 64);
        for (int kx = 0; kx < 3; kx++) {
            const float* wof = g_WR + (size_t)(ky * 3 + kx) * CC * CM;
            for (int k0 = 0; k0 < CM; k0 += 32) {
#pragma unroll
                for (int i = 0; i < 8; i++) {
                    int idx = t + i * 256;
                    int x = idx / 32, kk = idx % 32;
                    int cx = x + kx - 1;
                    float v = 0.f;
                    if (rv && cx >= 0 && cx < 64)
                        v = Gin[((size_t)ry * 64 + cx) * CM + k0 + kk];
                    As[kk][x] = v;
                }
#pragma unroll
                for (int i = 0; i < 8; i++) {
                    int idx = t + i * 256;
                    int n = idx / 32, kk = idx % 32;
                    Bs[kk][n] = wof[(size_t)(n0 + n) * CM + k0 + kk];
                }
                __syncthreads();
#pragma unroll
                for (int kk = 0; kk < 32; kk++) {
                    const float4 a4 = *(const float4*)&As[kk][ty * 4];
                    const float4 b4 = *(const float4*)&Bs[kk][tx * 4];
                    const float a[4] = {a4.x, a4.y, a4.z, a4.w};
                    const float b[4] = {b4.x, b4.y, b4.z, b4.w};
#pragma unroll
                    for (int i = 0; i < 4; i++)
#pragma unroll
                        for (int j = 0; j < 4; j++) acc[i][j] += a[i] * b[j];
                }
                __syncthreads();
            }
        }
    }
#pragma unroll
    for (int i = 0; i < 4; i++)
#pragma unroll
        for (int j = 0; j < 4; j++)
            Out[((size_t)row * 64 + ty * 4 + i) * CC + n0 + tx * 4 + j] =
                acc[i][j] + bias[n0 + tx * 4 + j];
}

// ---------------------------------------------------------------------------
// LayerNorm helpers (256 threads == CC, one row per block)
// ---------------------------------------------------------------------------
__device__ __forceinline__ float block_sum_256(float v, volatile float* red) {
#pragma unroll
    for (int o = 16; o > 0; o >>= 1) v += __shfl_xor_sync(0xffffffffu, v, o);
    if ((threadIdx.x & 31) == 0) red[threadIdx.x >> 5] = v;
    __syncthreads();
    float s = red[0] + red[1] + red[2] + red[3] + red[4] + red[5] + red[6] + red[7];
    __syncthreads();
    return s;
}

// Build concat row: Y[r, 0:256] = X[r], Y[r, 256:512] = LN(Min[r])
__global__ void ln_concat_kernel(const float* __restrict__ Min,
                                 const float* __restrict__ Xin,
                                 const float* __restrict__ g,
                                 const float* __restrict__ b,
                                 float* __restrict__ Y) {
    __shared__ float red[8];
    const int r = blockIdx.x;
    const int t = threadIdx.x;
    float v = Min[(size_t)r * CC + t];
    float mean = block_sum_256(v, red) * (1.0f / CC);
    float d = v - mean;
    float var = block_sum_256(d * d, red) * (1.0f / CC);
    float o = d * rsqrtf(var + 1e-5f) * g[t] + b[t];
    Y[(size_t)r * CM + 256 + t] = o;
    Y[(size_t)r * CM + t] = Xin[(size_t)r * CC + t];
}

// Out[r] = LN(Cin[r]) + Xin[r]
__global__ void ln_res_kernel(const float* __restrict__ Cin,
                              const float* __restrict__ Xin,
                              const float* __restrict__ g,
                              const float* __restrict__ b,
                              float* __restrict__ Out) {
    __shared__ float red[8];
    const int r = blockIdx.x;
    const int t = threadIdx.x;
    float v = Cin[(size_t)r * CC + t];
    float mean = block_sum_256(v, red) * (1.0f / CC);
    float d = v - mean;
    float var = block_sum_256(d * d, red) * (1.0f / CC);
    float o = d * rsqrtf(var + 1e-5f) * g[t] + b[t];
    Out[(size_t)r * CC + t] = o + Xin[(size_t)r * CC + t];
}

// ---------------------------------------------------------------------------
// Launch
// ---------------------------------------------------------------------------
extern "C" void kernel_launch(void* const* d_in, const int* in_sizes, int n_in,
                              void* d_out, int out_size) {
    const float* x0 = (const float*)d_in[0];
    const float* x1 = (const float*)d_in[1];
    // d_in[2..5] = h0,w0,h1,w1 scalars (always 64) — unused
    const float* proj_w = (const float*)d_in[6];
    const float* proj_b = (const float*)d_in[7];
    const float* merge_w = (const float*)d_in[8];
    const float* merge_b = (const float*)d_in[9];
    const float* n0g = (const float*)d_in[10];
    const float* n0b = (const float*)d_in[11];
    const float* lin_w = (const float*)d_in[12];
    const float* lin_b = (const float*)d_in[13];
    const float* conv_w = (const float*)d_in[14];
    const float* conv_b = (const float*)d_in[15];
    const float* n1g = (const float*)d_in[16];
    const float* n1b = (const float*)d_in[17];
    float* out = (float*)d_out;

    float *P0, *P1, *SIMp, *M0p, *M1p, *MM0p, *MM1p, *Y0p, *Y1p, *G0p, *G1p, *CV0p, *CV1p;
    cudaGetSymbolAddress((void**)&P0, g_P0);
    cudaGetSymbolAddress((void**)&P1, g_P1);
    cudaGetSymbolAddress((void**)&SIMp, g_SIM);
    cudaGetSymbolAddress((void**)&M0p, g_M0);
    cudaGetSymbolAddress((void**)&M1p, g_M1);
    cudaGetSymbolAddress((void**)&MM0p, g_MM0);
    cudaGetSymbolAddress((void**)&MM1p, g_MM1);
    cudaGetSymbolAddress((void**)&Y0p, g_Y0);
    cudaGetSymbolAddress((void**)&Y1p, g_Y1);
    cudaGetSymbolAddress((void**)&G0p, g_G0);
    cudaGetSymbolAddress((void**)&G1p, g_G1);
    cudaGetSymbolAddress((void**)&CV0p, g_CV0);
    cudaGetSymbolAddress((void**)&CV1p, g_CV1);

    // 0) conv weight repack
    repack_kernel<<<(CC * CM * 9) / 256, 256>>>(conv_w);

    // 1) proj: P = x @ proj_w^T + proj_b   [4096,512]
    gemm_abt<0><<<dim3(CM / 64, LQ / 64, 1), 256>>>(
        x0, CC, 0, proj_w, CC, 0, P0, CM, 0, CC, proj_b, 1.0f);
    gemm_abt<0><<<dim3(CM / 64, LQ / 64, 1), 256>>>(
        x1, CC, 0, proj_w, CC, 0, P1, CM, 0, CC, proj_b, 1.0f);

    // 2) sim[f] = qk0 @ qk1^T / sqrt(32)   [8][4096,4096]
    gemm_abt<0><<<dim3(LQ / 64, LQ / 64, NH), 256>>>(
        P0, CM, HD, P1, CM, HD, SIMp, LQ, (long)LQ * LQ,
        HD, nullptr, 0.17677669529663687f);

    // 3) softmax stats (rows over s for a01, cols over l for a10)
    row_stats_kernel<<<NH * LQ / 8, 256>>>();
    col_stats_kernel<<<dim3(LQ / 256, NH), 256>>>();

    // 4) attention AV
    attn_av_kernel<0><<<dim3(LQ / 64, NH), 256>>>();  // m0 = a01 @ v1
    attn_av_kernel<1><<<dim3(LQ / 64, NH), 256>>>();  // m1 = a10^T @ v0

    // 5) merge: MM = M @ merge_w^T + merge_b   [4096,256]
    gemm_abt<0><<<dim3(CC / 64, LQ / 64, 1), 256>>>(
        M0p, CC, 0, merge_w, CC, 0, MM0p, CC, 0, CC, merge_b, 1.0f);
    gemm_abt<0><<<dim3(CC / 64, LQ / 64, 1), 256>>>(
        M1p, CC, 0, merge_w, CC, 0, MM1p, CC, 0, CC, merge_b, 1.0f);

    // 6) Y = [x | LN(MM)]   [4096,512]
    ln_concat_kernel<<<LQ, 256>>>(MM0p, x0, n0g, n0b, Y0p);
    ln_concat_kernel<<<LQ, 256>>>(MM1p, x1, n0g, n0b, Y1p);

    // 7) G = gelu(Y @ lin_w^T + lin_b)   [4096,512]
    gemm_abt<1><<<dim3(CM / 64, LQ / 64, 1), 256>>>(
        Y0p, CM, 0, lin_w, CM, 0, G0p, CM, 0, CM, lin_b, 1.0f);
    gemm_abt<1><<<dim3(CM / 64, LQ / 64, 1), 256>>>(
        Y1p, CM, 0, lin_w, CM, 0, G1p, CM, 0, CM, lin_b, 1.0f);

    // 8) conv 3x3 SAME + bias   [64,64,512] -> [64,64,256]
    conv3_kernel<<<dim3(CC / 64, 64), 256>>>(G0p, conv_b, CV0p);
    conv3_kernel<<<dim3(CC / 64, 64), 256>>>(G1p, conv_b, CV1p);

    // 9) out = LN(conv) + x
    ln_res_kernel<<<LQ, 256>>>(CV0p, x0, n1g, n1b, out);
    ln_res_kernel<<<LQ, 256>>>(CV1p, x1, n1g, n1b, out + (size_t)LQ * CC);
}

// round 3
// speedup vs baseline: 3.6045x; 3.6045x over previous
#include <cuda_runtime.h>
#include <math.h>
#include <stdint.h>

#define LQ 4096
#define CC 256
#define NH 8
#define HD 32
#define CM 512

// ---------------------------------------------------------------------------
// Scratch
// ---------------------------------------------------------------------------
static __device__ float g_P0[LQ * CM];
static __device__ float g_P1[LQ * CM];
static __device__ float g_SIM[(size_t)NH * LQ * LQ];   // holds E = exp(sim*scale)
static __device__ float g_RS[NH * LQ];                 // row sums of E
static __device__ float g_CS[NH * LQ];                 // col sums of E
static __device__ float g_M0[LQ * CC];
static __device__ float g_M1[LQ * CC];
static __device__ float g_MM0[LQ * CC];
static __device__ float g_MM1[LQ * CC];
static __device__ float g_Y0[LQ * CM];
static __device__ float g_Y1[LQ * CM];
static __device__ float g_G0[LQ * CM];
static __device__ float g_G1[LQ * CM];
static __device__ float g_CV0[LQ * CC];
static __device__ float g_CV1[LQ * CC];
static __device__ float g_WR[9 * CC * CM];             // conv weights [k9][o][i]

// ---------------------------------------------------------------------------
// tf32 helpers
// ---------------------------------------------------------------------------
__device__ __forceinline__ uint32_t f2tf(float x) {
    uint32_t r;
    asm("cvt.rna.tf32.f32 %0, %1;" : "=r"(r) : "f"(x));
    return r;
}

__device__ __forceinline__ void mma_tf32(float4& d, uint32_t a0, uint32_t a1,
                                         uint32_t a2, uint32_t a3,
                                         uint32_t b0, uint32_t b1) {
    asm volatile(
        "mma.sync.aligned.m16n8k8.row.col.f32.tf32.tf32.f32 "
        "{%0,%1,%2,%3}, {%4,%5,%6,%7}, {%8,%9}, {%0,%1,%2,%3};"
        : "+f"(d.x), "+f"(d.y), "+f"(d.z), "+f"(d.w)
        : "r"(a0), "r"(a1), "r"(a2), "r"(a3), "r"(b0), "r"(b1));
}

// Polynomial exp (no MUFU): exp(x) = 2^(x*log2e), 2^f by degree-5 Horner.
__device__ __forceinline__ float fexp(float x) {
    float t = x * 1.4426950408889634f;
    t = fminf(fmaxf(t, -126.0f), 126.0f);
    float r = rintf(t);
    float f = t - r;
    float p = 1.33335581e-3f;
    p = fmaf(p, f, 9.61812911e-3f);
    p = fmaf(p, f, 5.55041087e-2f);
    p = fmaf(p, f, 2.40226507e-1f);
    p = fmaf(p, f, 6.93147181e-1f);
    p = fmaf(p, f, 1.0f);
    return p * __int_as_float(((int)r + 127) << 23);
}

// ---------------------------------------------------------------------------
// tf32 GEMM: C = scale*(A @ B^T) + bias, optional exact GELU.
// Block 64x64, 256 thr (8 warps: 4x2), warp tile 16x32, BK=16.
// Shared tiles stored output-dim-major with stride 28 (conflict-free frags).
// ---------------------------------------------------------------------------
template <int GELU>
__global__ void gemm_tc(const float* __restrict__ A, int lda,
                        const float* __restrict__ B, int ldb,
                        float* __restrict__ C, int ldc,
                        int K, const float* __restrict__ bias, float scale) {
    __shared__ __align__(16) uint32_t As[64][28];
    __shared__ __align__(16) uint32_t Bs[64][28];
    const int m0 = blockIdx.y * 64;
    const int n0 = blockIdx.x * 64;
    const int t = threadIdx.x;
    const int warp = t >> 5, lane = t & 31;
    const int wm = warp >> 1, wn = warp & 1;
    const int g = lane >> 2, q = lane & 3;
    const int lr = t >> 2, lq = t & 3;

    float4 acc[4] = {};
    for (int k0 = 0; k0 < K; k0 += 16) {
        float4 av = *(const float4*)(A + (size_t)(m0 + lr) * lda + k0 + lq * 4);
        float4 bv = *(const float4*)(B + (size_t)(n0 + lr) * ldb + k0 + lq * 4);
        uint4 au = {f2tf(av.x), f2tf(av.y), f2tf(av.z), f2tf(av.w)};
        uint4 bu = {f2tf(bv.x), f2tf(bv.y), f2tf(bv.z), f2tf(bv.w)};
        *(uint4*)&As[lr][lq * 4] = au;
        *(uint4*)&Bs[lr][lq * 4] = bu;
        __syncthreads();
#pragma unroll
        for (int ks = 0; ks < 2; ks++) {
            const int kb = ks * 8;
            uint32_t a0 = As[wm * 16 + g][kb + q];
            uint32_t a1 = As[wm * 16 + g + 8][kb + q];
            uint32_t a2 = As[wm * 16 + g][kb + q + 4];
            uint32_t a3 = As[wm * 16 + g + 8][kb + q + 4];
#pragma unroll
            for (int j = 0; j < 4; j++) {
                uint32_t b0 = Bs[wn * 32 + j * 8 + g][kb + q];
                uint32_t b1 = Bs[wn * 32 + j * 8 + g][kb + q + 4];
                mma_tf32(acc[j], a0, a1, a2, a3, b0, b1);
            }
        }
        __syncthreads();
    }
    const int r0 = m0 + wm * 16 + g, r1 = r0 + 8;
#pragma unroll
    for (int j = 0; j < 4; j++) {
        const int c = n0 + wn * 32 + j * 8 + q * 2;
        float bx = bias ? bias[c] : 0.f, by = bias ? bias[c + 1] : 0.f;
        float v00 = acc[j].x * scale + bx, v01 = acc[j].y * scale + by;
        float v10 = acc[j].z * scale + bx, v11 = acc[j].w * scale + by;
        if (GELU) {
            v00 = 0.5f * v00 * (1.0f + erff(v00 * 0.70710678118f));
            v01 = 0.5f * v01 * (1.0f + erff(v01 * 0.70710678118f));
            v10 = 0.5f * v10 * (1.0f + erff(v10 * 0.70710678118f));
            v11 = 0.5f * v11 * (1.0f + erff(v11 * 0.70710678118f));
        }
        *(float2*)&C[(size_t)r0 * ldc + c] = make_float2(v00, v01);
        *(float2*)&C[(size_t)r1 * ldc + c] = make_float2(v10, v11);
    }
}

// ---------------------------------------------------------------------------
// sim + exp + row/col sums, fused. E = exp(scale * qk0 @ qk1^T), one pass.
// grid (64, 64, NH), block 256. Same tiling as gemm_tc, K=32.
// ---------------------------------------------------------------------------
__global__ void simexp_kernel() {
    __shared__ __align__(16) uint32_t As[64][28];
    __shared__ __align__(16) uint32_t Bs[64][28];
    const int f = blockIdx.z;
    const float* A = g_P0 + f * HD;
    const float* B = g_P1 + f * HD;
    float* E = g_SIM + (size_t)f * LQ * LQ;
    const int m0 = blockIdx.y * 64;
    const int n0 = blockIdx.x * 64;
    const int t = threadIdx.x;
    const int warp = t >> 5, lane = t & 31;
    const int wm = warp >> 1, wn = warp & 1;
    const int g = lane >> 2, q = lane & 3;
    const int lr = t >> 2, lq = t & 3;

    float4 acc[4] = {};
#pragma unroll
    for (int k0 = 0; k0 < 32; k0 += 16) {
        float4 av = *(const float4*)(A + (size_t)(m0 + lr) * CM + k0 + lq * 4);
        float4 bv = *(const float4*)(B + (size_t)(n0 + lr) * CM + k0 + lq * 4);
        uint4 au = {f2tf(av.x), f2tf(av.y), f2tf(av.z), f2tf(av.w)};
        uint4 bu = {f2tf(bv.x), f2tf(bv.y), f2tf(bv.z), f2tf(bv.w)};
        *(uint4*)&As[lr][lq * 4] = au;
        *(uint4*)&Bs[lr][lq * 4] = bu;
        __syncthreads();
#pragma unroll
        for (int ks = 0; ks < 2; ks++) {
            const int kb = ks * 8;
            uint32_t a0 = As[wm * 16 + g][kb + q];
            uint32_t a1 = As[wm * 16 + g + 8][kb + q];
            uint32_t a2 = As[wm * 16 + g][kb + q + 4];
            uint32_t a3 = As[wm * 16 + g + 8][kb + q + 4];
#pragma unroll
            for (int j = 0; j < 4; j++) {
                uint32_t b0 = Bs[wn * 32 + j * 8 + g][kb + q];
                uint32_t b1 = Bs[wn * 32 + j * 8 + g][kb + q + 4];
                mma_tf32(acc[j], a0, a1, a2, a3, b0, b1);
            }
        }
        __syncthreads();
    }
    const float SC = 0.17677669529663687f;
    const int r0 = m0 + wm * 16 + g, r1 = r0 + 8;
    float ex[4][4];
    float rs0 = 0.f, rs1 = 0.f;
#pragma unroll
    for (int j = 0; j < 4; j++) {
        ex[j][0] = fexp(acc[j].x * SC);
        ex[j][1] = fexp(acc[j].y * SC);
        ex[j][2] = fexp(acc[j].z * SC);
        ex[j][3] = fexp(acc[j].w * SC);
        const int c = n0 + wn * 32 + j * 8 + q * 2;
        *(float2*)&E[(size_t)r0 * LQ + c] = make_float2(ex[j][0], ex[j][1]);
        *(float2*)&E[(size_t)r1 * LQ + c] = make_float2(ex[j][2], ex[j][3]);
        rs0 += ex[j][0] + ex[j][1];
        rs1 += ex[j][2] + ex[j][3];
    }
    // row partial sums: reduce over q (cols within warp stripe)
    rs0 += __shfl_xor_sync(0xffffffffu, rs0, 1);
    rs0 += __shfl_xor_sync(0xffffffffu, rs0, 2);
    rs1 += __shfl_xor_sync(0xffffffffu, rs1, 1);
    rs1 += __shfl_xor_sync(0xffffffffu, rs1, 2);
    if (q == 0) {
        atomicAdd(&g_RS[f * LQ + r0], rs0);
        atomicAdd(&g_RS[f * LQ + r1], rs1);
    }
    // col partial sums: reduce over g (rows within warp stripe)
#pragma unroll
    for (int j = 0; j < 4; j++) {
        float cs0 = ex[j][0] + ex[j][2];
        float cs1 = ex[j][1] + ex[j][3];
        cs0 += __shfl_xor_sync(0xffffffffu, cs0, 4);
        cs0 += __shfl_xor_sync(0xffffffffu, cs0, 8);
        cs0 += __shfl_xor_sync(0xffffffffu, cs0, 16);
        cs1 += __shfl_xor_sync(0xffffffffu, cs1, 4);
        cs1 += __shfl_xor_sync(0xffffffffu, cs1, 8);
        cs1 += __shfl_xor_sync(0xffffffffu, cs1, 16);
        if (lane < 4) {
            const int c = n0 + wn * 32 + j * 8 + lane * 2;
            atomicAdd(&g_CS[f * LQ + c], cs0);
            atomicAdd(&g_CS[f * LQ + c + 1], cs1);
        }
    }
}

// ---------------------------------------------------------------------------
// AV: OUT[m, f*32+d] = (1/sum[m]) * sum_k E'[m,k] * V[k,d]
// TRANS=0: E'[m,k]=E[m,k] (row softmax), V=v1, OUT=g_M0
// TRANS=1: E'[m,k]=E[k,m] (col softmax), V=v0, OUT=g_M1
// Block 128x32x(BK=32), 256 thr, 8 warps (warp=16 rows x 32 cols).
// ---------------------------------------------------------------------------
template <int TRANS>
__global__ void attn_av_tc() {
    __shared__ __align__(16) uint32_t EsM[TRANS ? 1 : 128][TRANS ? 1 : 36];
    __shared__ __align__(16) uint32_t EsK[TRANS ? 32 : 1][TRANS ? 136 : 1];
    __shared__ __align__(16) uint32_t Vs[32][40];
    __shared__ float sInv[128];
    const int f = blockIdx.y;
    const int m0 = blockIdx.x * 128;
    const float* E = g_SIM + (size_t)f * LQ * LQ;
    const float* V = (TRANS ? g_P0 : g_P1) + 256 + f * HD;
    const float* SUM = TRANS ? g_CS : g_RS;
    float* OUT = TRANS ? g_M1 : g_M0;
    const int t = threadIdx.x;
    if (t < 128) sInv[t] = __frcp_rn(SUM[f * LQ + m0 + t]);
    const int warp = t >> 5, lane = t & 31;
    const int g = lane >> 2, q = lane & 3;

    float4 acc[4] = {};
    for (int k0 = 0; k0 < LQ; k0 += 32) {
        if (!TRANS) {
#pragma unroll
            for (int i = 0; i < 4; i++) {
                int fid = t + i * 256;
                int mm = fid >> 3, k4 = (fid & 7) * 4;
                float4 v = *(const float4*)(E + (size_t)(m0 + mm) * LQ + k0 + k4);
                uint4 u = {f2tf(v.x), f2tf(v.y), f2tf(v.z), f2tf(v.w)};
                *(uint4*)&EsM[mm][k4] = u;
            }
        } else {
#pragma unroll
            for (int i = 0; i < 4; i++) {
                int fid = t + i * 256;
                int kk = fid >> 5, m4 = (fid & 31) * 4;
                float4 v = *(const float4*)(E + (size_t)(k0 + kk) * LQ + m0 + m4);
                uint4 u = {f2tf(v.x), f2tf(v.y), f2tf(v.z), f2tf(v.w)};
                *(uint4*)&EsK[kk][m4] = u;
            }
        }
        {
            int kk = t >> 3, d4 = (t & 7) * 4;
            float4 v = *(const float4*)(V + (size_t)(k0 + kk) * CM + d4);
            uint4 u = {f2tf(v.x), f2tf(v.y), f2tf(v.z), f2tf(v.w)};
            *(uint4*)&Vs[kk][d4] = u;
        }
        __syncthreads();
#pragma unroll
        for (int ks = 0; ks < 4; ks++) {
            const int kb = ks * 8;
            uint32_t a0, a1, a2, a3;
            if (!TRANS) {
                a0 = EsM[warp * 16 + g][kb + q];
                a1 = EsM[warp * 16 + g + 8][kb + q];
                a2 = EsM[warp * 16 + g][kb + q + 4];
                a3 = EsM[warp * 16 + g + 8][kb + q + 4];
            } else {
                a0 = EsK[kb + q][warp * 16 + g];
                a1 = EsK[kb + q][warp * 16 + g + 8];
                a2 = EsK[kb + q + 4][warp * 16 + g];
                a3 = EsK[kb + q + 4][warp * 16 + g + 8];
            }
#pragma unroll
            for (int j = 0; j < 4; j++) {
                uint32_t b0 = Vs[kb + q][j * 8 + g];
                uint32_t b1 = Vs[kb + q + 4][j * 8 + g];
                mma_tf32(acc[j], a0, a1, a2, a3, b0, b1);
            }
        }
        __syncthreads();
    }
    const int r0 = m0 + warp * 16 + g, r1 = r0 + 8;
    const float i0 = sInv[warp * 16 + g], i1 = sInv[warp * 16 + g + 8];
#pragma unroll
    for (int j = 0; j < 4; j++) {
        const int c = f * HD + j * 8 + q * 2;
        *(float2*)&OUT[(size_t)r0 * CC + c] = make_float2(acc[j].x * i0, acc[j].y * i0);
        *(float2*)&OUT[(size_t)r1 * CC + c] = make_float2(acc[j].z * i1, acc[j].w * i1);
    }
}

// ---------------------------------------------------------------------------
// conv weight repack OIHW -> [k9][o][i]
// ---------------------------------------------------------------------------
__global__ void repack_kernel(const float* __restrict__ w) {
    int i = blockIdx.x * 256 + threadIdx.x;
    int o = i / (CM * 9);
    int rem = i % (CM * 9);
    int ci = rem / 9;
    int k9 = rem % 9;
    g_WR[(size_t)k9 * CC * CM + (size_t)o * CM + ci] = w[i];
}

__global__ void zero_kernel() {
    int i = blockIdx.x * 256 + threadIdx.x;
    g_RS[i] = 0.f;
    g_CS[i] = 0.f;
}

// ---------------------------------------------------------------------------
// 3x3 SAME conv [64,64,CM] -> [64,64,CC], tf32 implicit GEMM.
// Block: 32 pixels x 64 outch, 128 thr (4 warps 2x2), BK=32.
// grid (CC/64=4, 4096/32=128)
// ---------------------------------------------------------------------------
__global__ void conv3_tc(const float* __restrict__ Gin,
                         const float* __restrict__ bias,
                         float* __restrict__ Out) {
    __shared__ __align__(16) uint32_t As[32][36];
    __shared__ __align__(16) uint32_t Bs[64][36];
    const int p0 = blockIdx.y * 32;
    const int n0 = blockIdx.x * 64;
    const int t = threadIdx.x;
    const int warp = t >> 5, lane = t & 31;
    const int wm = warp >> 1, wn = warp & 1;
    const int g = lane >> 2, q = lane & 3;

    float4 acc[4] = {};
    for (int ky = 0; ky < 3; ky++) {
        for (int kx = 0; kx < 3; kx++) {
            const float* wof = g_WR + (size_t)(ky * 3 + kx) * CC * CM;
            for (int k0 = 0; k0 < CM; k0 += 32) {
#pragma unroll
                for (int i = 0; i < 2; i++) {
                    int fid = t + i * 128;
                    int x = fid >> 3, k4 = (fid & 7) * 4;
                    int p = p0 + x;
                    int cx = (p & 63) + kx - 1;
                    int sp = p + (ky - 1) * 64 + (kx - 1);
                    uint4 u = {0u, 0u, 0u, 0u};
                    if ((unsigned)cx < 64u && (unsigned)sp < 4096u) {
                        float4 v = *(const float4*)(Gin + (size_t)sp * CM + k0 + k4);
                        u.x = f2tf(v.x); u.y = f2tf(v.y);
                        u.z = f2tf(v.z); u.w = f2tf(v.w);
                    }
                    *(uint4*)&As[x][k4] = u;
                }
#pragma unroll
                for (int i = 0; i < 4; i++) {
                    int fid = t + i * 128;
                    int n = fid >> 3, k4 = (fid & 7) * 4;
                    float4 v = *(const float4*)(wof + (size_t)(n0 + n) * CM + k0 + k4);
                    uint4 u = {f2tf(v.x), f2tf(v.y), f2tf(v.z), f2tf(v.w)};
                    *(uint4*)&Bs[n][k4] = u;
                }
                __syncthreads();
#pragma unroll
                for (int ks = 0; ks < 4; ks++) {
                    const int kb = ks * 8;
                    uint32_t a0 = As[wm * 16 + g][kb + q];
                    uint32_t a1 = As[wm * 16 + g + 8][kb + q];
                    uint32_t a2 = As[wm * 16 + g][kb + q + 4];
                    uint32_t a3 = As[wm * 16 + g + 8][kb + q + 4];
#pragma unroll
                    for (int j = 0; j < 4; j++) {
                        uint32_t b0 = Bs[wn * 32 + j * 8 + g][kb + q];
                        uint32_t b1 = Bs[wn * 32 + j * 8 + g][kb + q + 4];
                        mma_tf32(acc[j], a0, a1, a2, a3, b0, b1);
                    }
                }
                __syncthreads();
            }
        }
    }
    const int r0 = p0 + wm * 16 + g, r1 = r0 + 8;
#pragma unroll
    for (int j = 0; j < 4; j++) {
        const int c = n0 + wn * 32 + j * 8 + q * 2;
        float bx = bias[c], by = bias[c + 1];
        *(float2*)&Out[(size_t)r0 * CC + c] = make_float2(acc[j].x + bx, acc[j].y + by);
        *(float2*)&Out[(size_t)r1 * CC + c] = make_float2(acc[j].z + bx, acc[j].w + by);
    }
}

// ---------------------------------------------------------------------------
// LayerNorm (256 threads = CC, one row per block)
// ---------------------------------------------------------------------------
__device__ __forceinline__ float block_sum_256(float v, volatile float* red) {
#pragma unroll
    for (int o = 16; o > 0; o >>= 1) v += __shfl_xor_sync(0xffffffffu, v, o);
    if ((threadIdx.x & 31) == 0) red[threadIdx.x >> 5] = v;
    __syncthreads();
    float s = red[0] + red[1] + red[2] + red[3] + red[4] + red[5] + red[6] + red[7];
    __syncthreads();
    return s;
}

__global__ void ln_concat_kernel(const float* __restrict__ Min,
                                 const float* __restrict__ Xin,
                                 const float* __restrict__ g,
                                 const float* __restrict__ b,
                                 float* __restrict__ Y) {
    __shared__ float red[8];
    const int r = blockIdx.x;
    const int t = threadIdx.x;
    float v = Min[(size_t)r * CC + t];
    float mean = block_sum_256(v, red) * (1.0f / CC);
    float d = v - mean;
    float var = block_sum_256(d * d, red) * (1.0f / CC);
    float o = d * rsqrtf(var + 1e-5f) * g[t] + b[t];
    Y[(size_t)r * CM + 256 + t] = o;
    Y[(size_t)r * CM + t] = Xin[(size_t)r * CC + t];
}

__global__ void ln_res_kernel(const float* __restrict__ Cin,
                              const float* __restrict__ Xin,
                              const float* __restrict__ g,
                              const float* __restrict__ b,
                              float* __restrict__ Out) {
    __shared__ float red[8];
    const int r = blockIdx.x;
    const int t = threadIdx.x;
    float v = Cin[(size_t)r * CC + t];
    float mean = block_sum_256(v, red) * (1.0f / CC);
    float d = v - mean;
    float var = block_sum_256(d * d, red) * (1.0f / CC);
    float o = d * rsqrtf(var + 1e-5f) * g[t] + b[t];
    Out[(size_t)r * CC + t] = o + Xin[(size_t)r * CC + t];
}

// ---------------------------------------------------------------------------
// Launch
// ---------------------------------------------------------------------------
extern "C" void kernel_launch(void* const* d_in, const int* in_sizes, int n_in,
                              void* d_out, int out_size) {
    const float* x0 = (const float*)d_in[0];
    const float* x1 = (const float*)d_in[1];
    const float* proj_w = (const float*)d_in[6];
    const float* proj_b = (const float*)d_in[7];
    const float* merge_w = (const float*)d_in[8];
    const float* merge_b = (const float*)d_in[9];
    const float* n0g = (const float*)d_in[10];
    const float* n0b = (const float*)d_in[11];
    const float* lin_w = (const float*)d_in[12];
    const float* lin_b = (const float*)d_in[13];
    const float* conv_w = (const float*)d_in[14];
    const float* conv_b = (const float*)d_in[15];
    const float* n1g = (const float*)d_in[16];
    const float* n1b = (const float*)d_in[17];
    float* out = (float*)d_out;

    float *P0, *P1, *M0p, *M1p, *MM0p, *MM1p, *Y0p, *Y1p, *G0p, *G1p, *CV0p, *CV1p;
    cudaGetSymbolAddress((void**)&P0, g_P0);
    cudaGetSymbolAddress((void**)&P1, g_P1);
    cudaGetSymbolAddress((void**)&M0p, g_M0);
    cudaGetSymbolAddress((void**)&M1p, g_M1);
    cudaGetSymbolAddress((void**)&MM0p, g_MM0);
    cudaGetSymbolAddress((void**)&MM1p, g_MM1);
    cudaGetSymbolAddress((void**)&Y0p, g_Y0);
    cudaGetSymbolAddress((void**)&Y1p, g_Y1);
    cudaGetSymbolAddress((void**)&G0p, g_G0);
    cudaGetSymbolAddress((void**)&G1p, g_G1);
    cudaGetSymbolAddress((void**)&CV0p, g_CV0);
    cudaGetSymbolAddress((void**)&CV1p, g_CV1);

    zero_kernel<<<NH * LQ / 256, 256>>>();
    repack_kernel<<<(CC * CM * 9) / 256, 256>>>(conv_w);

    // proj: P = x @ proj_w^T + proj_b  [4096,512]
    gemm_tc<0><<<dim3(CM / 64, LQ / 64), 256>>>(x0, CC, proj_w, CC, P0, CM, CC, proj_b, 1.0f);
    gemm_tc<0><<<dim3(CM / 64, LQ / 64), 256>>>(x1, CC, proj_w, CC, P1, CM, CC, proj_b, 1.0f);

    // E = exp(scale * qk0 @ qk1^T) + row/col sums
    simexp_kernel<<<dim3(LQ / 64, LQ / 64, NH), 256>>>();

    // AV
    attn_av_tc<0><<<dim3(LQ / 128, NH), 256>>>();
    attn_av_tc<1><<<dim3(LQ / 128, NH), 256>>>();

    // merge
    gemm_tc<0><<<dim3(CC / 64, LQ / 64), 256>>>(M0p, CC, merge_w, CC, MM0p, CC, CC, merge_b, 1.0f);
    gemm_tc<0><<<dim3(CC / 64, LQ / 64), 256>>>(M1p, CC, merge_w, CC, MM1p, CC, CC, merge_b, 1.0f);

    // concat with LN
    ln_concat_kernel<<<LQ, 256>>>(MM0p, x0, n0g, n0b, Y0p);
    ln_concat_kernel<<<LQ, 256>>>(MM1p, x1, n0g, n0b, Y1p);

    // lin + gelu
    gemm_tc<1><<<dim3(CM / 64, LQ / 64), 256>>>(Y0p, CM, lin_w, CM, G0p, CM, CM, lin_b, 1.0f);
    gemm_tc<1><<<dim3(CM / 64, LQ / 64), 256>>>(Y1p, CM, lin_w, CM, G1p, CM, CM, lin_b, 1.0f);

    // conv
    conv3_tc<<<dim3(CC / 64, LQ / 32), 128>>>(G0p, conv_b, CV0p);
    conv3_tc<<<dim3(CC / 64, LQ / 32), 128>>>(G1p, conv_b, CV1p);

    // LN + residual
    ln_res_kernel<<<LQ, 256>>>(CV0p, x0, n1g, n1b, out);
    ln_res_kernel<<<LQ, 256>>>(CV1p, x1, n1g, n1b, out + (size_t)LQ * CC);
}

// round 4
// speedup vs baseline: 4.8035x; 1.3326x over previous
#include <cuda_runtime.h>
#include <math.h>
#include <stdint.h>

#define LQ 4096
#define CC 256
#define NH 8
#define HD 32
#define CM 512
#define GPW 66   // padded conv width

// ---------------------------------------------------------------------------
// Scratch
// ---------------------------------------------------------------------------
static __device__ uint32_t g_P0[LQ * CM];          // proj(x0), tf32 bits
static __device__ uint32_t g_P1[LQ * CM];          // proj(x1), tf32 bits
static __device__ float    g_CS[NH * LQ];          // col sums of E (atomic)
static __device__ float    g_M0[LQ * CC];
static __device__ float    g_M1[LQ * CC];          // atomic-accumulated
static __device__ float    g_MM0[LQ * CC];
static __device__ float    g_MM1[LQ * CC];
static __device__ float    g_Y0[LQ * CM];
static __device__ float    g_Y1[LQ * CM];
static __device__ uint32_t g_GP0[GPW * GPW * CM];  // padded gelu(lin), tf32
static __device__ uint32_t g_GP1[GPW * GPW * CM];
static __device__ float    g_CV0[LQ * CC];
static __device__ float    g_CV1[LQ * CC];
static __device__ uint32_t g_WR[9 * CC * CM];      // conv weights [k9][o][i], tf32

// ---------------------------------------------------------------------------
// helpers
// ---------------------------------------------------------------------------
__device__ __forceinline__ uint32_t f2tf(float x) {
    uint32_t r;
    asm("cvt.rna.tf32.f32 %0, %1;" : "=r"(r) : "f"(x));
    return r;
}

__device__ __forceinline__ void mma_tf32(float4& d, uint32_t a0, uint32_t a1,
                                         uint32_t a2, uint32_t a3,
                                         uint32_t b0, uint32_t b1) {
    asm volatile(
        "mma.sync.aligned.m16n8k8.row.col.f32.tf32.tf32.f32 "
        "{%0,%1,%2,%3}, {%4,%5,%6,%7}, {%8,%9}, {%0,%1,%2,%3};"
        : "+f"(d.x), "+f"(d.y), "+f"(d.z), "+f"(d.w)
        : "r"(a0), "r"(a1), "r"(a2), "r"(a3), "r"(b0), "r"(b1));
}

// Polynomial exp on FMA pipe (no MUFU).
__device__ __forceinline__ float fexp(float x) {
    float t = x * 1.4426950408889634f;
    t = fminf(fmaxf(t, -126.0f), 126.0f);
    float r = rintf(t);
    float f = t - r;
    float p = 1.33335581e-3f;
    p = fmaf(p, f, 9.61812911e-3f);
    p = fmaf(p, f, 5.55041087e-2f);
    p = fmaf(p, f, 2.40226507e-1f);
    p = fmaf(p, f, 6.93147181e-1f);
    p = fmaf(p, f, 1.0f);
    return p * __int_as_float(((int)r + 127) << 23);
}

// ---------------------------------------------------------------------------
// tf32 GEMM: C = A @ B^T + bias. MODE: 0 = fp32 C, 1 = tf32 C into padded
// conv layout (with GELU), 2 = tf32 C plain. Block 64x64, 256 thr, BK=16.
// ---------------------------------------------------------------------------
template <int GELU, int MODE>
__global__ void gemm_tc(const float* __restrict__ A, int lda,
                        const float* __restrict__ B, int ldb,
                        void* __restrict__ Cv, int ldc,
                        int K, const float* __restrict__ bias) {
    __shared__ __align__(16) uint32_t As[64][28];
    __shared__ __align__(16) uint32_t Bs[64][28];
    const int m0 = blockIdx.y * 64;
    const int n0 = blockIdx.x * 64;
    const int t = threadIdx.x;
    const int warp = t >> 5, lane = t & 31;
    const int wm = warp >> 1, wn = warp & 1;
    const int g = lane >> 2, q = lane & 3;
    const int lr = t >> 2, lq = t & 3;

    float4 acc[4] = {};
    for (int k0 = 0; k0 < K; k0 += 16) {
        float4 av = *(const float4*)(A + (size_t)(m0 + lr) * lda + k0 + lq * 4);
        float4 bv = *(const float4*)(B + (size_t)(n0 + lr) * ldb + k0 + lq * 4);
        uint4 au = {f2tf(av.x), f2tf(av.y), f2tf(av.z), f2tf(av.w)};
        uint4 bu = {f2tf(bv.x), f2tf(bv.y), f2tf(bv.z), f2tf(bv.w)};
        *(uint4*)&As[lr][lq * 4] = au;
        *(uint4*)&Bs[lr][lq * 4] = bu;
        __syncthreads();
#pragma unroll
        for (int ks = 0; ks < 2; ks++) {
            const int kb = ks * 8;
            uint32_t a0 = As[wm * 16 + g][kb + q];
            uint32_t a1 = As[wm * 16 + g + 8][kb + q];
            uint32_t a2 = As[wm * 16 + g][kb + q + 4];
            uint32_t a3 = As[wm * 16 + g + 8][kb + q + 4];
#pragma unroll
            for (int j = 0; j < 4; j++) {
                uint32_t b0 = Bs[wn * 32 + j * 8 + g][kb + q];
                uint32_t b1 = Bs[wn * 32 + j * 8 + g][kb + q + 4];
                mma_tf32(acc[j], a0, a1, a2, a3, b0, b1);
            }
        }
        __syncthreads();
    }
    const int r0 = m0 + wm * 16 + g, r1 = r0 + 8;
#pragma unroll
    for (int j = 0; j < 4; j++) {
        const int c = n0 + wn * 32 + j * 8 + q * 2;
        float bx = bias ? bias[c] : 0.f, by = bias ? bias[c + 1] : 0.f;
        float v00 = acc[j].x + bx, v01 = acc[j].y + by;
        float v10 = acc[j].z + bx, v11 = acc[j].w + by;
        if (GELU) {
            v00 = 0.5f * v00 * (1.0f + erff(v00 * 0.70710678118f));
            v01 = 0.5f * v01 * (1.0f + erff(v01 * 0.70710678118f));
            v10 = 0.5f * v10 * (1.0f + erff(v10 * 0.70710678118f));
            v11 = 0.5f * v11 * (1.0f + erff(v11 * 0.70710678118f));
        }
        if (MODE == 0) {
            float* C = (float*)Cv;
            *(float2*)&C[(size_t)r0 * ldc + c] = make_float2(v00, v01);
            *(float2*)&C[(size_t)r1 * ldc + c] = make_float2(v10, v11);
        } else if (MODE == 1) {
            uint32_t* C = (uint32_t*)Cv;
            size_t o0 = ((size_t)((r0 >> 6) + 1) * GPW + (r0 & 63) + 1) * CM + c;
            size_t o1 = ((size_t)((r1 >> 6) + 1) * GPW + (r1 & 63) + 1) * CM + c;
            *(uint2*)&C[o0] = make_uint2(f2tf(v00), f2tf(v01));
            *(uint2*)&C[o1] = make_uint2(f2tf(v10), f2tf(v11));
        } else {
            uint32_t* C = (uint32_t*)Cv;
            *(uint2*)&C[(size_t)r0 * ldc + c] = make_uint2(f2tf(v00), f2tf(v01));
            *(uint2*)&C[(size_t)r1 * ldc + c] = make_uint2(f2tf(v10), f2tf(v11));
        }
    }
}

// ---------------------------------------------------------------------------
// Fused flash-style dual-softmax attention. Block = (64-row l-tile, head f).
// Loops s-tiles; E never hits DRAM. m0 register-accumulated + row sums local;
// m1 & col sums via fp32 atomics. P0/P1 are tf32 bits.
// grid (LQ/64, NH), 256 threads.
// ---------------------------------------------------------------------------
__global__ void attn_fused() {
    __shared__ __align__(16) uint32_t Ks[64][36];   // qk1 tile (s x k) / q0 staging
    __shared__ __align__(16) uint32_t V1s[64][36];  // v1 tile (s x d) / v0 staging
    __shared__ __align__(16) uint32_t V0s[64][36];  // v0 tile (l x d), persistent
    __shared__ __align__(16) uint32_t Es[64][68];   // E tf32 (l x s)
    __shared__ float sRS[2][64];
    const int f = blockIdx.y;
    const int l0 = blockIdx.x * 64;
    const uint32_t* QK0 = g_P0 + f * HD;
    const uint32_t* QK1 = g_P1 + f * HD;
    const uint32_t* V1g = g_P1 + 256 + f * HD;
    const uint32_t* V0g = g_P0 + 256 + f * HD;
    const int t = threadIdx.x;
    const int warp = t >> 5, lane = t & 31;
    const int wm = warp >> 1, wn = warp & 1;
    const int g = lane >> 2, q = lane & 3;

    // stage q0 (into Ks) and v0 (into V0s)
#pragma unroll
    for (int i = 0; i < 2; i++) {
        int idx = t + i * 256;
        int row = idx >> 3, c4 = (idx & 7) * 4;
        *(uint4*)&Ks[row][c4] = *(const uint4*)(QK0 + (size_t)(l0 + row) * CM + c4);
        *(uint4*)&V0s[row][c4] = *(const uint4*)(V0g + (size_t)(l0 + row) * CM + c4);
    }
    __syncthreads();
    // persistent q0 A-fragments (K=32 -> 4 k-subtiles)
    uint32_t aq[4][4];
#pragma unroll
    for (int ks = 0; ks < 4; ks++) {
        const int kb = ks * 8;
        aq[ks][0] = Ks[wm * 16 + g][kb + q];
        aq[ks][1] = Ks[wm * 16 + g + 8][kb + q];
        aq[ks][2] = Ks[wm * 16 + g][kb + q + 4];
        aq[ks][3] = Ks[wm * 16 + g + 8][kb + q + 4];
    }
    __syncthreads();

    const float SC = 0.17677669529663687f;
    float4 macc[2] = {};
    float rs0 = 0.f, rs1 = 0.f;

    for (int s0 = 0; s0 < LQ; s0 += 64) {
        // load qk1 & v1 tiles
#pragma unroll
        for (int i = 0; i < 2; i++) {
            int idx = t + i * 256;
            int row = idx >> 3, c4 = (idx & 7) * 4;
            *(uint4*)&Ks[row][c4] = *(const uint4*)(QK1 + (size_t)(s0 + row) * CM + c4);
            *(uint4*)&V1s[row][c4] = *(const uint4*)(V1g + (size_t)(s0 + row) * CM + c4);
        }
        __syncthreads();
        // S = q0 @ qk1^T  (64l x 64s x 32k)
        float4 sacc[4] = {};
#pragma unroll
        for (int ks = 0; ks < 4; ks++) {
            const int kb = ks * 8;
#pragma unroll
            for (int j = 0; j < 4; j++) {
                uint32_t b0 = Ks[wn * 32 + j * 8 + g][kb + q];
                uint32_t b1 = Ks[wn * 32 + j * 8 + g][kb + q + 4];
                mma_tf32(sacc[j], aq[ks][0], aq[ks][1], aq[ks][2], aq[ks][3], b0, b1);
            }
        }
        // E = exp(S*SC); sums; store tf32 to Es
#pragma unroll
        for (int j = 0; j < 4; j++) {
            float e0 = fexp(sacc[j].x * SC);
            float e1 = fexp(sacc[j].y * SC);
            float e2 = fexp(sacc[j].z * SC);
            float e3 = fexp(sacc[j].w * SC);
            rs0 += e0 + e1;
            rs1 += e2 + e3;
            float cs0 = e0 + e2, cs1 = e1 + e3;
            cs0 += __shfl_xor_sync(0xffffffffu, cs0, 4);
            cs0 += __shfl_xor_sync(0xffffffffu, cs0, 8);
            cs0 += __shfl_xor_sync(0xffffffffu, cs0, 16);
            cs1 += __shfl_xor_sync(0xffffffffu, cs1, 4);
            cs1 += __shfl_xor_sync(0xffffffffu, cs1, 8);
            cs1 += __shfl_xor_sync(0xffffffffu, cs1, 16);
            if (lane < 4) {
                const int c = s0 + wn * 32 + j * 8 + lane * 2;
                atomicAdd(&g_CS[f * LQ + c], cs0);
                atomicAdd(&g_CS[f * LQ + c + 1], cs1);
            }
            const int ec = wn * 32 + j * 8 + q * 2;
            *(uint2*)&Es[wm * 16 + g][ec] = make_uint2(f2tf(e0), f2tf(e1));
            *(uint2*)&Es[wm * 16 + g + 8][ec] = make_uint2(f2tf(e2), f2tf(e3));
        }
        __syncthreads();
        // GEMM1: m0 += E @ v1   (64l x 32d x 64s)
#pragma unroll
        for (int ks = 0; ks < 8; ks++) {
            const int kb = ks * 8;
            uint32_t a0 = Es[wm * 16 + g][kb + q];
            uint32_t a1 = Es[wm * 16 + g + 8][kb + q];
            uint32_t a2 = Es[wm * 16 + g][kb + q + 4];
            uint32_t a3 = Es[wm * 16 + g + 8][kb + q + 4];
#pragma unroll
            for (int j = 0; j < 2; j++) {
                uint32_t b0 = V1s[kb + q][wn * 16 + j * 8 + g];
                uint32_t b1 = V1s[kb + q + 4][wn * 16 + j * 8 + g];
                mma_tf32(macc[j], a0, a1, a2, a3, b0, b1);
            }
        }
        // GEMM2: m1part = E^T @ v0  (64s x 32d x 64l)
        float4 nacc[2] = {};
#pragma unroll
        for (int ks = 0; ks < 8; ks++) {
            const int kb = ks * 8;
            uint32_t a0 = Es[kb + q][wm * 16 + g];
            uint32_t a1 = Es[kb + q][wm * 16 + g + 8];
            uint32_t a2 = Es[kb + q + 4][wm * 16 + g];
            uint32_t a3 = Es[kb + q + 4][wm * 16 + g + 8];
#pragma unroll
            for (int j = 0; j < 2; j++) {
                uint32_t b0 = V0s[kb + q][wn * 16 + j * 8 + g];
                uint32_t b1 = V0s[kb + q + 4][wn * 16 + j * 8 + g];
                mma_tf32(nacc[j], a0, a1, a2, a3, b0, b1);
            }
        }
        const int sr0 = s0 + wm * 16 + g, sr1 = sr0 + 8;
#pragma unroll
        for (int j = 0; j < 2; j++) {
            const int c = f * HD + wn * 16 + j * 8 + q * 2;
            atomicAdd(&g_M1[(size_t)sr0 * CC + c], nacc[j].x);
            atomicAdd(&g_M1[(size_t)sr0 * CC + c + 1], nacc[j].y);
            atomicAdd(&g_M1[(size_t)sr1 * CC + c], nacc[j].z);
            atomicAdd(&g_M1[(size_t)sr1 * CC + c + 1], nacc[j].w);
        }
        __syncthreads();
    }
    // finalize row sums (combine wn halves) and write normalized m0
    rs0 += __shfl_xor_sync(0xffffffffu, rs0, 1);
    rs0 += __shfl_xor_sync(0xffffffffu, rs0, 2);
    rs1 += __shfl_xor_sync(0xffffffffu, rs1, 1);
    rs1 += __shfl_xor_sync(0xffffffffu, rs1, 2);
    if (q == 0) {
        sRS[wn][wm * 16 + g] = rs0;
        sRS[wn][wm * 16 + g + 8] = rs1;
    }
    __syncthreads();
    const int r0 = wm * 16 + g, r1 = r0 + 8;
    const float i0 = __frcp_rn(sRS[0][r0] + sRS[1][r0]);
    const float i1 = __frcp_rn(sRS[0][r1] + sRS[1][r1]);
#pragma unroll
    for (int j = 0; j < 2; j++) {
        const int c = f * HD + wn * 16 + j * 8 + q * 2;
        *(float2*)&g_M0[(size_t)(l0 + r0) * CC + c] =
            make_float2(macc[j].x * i0, macc[j].y * i0);
        *(float2*)&g_M0[(size_t)(l0 + r1) * CC + c] =
            make_float2(macc[j].z * i1, macc[j].w * i1);
    }
}

// normalize m1 by col sums
__global__ void norm_m1_kernel() {
    const int r = blockIdx.x, c = threadIdx.x;
    g_M1[(size_t)r * CC + c] *= __frcp_rn(g_CS[(c >> 5) * LQ + r]);
}

// ---------------------------------------------------------------------------
// conv weight repack OIHW -> [k9][o][i], tf32
// ---------------------------------------------------------------------------
__global__ void repack_kernel(const float* __restrict__ w) {
    int i = blockIdx.x * 256 + threadIdx.x;
    int o = i / (CM * 9);
    int rem = i % (CM * 9);
    int ci = rem / 9;
    int k9 = rem % 9;
    g_WR[(size_t)k9 * CC * CM + (size_t)o * CM + ci] = f2tf(w[i]);
}

// ---------------------------------------------------------------------------
// 3x3 SAME conv on padded tf32 input [66][66][CM] -> [64,64,CC].
// Block = one output row (64 px) x 64 oc, 256 thr. A slab reused for 3 kx.
// grid (CC/64, 64)
// ---------------------------------------------------------------------------
__global__ void conv3p(const uint32_t* __restrict__ Gp,
                       const float* __restrict__ bias,
                       float* __restrict__ Out) {
    __shared__ __align__(16) uint32_t As[66][36];
    __shared__ __align__(16) uint32_t Bs[3][64][36];
    const int py = blockIdx.y;
    const int n0 = blockIdx.x * 64;
    const int t = threadIdx.x;
    const int warp = t >> 5, lane = t & 31;
    const int wm = warp >> 1, wn = warp & 1;
    const int g = lane >> 2, q = lane & 3;

    float4 acc[4] = {};
    for (int ky = 0; ky < 3; ky++) {
        const uint32_t* arow = Gp + (size_t)(py + ky) * GPW * CM;
        const uint32_t* wky = g_WR + (size_t)(ky * 3) * CC * CM;
        for (int kc = 0; kc < 16; kc++) {
            const int k0 = kc * 32;
            // A: 66 rows x 32 ch = 528 float4
#pragma unroll
            for (int i = 0; i < 3; i++) {
                int idx = t + i * 256;
                if (idx < 528) {
                    int row = idx >> 3, c4 = (idx & 7) * 4;
                    *(uint4*)&As[row][c4] =
                        *(const uint4*)(arow + (size_t)row * CM + k0 + c4);
                }
            }
            // B: 3 kx x 64 oc x 32 ch = 1536 float4
#pragma unroll
            for (int i = 0; i < 6; i++) {
                int idx = t + i * 256;
                int kx = idx >> 9, w = idx & 511;
                int row = w >> 3, c4 = (w & 7) * 4;
                *(uint4*)&Bs[kx][row][c4] =
                    *(const uint4*)(wky + (size_t)kx * CC * CM +
                                    (size_t)(n0 + row) * CM + k0 + c4);
            }
            __syncthreads();
#pragma unroll
            for (int kx = 0; kx < 3; kx++) {
#pragma unroll
                for (int ks = 0; ks < 4; ks++) {
                    const int kb = ks * 8;
                    uint32_t a0 = As[wm * 16 + g + kx][kb + q];
                    uint32_t a1 = As[wm * 16 + g + 8 + kx][kb + q];
                    uint32_t a2 = As[wm * 16 + g + kx][kb + q + 4];
                    uint32_t a3 = As[wm * 16 + g + 8 + kx][kb + q + 4];
#pragma unroll
                    for (int j = 0; j < 4; j++) {
                        uint32_t b0 = Bs[kx][wn * 32 + j * 8 + g][kb + q];
                        uint32_t b1 = Bs[kx][wn * 32 + j * 8 + g][kb + q + 4];
                        mma_tf32(acc[j], a0, a1, a2, a3, b0, b1);
                    }
                }
            }
            __syncthreads();
        }
    }
    const int p0 = wm * 16 + g, p1 = p0 + 8;
#pragma unroll
    for (int j = 0; j < 4; j++) {
        const int c = n0 + wn * 32 + j * 8 + q * 2;
        float bx = bias[c], by = bias[c + 1];
        *(float2*)&Out[((size_t)py * 64 + p0) * CC + c] =
            make_float2(acc[j].x + bx, acc[j].y + by);
        *(float2*)&Out[((size_t)py * 64 + p1) * CC + c] =
            make_float2(acc[j].z + bx, acc[j].w + by);
    }
}

// ---------------------------------------------------------------------------
// LayerNorm (256 threads = CC, one row per block)
// ---------------------------------------------------------------------------
__device__ __forceinline__ float block_sum_256(float v, volatile float* red) {
#pragma unroll
    for (int o = 16; o > 0; o >>= 1) v += __shfl_xor_sync(0xffffffffu, v, o);
    if ((threadIdx.x & 31) == 0) red[threadIdx.x >> 5] = v;
    __syncthreads();
    float s = red[0] + red[1] + red[2] + red[3] + red[4] + red[5] + red[6] + red[7];
    __syncthreads();
    return s;
}

__global__ void ln_concat_kernel(const float* __restrict__ Min,
                                 const float* __restrict__ Xin,
                                 const float* __restrict__ g,
                                 const float* __restrict__ b,
                                 float* __restrict__ Y) {
    __shared__ float red[8];
    const int r = blockIdx.x;
    const int t = threadIdx.x;
    float v = Min[(size_t)r * CC + t];
    float mean = block_sum_256(v, red) * (1.0f / CC);
    float d = v - mean;
    float var = block_sum_256(d * d, red) * (1.0f / CC);
    float o = d * rsqrtf(var + 1e-5f) * g[t] + b[t];
    Y[(size_t)r * CM + 256 + t] = o;
    Y[(size_t)r * CM + t] = Xin[(size_t)r * CC + t];
}

__global__ void ln_res_kernel(const float* __restrict__ Cin,
                              const float* __restrict__ Xin,
                              const float* __restrict__ g,
                              const float* __restrict__ b,
                              float* __restrict__ Out) {
    __shared__ float red[8];
    const int r = blockIdx.x;
    const int t = threadIdx.x;
    float v = Cin[(size_t)r * CC + t];
    float mean = block_sum_256(v, red) * (1.0f / CC);
    float d = v - mean;
    float var = block_sum_256(d * d, red) * (1.0f / CC);
    float o = d * rsqrtf(var + 1e-5f) * g[t] + b[t];
    Out[(size_t)r * CC + t] = o + Xin[(size_t)r * CC + t];
}

// ---------------------------------------------------------------------------
// Launch
// ---------------------------------------------------------------------------
extern "C" void kernel_launch(void* const* d_in, const int* in_sizes, int n_in,
                              void* d_out, int out_size) {
    const float* x0 = (const float*)d_in[0];
    const float* x1 = (const float*)d_in[1];
    const float* proj_w = (const float*)d_in[6];
    const float* proj_b = (const float*)d_in[7];
    const float* merge_w = (const float*)d_in[8];
    const float* merge_b = (const float*)d_in[9];
    const float* n0g = (const float*)d_in[10];
    const float* n0b = (const float*)d_in[11];
    const float* lin_w = (const float*)d_in[12];
    const float* lin_b = (const float*)d_in[13];
    const float* conv_w = (const float*)d_in[14];
    const float* conv_b = (const float*)d_in[15];
    const float* n1g = (const float*)d_in[16];
    const float* n1b = (const float*)d_in[17];
    float* out = (float*)d_out;

    void *P0, *P1, *CSp, *M0p, *M1p, *MM0p, *MM1p, *Y0p, *Y1p, *GP0p, *GP1p, *CV0p, *CV1p;
    cudaGetSymbolAddress(&P0, g_P0);
    cudaGetSymbolAddress(&P1, g_P1);
    cudaGetSymbolAddress(&CSp, g_CS);
    cudaGetSymbolAddress(&M0p, g_M0);
    cudaGetSymbolAddress(&M1p, g_M1);
    cudaGetSymbolAddress(&MM0p, g_MM0);
    cudaGetSymbolAddress(&MM1p, g_MM1);
    cudaGetSymbolAddress(&Y0p, g_Y0);
    cudaGetSymbolAddress(&Y1p, g_Y1);
    cudaGetSymbolAddress(&GP0p, g_GP0);
    cudaGetSymbolAddress(&GP1p, g_GP1);
    cudaGetSymbolAddress(&CV0p, g_CV0);
    cudaGetSymbolAddress(&CV1p, g_CV1);

    // zero atomic accumulators + padded conv buffers (borders)
    cudaMemsetAsync(M1p, 0, (size_t)LQ * CC * 4);
    cudaMemsetAsync(CSp, 0, (size_t)NH * LQ * 4);
    cudaMemsetAsync(GP0p, 0, (size_t)GPW * GPW * CM * 4);
    cudaMemsetAsync(GP1p, 0, (size_t)GPW * GPW * CM * 4);

    repack_kernel<<<(CC * CM * 9) / 256, 256>>>(conv_w);

    // proj -> tf32 P
    gemm_tc<0, 2><<<dim3(CM / 64, LQ / 64), 256>>>(x0, CC, proj_w, CC, P0, CM, CC, proj_b);
    gemm_tc<0, 2><<<dim3(CM / 64, LQ / 64), 256>>>(x1, CC, proj_w, CC, P1, CM, CC, proj_b);

    // fused attention
    attn_fused<<<dim3(LQ / 64, NH), 256>>>();
    norm_m1_kernel<<<LQ, 256>>>();

    // merge
    gemm_tc<0, 0><<<dim3(CC / 64, LQ / 64), 256>>>((const float*)M0p, CC, merge_w, CC, MM0p, CC, CC, merge_b);
    gemm_tc<0, 0><<<dim3(CC / 64, LQ / 64), 256>>>((const float*)M1p, CC, merge_w, CC, MM1p, CC, CC, merge_b);

    // concat with LN
    ln_concat_kernel<<<LQ, 256>>>((const float*)MM0p, x0, n0g, n0b, (float*)Y0p);
    ln_concat_kernel<<<LQ, 256>>>((const float*)MM1p, x1, n0g, n0b, (float*)Y1p);

    // lin + gelu -> padded tf32
    gemm_tc<1, 1><<<dim3(CM / 64, LQ / 64), 256>>>((const float*)Y0p, CM, lin_w, CM, GP0p, CM, CM, lin_b);
    gemm_tc<1, 1><<<dim3(CM / 64, LQ / 64), 256>>>((const float*)Y1p, CM, lin_w, CM, GP1p, CM, CM, lin_b);

    // conv
    conv3p<<<dim3(CC / 64, 64), 256>>>((const uint32_t*)GP0p, conv_b, (float*)CV0p);
    conv3p<<<dim3(CC / 64, 64), 256>>>((const uint32_t*)GP1p, conv_b, (float*)CV1p);

    // LN + residual
    ln_res_kernel<<<LQ, 256>>>((const float*)CV0p, x0, n1g, n1b, out);
    ln_res_kernel<<<LQ, 256>>>((const float*)CV1p, x1, n1g, n1b, out + (size_t)LQ * CC);
}

// round 6
// speedup vs baseline: 4.9145x; 1.0231x over previous
#include <cuda_runtime.h>
#include <math.h>
#include <stdint.h>

#define LQ 4096
#define CC 256
#define NH 8
#define HD 32
#define CM 512
#define GPW 66   // padded conv width

// ---------------------------------------------------------------------------
// Scratch
// ---------------------------------------------------------------------------
static __device__ uint32_t g_P0[LQ * CM];          // proj(x0), tf32 bits
static __device__ uint32_t g_P1[LQ * CM];          // proj(x1), tf32 bits
static __device__ float    g_M0[LQ * CC];
static __device__ float    g_M1[LQ * CC];
static __device__ float    g_MM0[LQ * CC];
static __device__ float    g_MM1[LQ * CC];
static __device__ float    g_Y0[LQ * CM];
static __device__ float    g_Y1[LQ * CM];
static __device__ uint32_t g_GP0[GPW * GPW * CM];  // padded gelu(lin), tf32
static __device__ uint32_t g_GP1[GPW * GPW * CM];
static __device__ float    g_CV0[LQ * CC];
static __device__ float    g_CV1[LQ * CC];
static __device__ uint32_t g_WR[9 * CC * CM];      // conv weights [k9][o][i], tf32

// ---------------------------------------------------------------------------
// helpers
// ---------------------------------------------------------------------------
__device__ __forceinline__ uint32_t f2tf(float x) {
    uint32_t r;
    asm("cvt.rna.tf32.f32 %0, %1;" : "=r"(r) : "f"(x));
    return r;
}

__device__ __forceinline__ void mma_tf32(float4& d, uint32_t a0, uint32_t a1,
                                         uint32_t a2, uint32_t a3,
                                         uint32_t b0, uint32_t b1) {
    asm volatile(
        "mma.sync.aligned.m16n8k8.row.col.f32.tf32.tf32.f32 "
        "{%0,%1,%2,%3}, {%4,%5,%6,%7}, {%8,%9}, {%0,%1,%2,%3};"
        : "+f"(d.x), "+f"(d.y), "+f"(d.z), "+f"(d.w)
        : "r"(a0), "r"(a1), "r"(a2), "r"(a3), "r"(b0), "r"(b1));
}

// Polynomial exp on FMA pipe (no MUFU).
__device__ __forceinline__ float fexp(float x) {
    float t = x * 1.4426950408889634f;
    t = fminf(fmaxf(t, -126.0f), 126.0f);
    float r = rintf(t);
    float f = t - r;
    float p = 1.33335581e-3f;
    p = fmaf(p, f, 9.61812911e-3f);
    p = fmaf(p, f, 5.55041087e-2f);
    p = fmaf(p, f, 2.40226507e-1f);
    p = fmaf(p, f, 6.93147181e-1f);
    p = fmaf(p, f, 1.0f);
    return p * __int_as_float(((int)r + 127) << 23);
}

__device__ __forceinline__ uint32_t sptr(const void* p) {
    return (uint32_t)__cvta_generic_to_shared(p);
}
#define CP16(dst, src) \
    asm volatile("cp.async.cg.shared.global [%0], [%1], 16;" :: "r"(dst), "l"(src))

// ---------------------------------------------------------------------------
// tf32 GEMM: C = A @ B^T + bias. MODE: 0 = fp32 C, 1 = tf32 C into padded
// conv layout (with GELU), 2 = tf32 C plain. Block 64x64, 256 thr, BK=16.
// ---------------------------------------------------------------------------
template <int GELU, int MODE>
__global__ void gemm_tc(const float* __restrict__ A, int lda,
                        const float* __restrict__ B, int ldb,
                        void* __restrict__ Cv, int ldc,
                        int K, const float* __restrict__ bias) {
    __shared__ __align__(16) uint32_t As[64][28];
    __shared__ __align__(16) uint32_t Bs[64][28];
    const int m0 = blockIdx.y * 64;
    const int n0 = blockIdx.x * 64;
    const int t = threadIdx.x;
    const int warp = t >> 5, lane = t & 31;
    const int wm = warp >> 1, wn = warp & 1;
    const int g = lane >> 2, q = lane & 3;
    const int lr = t >> 2, lq = t & 3;

    float4 acc[4] = {};
    for (int k0 = 0; k0 < K; k0 += 16) {
        float4 av = *(const float4*)(A + (size_t)(m0 + lr) * lda + k0 + lq * 4);
        float4 bv = *(const float4*)(B + (size_t)(n0 + lr) * ldb + k0 + lq * 4);
        uint4 au = {f2tf(av.x), f2tf(av.y), f2tf(av.z), f2tf(av.w)};
        uint4 bu = {f2tf(bv.x), f2tf(bv.y), f2tf(bv.z), f2tf(bv.w)};
        *(uint4*)&As[lr][lq * 4] = au;
        *(uint4*)&Bs[lr][lq * 4] = bu;
        __syncthreads();
#pragma unroll
        for (int ks = 0; ks < 2; ks++) {
            const int kb = ks * 8;
            uint32_t a0 = As[wm * 16 + g][kb + q];
            uint32_t a1 = As[wm * 16 + g + 8][kb + q];
            uint32_t a2 = As[wm * 16 + g][kb + q + 4];
            uint32_t a3 = As[wm * 16 + g + 8][kb + q + 4];
#pragma unroll
            for (int j = 0; j < 4; j++) {
                uint32_t b0 = Bs[wn * 32 + j * 8 + g][kb + q];
                uint32_t b1 = Bs[wn * 32 + j * 8 + g][kb + q + 4];
                mma_tf32(acc[j], a0, a1, a2, a3, b0, b1);
            }
        }
        __syncthreads();
    }
    const int r0 = m0 + wm * 16 + g, r1 = r0 + 8;
#pragma unroll
    for (int j = 0; j < 4; j++) {
        const int c = n0 + wn * 32 + j * 8 + q * 2;
        float bx = bias ? bias[c] : 0.f, by = bias ? bias[c + 1] : 0.f;
        float v00 = acc[j].x + bx, v01 = acc[j].y + by;
        float v10 = acc[j].z + bx, v11 = acc[j].w + by;
        if (GELU) {
            v00 = 0.5f * v00 * (1.0f + erff(v00 * 0.70710678118f));
            v01 = 0.5f * v01 * (1.0f + erff(v01 * 0.70710678118f));
            v10 = 0.5f * v10 * (1.0f + erff(v10 * 0.70710678118f));
            v11 = 0.5f * v11 * (1.0f + erff(v11 * 0.70710678118f));
        }
        if (MODE == 0) {
            float* C = (float*)Cv;
            *(float2*)&C[(size_t)r0 * ldc + c] = make_float2(v00, v01);
            *(float2*)&C[(size_t)r1 * ldc + c] = make_float2(v10, v11);
        } else if (MODE == 1) {
            uint32_t* C = (uint32_t*)Cv;
            size_t o0 = ((size_t)((r0 >> 6) + 1) * GPW + (r0 & 63) + 1) * CM + c;
            size_t o1 = ((size_t)((r1 >> 6) + 1) * GPW + (r1 & 63) + 1) * CM + c;
            *(uint2*)&C[o0] = make_uint2(f2tf(v00), f2tf(v01));
            *(uint2*)&C[o1] = make_uint2(f2tf(v10), f2tf(v11));
        } else {
            uint32_t* C = (uint32_t*)Cv;
            *(uint2*)&C[(size_t)r0 * ldc + c] = make_uint2(f2tf(v00), f2tf(v01));
            *(uint2*)&C[(size_t)r1 * ldc + c] = make_uint2(f2tf(v10), f2tf(v11));
        }
    }
}

// ---------------------------------------------------------------------------
// One-sided flash attention: OUT[m, f*HD+d] = rownorm(exp(SC*A_qk@B_qk^T))@B_v
// Call (qk0,qk1,v1)->m0 and (qk1,qk0,v0)->m1. No atomics; register accum.
// Double-buffered cp.async K/V tile loads. Dynamic smem (54.8 KB).
// grid (LQ/64, NH), 256 thr.
// ---------------------------------------------------------------------------
struct AttnSmem {
    uint32_t Kb[2][64][36];
    uint32_t Vbs[2][64][36];
    uint32_t Es[64][68];
    float sRS[2][64];
};

__global__ __launch_bounds__(256, 3) void attn_one(
        const uint32_t* __restrict__ QKa, const uint32_t* __restrict__ QKb,
        const uint32_t* __restrict__ Vg, float* __restrict__ OUT) {
    extern __shared__ __align__(16) char smem_raw[];
    AttnSmem& S = *reinterpret_cast<AttnSmem*>(smem_raw);
    const int f = blockIdx.y;
    const int l0 = blockIdx.x * 64;
    const uint32_t* A = QKa + f * HD;
    const uint32_t* B = QKb + f * HD;
    const uint32_t* V = Vg + f * HD;
    const int t = threadIdx.x;
    const int warp = t >> 5, lane = t & 31;
    const int wm = warp >> 1, wn = warp & 1;
    const int g = lane >> 2, q = lane & 3;
    const int lrow = t >> 3, lc4 = (t & 7) * 4;

    // prefetch s-tile 0 (async) + stage q tile into Es (sync loads)
#pragma unroll
    for (int i = 0; i < 2; i++) {
        int row = lrow + i * 32;
        CP16(sptr(&S.Kb[0][row][lc4]), B + (size_t)row * CM + lc4);
        CP16(sptr(&S.Vbs[0][row][lc4]), V + (size_t)row * CM + lc4);
    }
    asm volatile("cp.async.commit_group;");
#pragma unroll
    for (int i = 0; i < 2; i++) {
        int idx = t + i * 256;
        int row = idx >> 3, c4 = (idx & 7) * 4;
        *(uint4*)&S.Es[row][c4] = *(const uint4*)(A + (size_t)(l0 + row) * CM + c4);
    }
    __syncthreads();
    uint32_t aq[4][4];
#pragma unroll
    for (int ks = 0; ks < 4; ks++) {
        const int kb = ks * 8;
        aq[ks][0] = S.Es[wm * 16 + g][kb + q];
        aq[ks][1] = S.Es[wm * 16 + g + 8][kb + q];
        aq[ks][2] = S.Es[wm * 16 + g][kb + q + 4];
        aq[ks][3] = S.Es[wm * 16 + g + 8][kb + q + 4];
    }
    asm volatile("cp.async.wait_group 0;" ::: "memory");
    __syncthreads();

    const float SC = 0.17677669529663687f;
    float4 macc[2] = {};
    float rs0 = 0.f, rs1 = 0.f;

    for (int it = 0; it < 64; it++) {
        const int cur = it & 1;
        if (it < 63) {
            const uint32_t* Bn = B + (size_t)(it + 1) * 64 * CM;
            const uint32_t* Vn = V + (size_t)(it + 1) * 64 * CM;
#pragma unroll
            for (int i = 0; i < 2; i++) {
                int row = lrow + i * 32;
                CP16(sptr(&S.Kb[cur ^ 1][row][lc4]), Bn + (size_t)row * CM + lc4);
                CP16(sptr(&S.Vbs[cur ^ 1][row][lc4]), Vn + (size_t)row * CM + lc4);
            }
            asm volatile("cp.async.commit_group;");
        }
        // S = qA @ qB^T (64x64x32)
        float4 sacc[4] = {};
#pragma unroll
        for (int ks = 0; ks < 4; ks++) {
            const int kb = ks * 8;
#pragma unroll
            for (int j = 0; j < 4; j++) {
                uint32_t b0 = S.Kb[cur][wn * 32 + j * 8 + g][kb + q];
                uint32_t b1 = S.Kb[cur][wn * 32 + j * 8 + g][kb + q + 4];
                mma_tf32(sacc[j], aq[ks][0], aq[ks][1], aq[ks][2], aq[ks][3], b0, b1);
            }
        }
        // E = exp(S*SC), accumulate row sums, park tf32 E in smem
#pragma unroll
        for (int j = 0; j < 4; j++) {
            float e0 = fexp(sacc[j].x * SC);
            float e1 = fexp(sacc[j].y * SC);
            float e2 = fexp(sacc[j].z * SC);
            float e3 = fexp(sacc[j].w * SC);
            rs0 += e0 + e1;
            rs1 += e2 + e3;
            const int ec = wn * 32 + j * 8 + q * 2;
            *(uint2*)&S.Es[wm * 16 + g][ec] = make_uint2(f2tf(e0), f2tf(e1));
            *(uint2*)&S.Es[wm * 16 + g + 8][ec] = make_uint2(f2tf(e2), f2tf(e3));
        }
        __syncthreads();
        // OUT += E @ V (64x32x64)
#pragma unroll
        for (int ks = 0; ks < 8; ks++) {
            const int kb = ks * 8;
            uint32_t a0 = S.Es[wm * 16 + g][kb + q];
            uint32_t a1 = S.Es[wm * 16 + g + 8][kb + q];
            uint32_t a2 = S.Es[wm * 16 + g][kb + q + 4];
            uint32_t a3 = S.Es[wm * 16 + g + 8][kb + q + 4];
#pragma unroll
            for (int j = 0; j < 2; j++) {
                uint32_t b0 = S.Vbs[cur][kb + q][wn * 16 + j * 8 + g];
                uint32_t b1 = S.Vbs[cur][kb + q + 4][wn * 16 + j * 8 + g];
                mma_tf32(macc[j], a0, a1, a2, a3, b0, b1);
            }
        }
        asm volatile("cp.async.wait_group 0;" ::: "memory");
        __syncthreads();
    }
    // combine row sums across wn halves, normalize, write
    rs0 += __shfl_xor_sync(0xffffffffu, rs0, 1);
    rs0 += __shfl_xor_sync(0xffffffffu, rs0, 2);
    rs1 += __shfl_xor_sync(0xffffffffu, rs1, 1);
    rs1 += __shfl_xor_sync(0xffffffffu, rs1, 2);
    if (q == 0) {
        S.sRS[wn][wm * 16 + g] = rs0;
        S.sRS[wn][wm * 16 + g + 8] = rs1;
    }
    __syncthreads();
    const int r0 = wm * 16 + g, r1 = r0 + 8;
    const float i0 = __frcp_rn(S.sRS[0][r0] + S.sRS[1][r0]);
    const float i1 = __frcp_rn(S.sRS[0][r1] + S.sRS[1][r1]);
#pragma unroll
    for (int j = 0; j < 2; j++) {
        const int c = f * HD + wn * 16 + j * 8 + q * 2;
        *(float2*)&OUT[(size_t)(l0 + r0) * CC + c] =
            make_float2(macc[j].x * i0, macc[j].y * i0);
        *(float2*)&OUT[(size_t)(l0 + r1) * CC + c] =
            make_float2(macc[j].z * i1, macc[j].w * i1);
    }
}

// ---------------------------------------------------------------------------
// conv weight repack OIHW -> [k9][o][i], tf32
// ---------------------------------------------------------------------------
__global__ void repack_kernel(const float* __restrict__ w) {
    int i = blockIdx.x * 256 + threadIdx.x;
    int o = i / (CM * 9);
    int rem = i % (CM * 9);
    int ci = rem / 9;
    int k9 = rem % 9;
    g_WR[(size_t)k9 * CC * CM + (size_t)o * CM + ci] = f2tf(w[i]);
}

// ---------------------------------------------------------------------------
// 3x3 SAME conv on padded tf32 input [66][66][CM] -> [64,64,CC].
// ---------------------------------------------------------------------------
__global__ void conv3p(const uint32_t* __restrict__ Gp,
                       const float* __restrict__ bias,
                       float* __restrict__ Out) {
    __shared__ __align__(16) uint32_t As[66][36];
    __shared__ __align__(16) uint32_t Bs[3][64][36];
    const int py = blockIdx.y;
    const int n0 = blockIdx.x * 64;
    const int t = threadIdx.x;
    const int warp = t >> 5, lane = t & 31;
    const int wm = warp >> 1, wn = warp & 1;
    const int g = lane >> 2, q = lane & 3;

    float4 acc[4] = {};
    for (int ky = 0; ky < 3; ky++) {
        const uint32_t* arow = Gp + (size_t)(py + ky) * GPW * CM;
        const uint32_t* wky = g_WR + (size_t)(ky * 3) * CC * CM;
        for (int kc = 0; kc < 16; kc++) {
            const int k0 = kc * 32;
#pragma unroll
            for (int i = 0; i < 3; i++) {
                int idx = t + i * 256;
                if (idx < 528) {
                    int row = idx >> 3, c4 = (idx & 7) * 4;
                    *(uint4*)&As[row][c4] =
                        *(const uint4*)(arow + (size_t)row * CM + k0 + c4);
                }
            }
#pragma unroll
            for (int i = 0; i < 6; i++) {
                int idx = t + i * 256;
                int kx = idx >> 9, w = idx & 511;
                int row = w >> 3, c4 = (w & 7) * 4;
                *(uint4*)&Bs[kx][row][c4] =
                    *(const uint4*)(wky + (size_t)kx * CC * CM +
                                    (size_t)(n0 + row) * CM + k0 + c4);
            }
            __syncthreads();
#pragma unroll
            for (int kx = 0; kx < 3; kx++) {
#pragma unroll
                for (int ks = 0; ks < 4; ks++) {
                    const int kb = ks * 8;
                    uint32_t a0 = As[wm * 16 + g + kx][kb + q];
                    uint32_t a1 = As[wm * 16 + g + 8 + kx][kb + q];
                    uint32_t a2 = As[wm * 16 + g + kx][kb + q + 4];
                    uint32_t a3 = As[wm * 16 + g + 8 + kx][kb + q + 4];
#pragma unroll
                    for (int j = 0; j < 4; j++) {
                        uint32_t b0 = Bs[kx][wn * 32 + j * 8 + g][kb + q];
                        uint32_t b1 = Bs[kx][wn * 32 + j * 8 + g][kb + q + 4];
                        mma_tf32(acc[j], a0, a1, a2, a3, b0, b1);
                    }
                }
            }
            __syncthreads();
        }
    }
    const int p0 = wm * 16 + g, p1 = p0 + 8;
#pragma unroll
    for (int j = 0; j < 4; j++) {
        const int c = n0 + wn * 32 + j * 8 + q * 2;
        float bx = bias[c], by = bias[c + 1];
        *(float2*)&Out[((size_t)py * 64 + p0) * CC + c] =
            make_float2(acc[j].x + bx, acc[j].y + by);
        *(float2*)&Out[((size_t)py * 64 + p1) * CC + c] =
            make_float2(acc[j].z + bx, acc[j].w + by);
    }
}

// ---------------------------------------------------------------------------
// LayerNorm (256 threads = CC, one row per block)
// ---------------------------------------------------------------------------
__device__ __forceinline__ float block_sum_256(float v, volatile float* red) {
#pragma unroll
    for (int o = 16; o > 0; o >>= 1) v += __shfl_xor_sync(0xffffffffu, v, o);
    if ((threadIdx.x & 31) == 0) red[threadIdx.x >> 5] = v;
    __syncthreads();
    float s = red[0] + red[1] + red[2] + red[3] + red[4] + red[5] + red[6] + red[7];
    __syncthreads();
    return s;
}

__global__ void ln_concat_kernel(const float* __restrict__ Min,
                                 const float* __restrict__ Xin,
                                 const float* __restrict__ g,
                                 const float* __restrict__ b,
                                 float* __restrict__ Y) {
    __shared__ float red[8];
    const int r = blockIdx.x;
    const int t = threadIdx.x;
    float v = Min[(size_t)r * CC + t];
    float mean = block_sum_256(v, red) * (1.0f / CC);
    float d = v - mean;
    float var = block_sum_256(d * d, red) * (1.0f / CC);
    float o = d * rsqrtf(var + 1e-5f) * g[t] + b[t];
    Y[(size_t)r * CM + 256 + t] = o;
    Y[(size_t)r * CM + t] = Xin[(size_t)r * CC + t];
}

__global__ void ln_res_kernel(const float* __restrict__ Cin,
                              const float* __restrict__ Xin,
                              const float* __restrict__ g,
                              const float* __restrict__ b,
                              float* __restrict__ Out) {
    __shared__ float red[8];
    const int r = blockIdx.x;
    const int t = threadIdx.x;
    float v = Cin[(size_t)r * CC + t];
    float mean = block_sum_256(v, red) * (1.0f / CC);
    float d = v - mean;
    float var = block_sum_256(d * d, red) * (1.0f / CC);
    float o = d * rsqrtf(var + 1e-5f) * g[t] + b[t];
    Out[(size_t)r * CC + t] = o + Xin[(size_t)r * CC + t];
}

// ---------------------------------------------------------------------------
// Launch
// ---------------------------------------------------------------------------
extern "C" void kernel_launch(void* const* d_in, const int* in_sizes, int n_in,
                              void* d_out, int out_size) {
    const float* x0 = (const float*)d_in[0];
    const float* x1 = (const float*)d_in[1];
    const float* proj_w = (const float*)d_in[6];
    const float* proj_b = (const float*)d_in[7];
    const float* merge_w = (const float*)d_in[8];
    const float* merge_b = (const float*)d_in[9];
    const float* n0g = (const float*)d_in[10];
    const float* n0b = (const float*)d_in[11];
    const float* lin_w = (const float*)d_in[12];
    const float* lin_b = (const float*)d_in[13];
    const float* conv_w = (const float*)d_in[14];
    const float* conv_b = (const float*)d_in[15];
    const float* n1g = (const float*)d_in[16];
    const float* n1b = (const float*)d_in[17];
    float* out = (float*)d_out;

    void *P0, *P1, *M0p, *M1p, *MM0p, *MM1p, *Y0p, *Y1p, *GP0p, *GP1p, *CV0p, *CV1p;
    cudaGetSymbolAddress(&P0, g_P0);
    cudaGetSymbolAddress(&P1, g_P1);
    cudaGetSymbolAddress(&M0p, g_M0);
    cudaGetSymbolAddress(&M1p, g_M1);
    cudaGetSymbolAddress(&MM0p, g_MM0);
    cudaGetSymbolAddress(&MM1p, g_MM1);
    cudaGetSymbolAddress(&Y0p, g_Y0);
    cudaGetSymbolAddress(&Y1p, g_Y1);
    cudaGetSymbolAddress(&GP0p, g_GP0);
    cudaGetSymbolAddress(&GP1p, g_GP1);
    cudaGetSymbolAddress(&CV0p, g_CV0);
    cudaGetSymbolAddress(&CV1p, g_CV1);

    // raise dynamic smem limit for attn_one (54.8 KB); idempotent host call
    cudaFuncSetAttribute(attn_one, cudaFuncAttributeMaxDynamicSharedMemorySize,
                         (int)sizeof(AttnSmem));

    // zero padded conv buffers (borders)
    cudaMemsetAsync(GP0p, 0, (size_t)GPW * GPW * CM * 4);
    cudaMemsetAsync(GP1p, 0, (size_t)GPW * GPW * CM * 4);

    repack_kernel<<<(CC * CM * 9) / 256, 256>>>(conv_w);

    // proj -> tf32 P
    gemm_tc<0, 2><<<dim3(CM / 64, LQ / 64), 256>>>(x0, CC, proj_w, CC, P0, CM, CC, proj_b);
    gemm_tc<0, 2><<<dim3(CM / 64, LQ / 64), 256>>>(x1, CC, proj_w, CC, P1, CM, CC, proj_b);

    // dual one-sided flash attention (sim' = sim^T symmetry)
    attn_one<<<dim3(LQ / 64, NH), 256, sizeof(AttnSmem)>>>(
        (const uint32_t*)P0, (const uint32_t*)P1,
        (const uint32_t*)P1 + 256, (float*)M0p);
    attn_one<<<dim3(LQ / 64, NH), 256, sizeof(AttnSmem)>>>(
        (const uint32_t*)P1, (const uint32_t*)P0,
        (const uint32_t*)P0 + 256, (float*)M1p);

    // merge
    gemm_tc<0, 0><<<dim3(CC / 64, LQ / 64), 256>>>((const float*)M0p, CC, merge_w, CC, MM0p, CC, CC, merge_b);
    gemm_tc<0, 0><<<dim3(CC / 64, LQ / 64), 256>>>((const float*)M1p, CC, merge_w, CC, MM1p, CC, CC, merge_b);

    // concat with LN
    ln_concat_kernel<<<LQ, 256>>>((const float*)MM0p, x0, n0g, n0b, (float*)Y0p);
    ln_concat_kernel<<<LQ, 256>>>((const float*)MM1p, x1, n0g, n0b, (float*)Y1p);

    // lin + gelu -> padded tf32
    gemm_tc<1, 1><<<dim3(CM / 64, LQ / 64), 256>>>((const float*)Y0p, CM, lin_w, CM, GP0p, CM, CM, lin_b);
    gemm_tc<1, 1><<<dim3(CM / 64, LQ / 64), 256>>>((const float*)Y1p, CM, lin_w, CM, GP1p, CM, CM, lin_b);

    // conv
    conv3p<<<dim3(CC / 64, 64), 256>>>((const uint32_t*)GP0p, conv_b, (float*)CV0p);
    conv3p<<<dim3(CC / 64, 64), 256>>>((const uint32_t*)GP1p, conv_b, (float*)CV1p);

    // LN + residual
    ln_res_kernel<<<LQ, 256>>>((const float*)CV0p, x0, n1g, n1b, out);
    ln_res_kernel<<<LQ, 256>>>((const float*)CV1p, x1, n1g, n1b, out + (size_t)LQ * CC);
}

// round 7
// speedup vs baseline: 5.9182x; 1.2042x over previous
#include <cuda_runtime.h>
#include <math.h>
#include <stdint.h>

#define LQ 4096
#define CC 256
#define NH 8
#define HD 32
#define CM 512
#define GPW 66   // padded conv width

// ---------------------------------------------------------------------------
// Scratch
// ---------------------------------------------------------------------------
static __device__ uint32_t g_P0[LQ * CM];          // proj(x0), tf32 bits
static __device__ uint32_t g_P1[LQ * CM];          // proj(x1), tf32 bits
static __device__ float    g_M0[LQ * CC];
static __device__ float    g_M1[LQ * CC];
static __device__ float    g_MM0[LQ * CC];
static __device__ float    g_MM1[LQ * CC];
static __device__ float    g_Y0[LQ * CM];
static __device__ float    g_Y1[LQ * CM];
static __device__ uint32_t g_GP0[GPW * GPW * CM];  // padded gelu(lin), tf32
static __device__ uint32_t g_GP1[GPW * GPW * CM];
static __device__ float    g_CV0[LQ * CC];
static __device__ float    g_CV1[LQ * CC];
static __device__ uint32_t g_WR[9 * CC * CM];      // conv weights [k9][o][i], tf32

// ---------------------------------------------------------------------------
// helpers
// ---------------------------------------------------------------------------
__device__ __forceinline__ uint32_t f2tf(float x) {
    uint32_t r;
    asm("cvt.rna.tf32.f32 %0, %1;" : "=r"(r) : "f"(x));
    return r;
}

__device__ __forceinline__ void mma_tf32(float4& d, uint32_t a0, uint32_t a1,
                                         uint32_t a2, uint32_t a3,
                                         uint32_t b0, uint32_t b1) {
    asm volatile(
        "mma.sync.aligned.m16n8k8.row.col.f32.tf32.tf32.f32 "
        "{%0,%1,%2,%3}, {%4,%5,%6,%7}, {%8,%9}, {%0,%1,%2,%3};"
        : "+f"(d.x), "+f"(d.y), "+f"(d.z), "+f"(d.w)
        : "r"(a0), "r"(a1), "r"(a2), "r"(a3), "r"(b0), "r"(b1));
}

// Polynomial exp on FMA pipe (no MUFU).
__device__ __forceinline__ float fexp(float x) {
    float t = x * 1.4426950408889634f;
    t = fminf(fmaxf(t, -126.0f), 126.0f);
    float r = rintf(t);
    float f = t - r;
    float p = 1.33335581e-3f;
    p = fmaf(p, f, 9.61812911e-3f);
    p = fmaf(p, f, 5.55041087e-2f);
    p = fmaf(p, f, 2.40226507e-1f);
    p = fmaf(p, f, 6.93147181e-1f);
    p = fmaf(p, f, 1.0f);
    return p * __int_as_float(((int)r + 127) << 23);
}

__device__ __forceinline__ uint32_t sptr(const void* p) {
    return (uint32_t)__cvta_generic_to_shared(p);
}
#define CP16(dst, src) \
    asm volatile("cp.async.cg.shared.global [%0], [%1], 16;" :: "r"(dst), "l"(src))

// ---------------------------------------------------------------------------
// tf32 GEMM: C = A @ B^T + bias. MODE: 0 = fp32 C, 1 = tf32 C into padded
// conv layout (with GELU), 2 = tf32 C plain. Block 64x64, 256 thr, BK=16.
// ---------------------------------------------------------------------------
template <int GELU, int MODE>
__global__ void gemm_tc(const float* __restrict__ A, int lda,
                        const float* __restrict__ B, int ldb,
                        void* __restrict__ Cv, int ldc,
                        int K, const float* __restrict__ bias) {
    __shared__ __align__(16) uint32_t As[64][28];
    __shared__ __align__(16) uint32_t Bs[64][28];
    const int m0 = blockIdx.y * 64;
    const int n0 = blockIdx.x * 64;
    const int t = threadIdx.x;
    const int warp = t >> 5, lane = t & 31;
    const int wm = warp >> 1, wn = warp & 1;
    const int g = lane >> 2, q = lane & 3;
    const int lr = t >> 2, lq = t & 3;

    float4 acc[4] = {};
    for (int k0 = 0; k0 < K; k0 += 16) {
        float4 av = *(const float4*)(A + (size_t)(m0 + lr) * lda + k0 + lq * 4);
        float4 bv = *(const float4*)(B + (size_t)(n0 + lr) * ldb + k0 + lq * 4);
        uint4 au = {f2tf(av.x), f2tf(av.y), f2tf(av.z), f2tf(av.w)};
        uint4 bu = {f2tf(bv.x), f2tf(bv.y), f2tf(bv.z), f2tf(bv.w)};
        *(uint4*)&As[lr][lq * 4] = au;
        *(uint4*)&Bs[lr][lq * 4] = bu;
        __syncthreads();
#pragma unroll
        for (int ks = 0; ks < 2; ks++) {
            const int kb = ks * 8;
            uint32_t a0 = As[wm * 16 + g][kb + q];
            uint32_t a1 = As[wm * 16 + g + 8][kb + q];
            uint32_t a2 = As[wm * 16 + g][kb + q + 4];
            uint32_t a3 = As[wm * 16 + g + 8][kb + q + 4];
#pragma unroll
            for (int j = 0; j < 4; j++) {
                uint32_t b0 = Bs[wn * 32 + j * 8 + g][kb + q];
                uint32_t b1 = Bs[wn * 32 + j * 8 + g][kb + q + 4];
                mma_tf32(acc[j], a0, a1, a2, a3, b0, b1);
            }
        }
        __syncthreads();
    }
    const int r0 = m0 + wm * 16 + g, r1 = r0 + 8;
#pragma unroll
    for (int j = 0; j < 4; j++) {
        const int c = n0 + wn * 32 + j * 8 + q * 2;
        float bx = bias ? bias[c] : 0.f, by = bias ? bias[c + 1] : 0.f;
        float v00 = acc[j].x + bx, v01 = acc[j].y + by;
        float v10 = acc[j].z + bx, v11 = acc[j].w + by;
        if (GELU) {
            v00 = 0.5f * v00 * (1.0f + erff(v00 * 0.70710678118f));
            v01 = 0.5f * v01 * (1.0f + erff(v01 * 0.70710678118f));
            v10 = 0.5f * v10 * (1.0f + erff(v10 * 0.70710678118f));
            v11 = 0.5f * v11 * (1.0f + erff(v11 * 0.70710678118f));
        }
        if (MODE == 0) {
            float* C = (float*)Cv;
            *(float2*)&C[(size_t)r0 * ldc + c] = make_float2(v00, v01);
            *(float2*)&C[(size_t)r1 * ldc + c] = make_float2(v10, v11);
        } else if (MODE == 1) {
            uint32_t* C = (uint32_t*)Cv;
            size_t o0 = ((size_t)((r0 >> 6) + 1) * GPW + (r0 & 63) + 1) * CM + c;
            size_t o1 = ((size_t)((r1 >> 6) + 1) * GPW + (r1 & 63) + 1) * CM + c;
            *(uint2*)&C[o0] = make_uint2(f2tf(v00), f2tf(v01));
            *(uint2*)&C[o1] = make_uint2(f2tf(v10), f2tf(v11));
        } else {
            uint32_t* C = (uint32_t*)Cv;
            *(uint2*)&C[(size_t)r0 * ldc + c] = make_uint2(f2tf(v00), f2tf(v01));
            *(uint2*)&C[(size_t)r1 * ldc + c] = make_uint2(f2tf(v10), f2tf(v11));
        }
    }
}

// ---------------------------------------------------------------------------
// One-sided flash attention, FA2-style register-resident E.
// Warp (wm,wn): rows wm*16+{g,g+8}; S cols wn*32+j*8; AV is k-split over the
// SAME cols -> E C-frags become A-frags via intra-warp shuffles (no smem E).
// Cross-wn AV partial reduction once at the end. grid (LQ/64, NH, 2).
// ---------------------------------------------------------------------------
__global__ __launch_bounds__(256, 3) void attn_one(
        const uint32_t* __restrict__ P0, const uint32_t* __restrict__ P1,
        float* __restrict__ M0, float* __restrict__ M1) {
    __shared__ __align__(16) uint32_t Kb[2][64][36];
    __shared__ __align__(16) uint32_t Vbs[2][64][40];
    __shared__ float sRS[2][64];
    __shared__ __align__(8) float redM[4][16][34];
    const int f = blockIdx.y;
    const int l0 = blockIdx.x * 64;
    const int dir = blockIdx.z;
    const uint32_t* A = (dir ? P1 : P0) + f * HD;
    const uint32_t* B = (dir ? P0 : P1) + f * HD;
    const uint32_t* V = (dir ? P0 : P1) + 256 + f * HD;
    float* OUT = dir ? M1 : M0;
    const int t = threadIdx.x;
    const int warp = t >> 5, lane = t & 31;
    const int wm = warp >> 1, wn = warp & 1;
    const int g = lane >> 2, q = lane & 3;
    const int lrow = t >> 3, lc4 = (t & 7) * 4;

    // prefetch s-tile 0 (async) + stage q tile in Kb[1] (sync loads)
#pragma unroll
    for (int i = 0; i < 2; i++) {
        int row = lrow + i * 32;
        CP16(sptr(&Kb[0][row][lc4]), B + (size_t)row * CM + lc4);
        CP16(sptr(&Vbs[0][row][lc4]), V + (size_t)row * CM + lc4);
        *(uint4*)&Kb[1][row][lc4] = *(const uint4*)(A + (size_t)(l0 + row) * CM + lc4);
    }
    asm volatile("cp.async.commit_group;");
    __syncthreads();
    uint32_t aq[4][4];
#pragma unroll
    for (int ks = 0; ks < 4; ks++) {
        const int kb = ks * 8;
        aq[ks][0] = Kb[1][wm * 16 + g][kb + q];
        aq[ks][1] = Kb[1][wm * 16 + g + 8][kb + q];
        aq[ks][2] = Kb[1][wm * 16 + g][kb + q + 4];
        aq[ks][3] = Kb[1][wm * 16 + g + 8][kb + q + 4];
    }
    asm volatile("cp.async.wait_group 0;" ::: "memory");
    __syncthreads();

    const float SC = 0.17677669529663687f;
    const int sl = 4 * g + (q >> 1), sl2 = sl + 2;
    const bool odd = (q & 1);
    float4 macc[4] = {};
    float rs0 = 0.f, rs1 = 0.f;

    for (int it = 0; it < 64; it++) {
        const int cur = it & 1;
        if (it < 63) {
            const uint32_t* Bn = B + (size_t)(it + 1) * 64 * CM;
            const uint32_t* Vn = V + (size_t)(it + 1) * 64 * CM;
#pragma unroll
            for (int i = 0; i < 2; i++) {
                int row = lrow + i * 32;
                CP16(sptr(&Kb[cur ^ 1][row][lc4]), Bn + (size_t)row * CM + lc4);
                CP16(sptr(&Vbs[cur ^ 1][row][lc4]), Vn + (size_t)row * CM + lc4);
            }
            asm volatile("cp.async.commit_group;");
        }
        // S = qA @ qB^T (rows wm*16.., cols wn*32 + j*8)
        float4 sacc[4] = {};
#pragma unroll
        for (int ks = 0; ks < 4; ks++) {
            const int kb = ks * 8;
#pragma unroll
            for (int j = 0; j < 4; j++) {
                uint32_t b0 = Kb[cur][wn * 32 + j * 8 + g][kb + q];
                uint32_t b1 = Kb[cur][wn * 32 + j * 8 + g][kb + q + 4];
                mma_tf32(sacc[j], aq[ks][0], aq[ks][1], aq[ks][2], aq[ks][3], b0, b1);
            }
        }
        // per j: E, row sums, C-frag -> A-frag shuffles, AV mma (k-split)
#pragma unroll
        for (int j = 0; j < 4; j++) {
            float e0 = fexp(sacc[j].x * SC);   // row g,   col 2q
            float e1 = fexp(sacc[j].y * SC);   // row g,   col 2q+1
            float e2 = fexp(sacc[j].z * SC);   // row g+8, col 2q
            float e3 = fexp(sacc[j].w * SC);   // row g+8, col 2q+1
            rs0 += e0 + e1;
            rs1 += e2 + e3;
            float w00 = __shfl_sync(0xffffffffu, e0, sl);
            float w01 = __shfl_sync(0xffffffffu, e1, sl);
            float w10 = __shfl_sync(0xffffffffu, e2, sl);
            float w11 = __shfl_sync(0xffffffffu, e3, sl);
            float w20 = __shfl_sync(0xffffffffu, e0, sl2);
            float w21 = __shfl_sync(0xffffffffu, e1, sl2);
            float w30 = __shfl_sync(0xffffffffu, e2, sl2);
            float w31 = __shfl_sync(0xffffffffu, e3, sl2);
            uint32_t a0 = f2tf(odd ? w01 : w00);   // (row g,   k q)
            uint32_t a1 = f2tf(odd ? w11 : w10);   // (row g+8, k q)
            uint32_t a2 = f2tf(odd ? w21 : w20);   // (row g,   k q+4)
            uint32_t a3 = f2tf(odd ? w31 : w30);   // (row g+8, k q+4)
            const int kb = wn * 32 + j * 8;
#pragma unroll
            for (int jj = 0; jj < 4; jj++) {
                uint32_t b0 = Vbs[cur][kb + q][jj * 8 + g];
                uint32_t b1 = Vbs[cur][kb + q + 4][jj * 8 + g];
                mma_tf32(macc[jj], a0, a1, a2, a3, b0, b1);
            }
        }
        asm volatile("cp.async.wait_group 0;" ::: "memory");
        __syncthreads();
    }
    // row sums: reduce over q, publish per wn half
    rs0 += __shfl_xor_sync(0xffffffffu, rs0, 1);
    rs0 += __shfl_xor_sync(0xffffffffu, rs0, 2);
    rs1 += __shfl_xor_sync(0xffffffffu, rs1, 1);
    rs1 += __shfl_xor_sync(0xffffffffu, rs1, 2);
    if (q == 0) {
        sRS[wn][wm * 16 + g] = rs0;
        sRS[wn][wm * 16 + g + 8] = rs1;
    }
    // wn=0 parks its AV partials
    if (wn == 0) {
#pragma unroll
        for (int jj = 0; jj < 4; jj++) {
            *(float2*)&redM[wm][g][jj * 8 + 2 * q] = make_float2(macc[jj].x, macc[jj].y);
            *(float2*)&redM[wm][g + 8][jj * 8 + 2 * q] = make_float2(macc[jj].z, macc[jj].w);
        }
    }
    __syncthreads();
    // wn=1 combines, normalizes, writes
    if (wn == 1) {
        const int r0 = wm * 16 + g, r1 = r0 + 8;
        const float i0 = __frcp_rn(sRS[0][r0] + sRS[1][r0]);
        const float i1 = __frcp_rn(sRS[0][r1] + sRS[1][r1]);
#pragma unroll
        for (int jj = 0; jj < 4; jj++) {
            float2 p0 = *(float2*)&redM[wm][g][jj * 8 + 2 * q];
            float2 p1 = *(float2*)&redM[wm][g + 8][jj * 8 + 2 * q];
            const int c = f * HD + jj * 8 + 2 * q;
            *(float2*)&OUT[(size_t)(l0 + r0) * CC + c] =
                make_float2((macc[jj].x + p0.x) * i0, (macc[jj].y + p0.y) * i0);
            *(float2*)&OUT[(size_t)(l0 + r1) * CC + c] =
                make_float2((macc[jj].z + p1.x) * i1, (macc[jj].w + p1.y) * i1);
        }
    }
}

// ---------------------------------------------------------------------------
// conv weight repack OIHW -> [k9][o][i], tf32
// ---------------------------------------------------------------------------
__global__ void repack_kernel(const float* __restrict__ w) {
    int i = blockIdx.x * 256 + threadIdx.x;
    int o = i / (CM * 9);
    int rem = i % (CM * 9);
    int ci = rem / 9;
    int k9 = rem % 9;
    g_WR[(size_t)k9 * CC * CM + (size_t)o * CM + ci] = f2tf(w[i]);
}

// ---------------------------------------------------------------------------
// 3x3 SAME conv on padded tf32 input [66][66][CM] -> [64,64,CC].
// ---------------------------------------------------------------------------
__global__ void conv3p(const uint32_t* __restrict__ Gp,
                       const float* __restrict__ bias,
                       float* __restrict__ Out) {
    __shared__ __align__(16) uint32_t As[66][36];
    __shared__ __align__(16) uint32_t Bs[3][64][36];
    const int py = blockIdx.y;
    const int n0 = blockIdx.x * 64;
    const int t = threadIdx.x;
    const int warp = t >> 5, lane = t & 31;
    const int wm = warp >> 1, wn = warp & 1;
    const int g = lane >> 2, q = lane & 3;

    float4 acc[4] = {};
    for (int ky = 0; ky < 3; ky++) {
        const uint32_t* arow = Gp + (size_t)(py + ky) * GPW * CM;
        const uint32_t* wky = g_WR + (size_t)(ky * 3) * CC * CM;
        for (int kc = 0; kc < 16; kc++) {
            const int k0 = kc * 32;
#pragma unroll
            for (int i = 0; i < 3; i++) {
                int idx = t + i * 256;
                if (idx < 528) {
                    int row = idx >> 3, c4 = (idx & 7) * 4;
                    *(uint4*)&As[row][c4] =
                        *(const uint4*)(arow + (size_t)row * CM + k0 + c4);
                }
            }
#pragma unroll
            for (int i = 0; i < 6; i++) {
                int idx = t + i * 256;
                int kx = idx >> 9, w = idx & 511;
                int row = w >> 3, c4 = (w & 7) * 4;
                *(uint4*)&Bs[kx][row][c4] =
                    *(const uint4*)(wky + (size_t)kx * CC * CM +
                                    (size_t)(n0 + row) * CM + k0 + c4);
            }
            __syncthreads();
#pragma unroll
            for (int kx = 0; kx < 3; kx++) {
#pragma unroll
                for (int ks = 0; ks < 4; ks++) {
                    const int kb = ks * 8;
                    uint32_t a0 = As[wm * 16 + g + kx][kb + q];
                    uint32_t a1 = As[wm * 16 + g + 8 + kx][kb + q];
                    uint32_t a2 = As[wm * 16 + g + kx][kb + q + 4];
                    uint32_t a3 = As[wm * 16 + g + 8 + kx][kb + q + 4];
#pragma unroll
                    for (int j = 0; j < 4; j++) {
                        uint32_t b0 = Bs[kx][wn * 32 + j * 8 + g][kb + q];
                        uint32_t b1 = Bs[kx][wn * 32 + j * 8 + g][kb + q + 4];
                        mma_tf32(acc[j], a0, a1, a2, a3, b0, b1);
                    }
                }
            }
            __syncthreads();
        }
    }
    const int p0 = wm * 16 + g, p1 = p0 + 8;
#pragma unroll
    for (int j = 0; j < 4; j++) {
        const int c = n0 + wn * 32 + j * 8 + q * 2;
        float bx = bias[c], by = bias[c + 1];
        *(float2*)&Out[((size_t)py * 64 + p0) * CC + c] =
            make_float2(acc[j].x + bx, acc[j].y + by);
        *(float2*)&Out[((size_t)py * 64 + p1) * CC + c] =
            make_float2(acc[j].z + bx, acc[j].w + by);
    }
}

// ---------------------------------------------------------------------------
// LayerNorm (256 threads = CC, one row per block)
// ---------------------------------------------------------------------------
__device__ __forceinline__ float block_sum_256(float v, volatile float* red) {
#pragma unroll
    for (int o = 16; o > 0; o >>= 1) v += __shfl_xor_sync(0xffffffffu, v, o);
    if ((threadIdx.x & 31) == 0) red[threadIdx.x >> 5] = v;
    __syncthreads();
    float s = red[0] + red[1] + red[2] + red[3] + red[4] + red[5] + red[6] + red[7];
    __syncthreads();
    return s;
}

__global__ void ln_concat_kernel(const float* __restrict__ Min,
                                 const float* __restrict__ Xin,
                                 const float* __restrict__ g,
                                 const float* __restrict__ b,
                                 float* __restrict__ Y) {
    __shared__ float red[8];
    const int r = blockIdx.x;
    const int t = threadIdx.x;
    float v = Min[(size_t)r * CC + t];
    float mean = block_sum_256(v, red) * (1.0f / CC);
    float d = v - mean;
    float var = block_sum_256(d * d, red) * (1.0f / CC);
    float o = d * rsqrtf(var + 1e-5f) * g[t] + b[t];
    Y[(size_t)r * CM + 256 + t] = o;
    Y[(size_t)r * CM + t] = Xin[(size_t)r * CC + t];
}

__global__ void ln_res_kernel(const float* __restrict__ Cin,
                              const float* __restrict__ Xin,
                              const float* __restrict__ g,
                              const float* __restrict__ b,
                              float* __restrict__ Out) {
    __shared__ float red[8];
    const int r = blockIdx.x;
    const int t = threadIdx.x;
    float v = Cin[(size_t)r * CC + t];
    float mean = block_sum_256(v, red) * (1.0f / CC);
    float d = v - mean;
    float var = block_sum_256(d * d, red) * (1.0f / CC);
    float o = d * rsqrtf(var + 1e-5f) * g[t] + b[t];
    Out[(size_t)r * CC + t] = o + Xin[(size_t)r * CC + t];
}

// ---------------------------------------------------------------------------
// Launch
// ---------------------------------------------------------------------------
extern "C" void kernel_launch(void* const* d_in, const int* in_sizes, int n_in,
                              void* d_out, int out_size) {
    const float* x0 = (const float*)d_in[0];
    const float* x1 = (const float*)d_in[1];
    const float* proj_w = (const float*)d_in[6];
    const float* proj_b = (const float*)d_in[7];
    const float* merge_w = (const float*)d_in[8];
    const float* merge_b = (const float*)d_in[9];
    const float* n0g = (const float*)d_in[10];
    const float* n0b = (const float*)d_in[11];
    const float* lin_w = (const float*)d_in[12];
    const float* lin_b = (const float*)d_in[13];
    const float* conv_w = (const float*)d_in[14];
    const float* conv_b = (const float*)d_in[15];
    const float* n1g = (const float*)d_in[16];
    const float* n1b = (const float*)d_in[17];
    float* out = (float*)d_out;

    void *P0, *P1, *M0p, *M1p, *MM0p, *MM1p, *Y0p, *Y1p, *GP0p, *GP1p, *CV0p, *CV1p;
    cudaGetSymbolAddress(&P0, g_P0);
    cudaGetSymbolAddress(&P1, g_P1);
    cudaGetSymbolAddress(&M0p, g_M0);
    cudaGetSymbolAddress(&M1p, g_M1);
    cudaGetSymbolAddress(&MM0p, g_MM0);
    cudaGetSymbolAddress(&MM1p, g_MM1);
    cudaGetSymbolAddress(&Y0p, g_Y0);
    cudaGetSymbolAddress(&Y1p, g_Y1);
    cudaGetSymbolAddress(&GP0p, g_GP0);
    cudaGetSymbolAddress(&GP1p, g_GP1);
    cudaGetSymbolAddress(&CV0p, g_CV0);
    cudaGetSymbolAddress(&CV1p, g_CV1);

    // zero padded conv buffers (borders)
    cudaMemsetAsync(GP0p, 0, (size_t)GPW * GPW * CM * 4);
    cudaMemsetAsync(GP1p, 0, (size_t)GPW * GPW * CM * 4);

    repack_kernel<<<(CC * CM * 9) / 256, 256>>>(conv_w);

    // proj -> tf32 P
    gemm_tc<0, 2><<<dim3(CM / 64, LQ / 64), 256>>>(x0, CC, proj_w, CC, P0, CM, CC, proj_b);
    gemm_tc<0, 2><<<dim3(CM / 64, LQ / 64), 256>>>(x1, CC, proj_w, CC, P1, CM, CC, proj_b);

    // dual one-sided flash attention in one launch (z = direction)
    attn_one<<<dim3(LQ / 64, NH, 2), 256>>>(
        (const uint32_t*)P0, (const uint32_t*)P1, (float*)M0p, (float*)M1p);

    // merge
    gemm_tc<0, 0><<<dim3(CC / 64, LQ / 64), 256>>>((const float*)M0p, CC, merge_w, CC, MM0p, CC, CC, merge_b);
    gemm_tc<0, 0><<<dim3(CC / 64, LQ / 64), 256>>>((const float*)M1p, CC, merge_w, CC, MM1p, CC, CC, merge_b);

    // concat with LN
    ln_concat_kernel<<<LQ, 256>>>((const float*)MM0p, x0, n0g, n0b, (float*)Y0p);
    ln_concat_kernel<<<LQ, 256>>>((const float*)MM1p, x1, n0g, n0b, (float*)Y1p);

    // lin + gelu -> padded tf32
    gemm_tc<1, 1><<<dim3(CM / 64, LQ / 64), 256>>>((const float*)Y0p, CM, lin_w, CM, GP0p, CM, CM, lin_b);
    gemm_tc<1, 1><<<dim3(CM / 64, LQ / 64), 256>>>((const float*)Y1p, CM, lin_w, CM, GP1p, CM, CM, lin_b);

    // conv
    conv3p<<<dim3(CC / 64, 64), 256>>>((const uint32_t*)GP0p, conv_b, (float*)CV0p);
    conv3p<<<dim3(CC / 64, 64), 256>>>((const uint32_t*)GP1p, conv_b, (float*)CV1p);

    // LN + residual
    ln_res_kernel<<<LQ, 256>>>((const float*)CV0p, x0, n1g, n1b, out);
    ln_res_kernel<<<LQ, 256>>>((const float*)CV1p, x1, n1g, n1b, out + (size_t)LQ * CC);
}

// round 9
// speedup vs baseline: 7.8990x; 1.3347x over previous
#include <cuda_runtime.h>
#include <cuda_fp16.h>
#include <math.h>
#include <stdint.h>

#define LQ 4096
#define CC 256
#define NH 8
#define HD 32
#define CM 512
#define GPW 66   // padded conv width

// ---------------------------------------------------------------------------
// Scratch
// ---------------------------------------------------------------------------
static __device__ uint32_t g_P0[LQ * CM];          // proj(x0), tf32 bits
static __device__ uint32_t g_P1[LQ * CM];          // proj(x1), tf32 bits
static __device__ __align__(16) __half g_VT0[NH * HD * LQ];  // v0 transposed [f*HD+d][s]
static __device__ __align__(16) __half g_VT1[NH * HD * LQ];  // v1 transposed
static __device__ float    g_M0[LQ * CC];
static __device__ float    g_M1[LQ * CC];
static __device__ float    g_MM0[LQ * CC];
static __device__ float    g_MM1[LQ * CC];
static __device__ float    g_Y0[LQ * CM];
static __device__ float    g_Y1[LQ * CM];
static __device__ __align__(16) __half g_GP0[GPW * GPW * CM];  // padded gelu(lin), fp16
static __device__ __align__(16) __half g_GP1[GPW * GPW * CM];
static __device__ float    g_CV0[LQ * CC];
static __device__ float    g_CV1[LQ * CC];
static __device__ __align__(16) __half g_WRh[9 * CC * CM];     // conv weights [k9][o][i], fp16

// ---------------------------------------------------------------------------
// helpers
// ---------------------------------------------------------------------------
__device__ __forceinline__ uint32_t f2tf(float x) {
    uint32_t r;
    asm("cvt.rna.tf32.f32 %0, %1;" : "=r"(r) : "f"(x));
    return r;
}

__device__ __forceinline__ void mma_tf32(float4& d, uint32_t a0, uint32_t a1,
                                         uint32_t a2, uint32_t a3,
                                         uint32_t b0, uint32_t b1) {
    asm volatile(
        "mma.sync.aligned.m16n8k8.row.col.f32.tf32.tf32.f32 "
        "{%0,%1,%2,%3}, {%4,%5,%6,%7}, {%8,%9}, {%0,%1,%2,%3};"
        : "+f"(d.x), "+f"(d.y), "+f"(d.z), "+f"(d.w)
        : "r"(a0), "r"(a1), "r"(a2), "r"(a3), "r"(b0), "r"(b1));
}

__device__ __forceinline__ void mma_f16(float4& d, uint32_t a0, uint32_t a1,
                                        uint32_t a2, uint32_t a3,
                                        uint32_t b0, uint32_t b1) {
    asm volatile(
        "mma.sync.aligned.m16n8k16.row.col.f32.f16.f16.f32 "
        "{%0,%1,%2,%3}, {%4,%5,%6,%7}, {%8,%9}, {%0,%1,%2,%3};"
        : "+f"(d.x), "+f"(d.y), "+f"(d.z), "+f"(d.w)
        : "r"(a0), "r"(a1), "r"(a2), "r"(a3), "r"(b0), "r"(b1));
}

__device__ __forceinline__ uint32_t h2u(__half2 h) {
    return *reinterpret_cast<uint32_t*>(&h);
}

// Polynomial exp on FMA pipe (no MUFU).
__device__ __forceinline__ float fexp(float x) {
    float t = x * 1.4426950408889634f;
    t = fminf(fmaxf(t, -126.0f), 126.0f);
    float r = rintf(t);
    float f = t - r;
    float p = 1.33335581e-3f;
    p = fmaf(p, f, 9.61812911e-3f);
    p = fmaf(p, f, 5.55041087e-2f);
    p = fmaf(p, f, 2.40226507e-1f);
    p = fmaf(p, f, 6.93147181e-1f);
    p = fmaf(p, f, 1.0f);
    return p * __int_as_float(((int)r + 127) << 23);
}

__device__ __forceinline__ uint32_t sptr(const void* p) {
    return (uint32_t)__cvta_generic_to_shared(p);
}
#define CP16(dst, src) \
    asm volatile("cp.async.cg.shared.global [%0], [%1], 16;" :: "r"(dst), "l"(src))

// ---------------------------------------------------------------------------
// tf32 GEMM: C = A @ B^T + bias. MODE: 0 = fp32 C, 1 = fp16 C into padded
// conv layout (with GELU), 2 = tf32 C plain. Block 64x64, 256 thr, BK=16.
// ---------------------------------------------------------------------------
template <int GELU, int MODE>
__global__ void gemm_tc(const float* __restrict__ A, int lda,
                        const float* __restrict__ B, int ldb,
                        void* __restrict__ Cv, int ldc,
                        int K, const float* __restrict__ bias) {
    __shared__ __align__(16) uint32_t As[64][28];
    __shared__ __align__(16) uint32_t Bs[64][28];
    const int m0 = blockIdx.y * 64;
    const int n0 = blockIdx.x * 64;
    const int t = threadIdx.x;
    const int warp = t >> 5, lane = t & 31;
    const int wm = warp >> 1, wn = warp & 1;
    const int g = lane >> 2, q = lane & 3;
    const int lr = t >> 2, lq = t & 3;

    float4 acc[4] = {};
    for (int k0 = 0; k0 < K; k0 += 16) {
        float4 av = *(const float4*)(A + (size_t)(m0 + lr) * lda + k0 + lq * 4);
        float4 bv = *(const float4*)(B + (size_t)(n0 + lr) * ldb + k0 + lq * 4);
        uint4 au = {f2tf(av.x), f2tf(av.y), f2tf(av.z), f2tf(av.w)};
        uint4 bu = {f2tf(bv.x), f2tf(bv.y), f2tf(bv.z), f2tf(bv.w)};
        *(uint4*)&As[lr][lq * 4] = au;
        *(uint4*)&Bs[lr][lq * 4] = bu;
        __syncthreads();
#pragma unroll
        for (int ks = 0; ks < 2; ks++) {
            const int kb = ks * 8;
            uint32_t a0 = As[wm * 16 + g][kb + q];
            uint32_t a1 = As[wm * 16 + g + 8][kb + q];
            uint32_t a2 = As[wm * 16 + g][kb + q + 4];
            uint32_t a3 = As[wm * 16 + g + 8][kb + q + 4];
#pragma unroll
            for (int j = 0; j < 4; j++) {
                uint32_t b0 = Bs[wn * 32 + j * 8 + g][kb + q];
                uint32_t b1 = Bs[wn * 32 + j * 8 + g][kb + q + 4];
                mma_tf32(acc[j], a0, a1, a2, a3, b0, b1);
            }
        }
        __syncthreads();
    }
    const int r0 = m0 + wm * 16 + g, r1 = r0 + 8;
#pragma unroll
    for (int j = 0; j < 4; j++) {
        const int c = n0 + wn * 32 + j * 8 + q * 2;
        float bx = bias ? bias[c] : 0.f, by = bias ? bias[c + 1] : 0.f;
        float v00 = acc[j].x + bx, v01 = acc[j].y + by;
        float v10 = acc[j].z + bx, v11 = acc[j].w + by;
        if (GELU) {
            v00 = 0.5f * v00 * (1.0f + erff(v00 * 0.70710678118f));
            v01 = 0.5f * v01 * (1.0f + erff(v01 * 0.70710678118f));
            v10 = 0.5f * v10 * (1.0f + erff(v10 * 0.70710678118f));
            v11 = 0.5f * v11 * (1.0f + erff(v11 * 0.70710678118f));
        }
        if (MODE == 0) {
            float* C = (float*)Cv;
            *(float2*)&C[(size_t)r0 * ldc + c] = make_float2(v00, v01);
            *(float2*)&C[(size_t)r1 * ldc + c] = make_float2(v10, v11);
        } else if (MODE == 1) {
            __half* C = (__half*)Cv;
            size_t o0 = ((size_t)((r0 >> 6) + 1) * GPW + (r0 & 63) + 1) * CM + c;
            size_t o1 = ((size_t)((r1 >> 6) + 1) * GPW + (r1 & 63) + 1) * CM + c;
            *(__half2*)&C[o0] = __floats2half2_rn(v00, v01);
            *(__half2*)&C[o1] = __floats2half2_rn(v10, v11);
        } else {
            uint32_t* C = (uint32_t*)Cv;
            *(uint2*)&C[(size_t)r0 * ldc + c] = make_uint2(f2tf(v00), f2tf(v01));
            *(uint2*)&C[(size_t)r1 * ldc + c] = make_uint2(f2tf(v10), f2tf(v11));
        }
    }
}

// ---------------------------------------------------------------------------
// VT pack: P's v-half (tf32 bits == valid floats) -> fp16 transposed VT[f*HD+d][s]
// Scalar smem stores (odd stride 33 forbids STS.128; reads stay conflict-free).
// grid (LQ/64, NH), 256 thr.
// ---------------------------------------------------------------------------
__global__ void vt_pack(const uint32_t* __restrict__ P, __half* __restrict__ VT) {
    __shared__ float Sh[64][33];
    const int s0 = blockIdx.x * 64, f = blockIdx.y;
    const int t = threadIdx.x;
    const float* Pf = (const float*)P;
    {
        int r = t >> 2, dg = (t & 3) * 8;
        const float* src = Pf + (size_t)(s0 + r) * CM + 256 + f * HD + dg;
        float4 v0 = *(const float4*)src;
        float4 v1 = *(const float4*)(src + 4);
        Sh[r][dg + 0] = v0.x; Sh[r][dg + 1] = v0.y;
        Sh[r][dg + 2] = v0.z; Sh[r][dg + 3] = v0.w;
        Sh[r][dg + 4] = v1.x; Sh[r][dg + 5] = v1.y;
        Sh[r][dg + 6] = v1.z; Sh[r][dg + 7] = v1.w;
    }
    __syncthreads();
    {
        int d = t >> 3, sg = (t & 7) * 8;
        __half2 p0 = __floats2half2_rn(Sh[sg + 0][d], Sh[sg + 1][d]);
        __half2 p1 = __floats2half2_rn(Sh[sg + 2][d], Sh[sg + 3][d]);
        __half2 p2 = __floats2half2_rn(Sh[sg + 4][d], Sh[sg + 5][d]);
        __half2 p3 = __floats2half2_rn(Sh[sg + 6][d], Sh[sg + 7][d]);
        uint4 u = {h2u(p0), h2u(p1), h2u(p2), h2u(p3)};
        *(uint4*)(VT + (size_t)(f * HD + d) * LQ + s0 + sg) = u;
    }
}

// ---------------------------------------------------------------------------
// One-sided flash attention. S in tf32; AV in fp16 with ZERO cross-thread E
// movement: S C-frags of two adjacent j-groups ARE the m16n8k16 A-frags.
// grid (LQ/64, NH, 2), 256 thr.
// ---------------------------------------------------------------------------
__global__ __launch_bounds__(256, 3) void attn_one(
        const uint32_t* __restrict__ P0, const uint32_t* __restrict__ P1,
        const __half* __restrict__ VT0, const __half* __restrict__ VT1,
        float* __restrict__ M0, float* __restrict__ M1) {
    __shared__ __align__(16) uint32_t Kb[2][64][36];
    __shared__ __align__(16) __half Vh[2][32][72];   // [d][k halfs]
    __shared__ float sRS[2][64];
    __shared__ __align__(8) float redM[4][16][34];
    const int f = blockIdx.y;
    const int l0 = blockIdx.x * 64;
    const int dir = blockIdx.z;
    const uint32_t* A = (dir ? P1 : P0) + f * HD;
    const uint32_t* B = (dir ? P0 : P1) + f * HD;
    const __half* VTf = (dir ? VT0 : VT1) + (size_t)f * HD * LQ;
    float* OUT = dir ? M1 : M0;
    const int t = threadIdx.x;
    const int warp = t >> 5, lane = t & 31;
    const int wm = warp >> 1, wn = warp & 1;
    const int g = lane >> 2, q = lane & 3;
    const int lrow = t >> 3, lc4 = (t & 7) * 4;
    const int vd = t >> 3, vc8 = (t & 7) * 8;

    // prefetch s-tile 0 (async) + stage q tile in Kb[1] (sync loads)
#pragma unroll
    for (int i = 0; i < 2; i++) {
        int row = lrow + i * 32;
        CP16(sptr(&Kb[0][row][lc4]), B + (size_t)row * CM + lc4);
        *(uint4*)&Kb[1][row][lc4] = *(const uint4*)(A + (size_t)(l0 + row) * CM + lc4);
    }
    CP16(sptr(&Vh[0][vd][vc8]), VTf + (size_t)vd * LQ + vc8);
    asm volatile("cp.async.commit_group;");
    __syncthreads();
    uint32_t aq[4][4];
#pragma unroll
    for (int ks = 0; ks < 4; ks++) {
        const int kb = ks * 8;
        aq[ks][0] = Kb[1][wm * 16 + g][kb + q];
        aq[ks][1] = Kb[1][wm * 16 + g + 8][kb + q];
        aq[ks][2] = Kb[1][wm * 16 + g][kb + q + 4];
        aq[ks][3] = Kb[1][wm * 16 + g + 8][kb + q + 4];
    }
    asm volatile("cp.async.wait_group 0;" ::: "memory");
    __syncthreads();

    const float SC = 0.17677669529663687f;
    float4 macc[4] = {};
    float rs0 = 0.f, rs1 = 0.f;

    for (int it = 0; it < 64; it++) {
        const int cur = it & 1;
        if (it < 63) {
            const uint32_t* Bn = B + (size_t)(it + 1) * 64 * CM;
#pragma unroll
            for (int i = 0; i < 2; i++) {
                int row = lrow + i * 32;
                CP16(sptr(&Kb[cur ^ 1][row][lc4]), Bn + (size_t)row * CM + lc4);
            }
            CP16(sptr(&Vh[cur ^ 1][vd][vc8]),
                 VTf + (size_t)vd * LQ + (it + 1) * 64 + vc8);
            asm volatile("cp.async.commit_group;");
        }
        // S = qA @ qB^T (rows wm*16.., cols wn*32 + j*8), tf32
        float4 sacc[4] = {};
#pragma unroll
        for (int ks = 0; ks < 4; ks++) {
            const int kb = ks * 8;
#pragma unroll
            for (int j = 0; j < 4; j++) {
                uint32_t b0 = Kb[cur][wn * 32 + j * 8 + g][kb + q];
                uint32_t b1 = Kb[cur][wn * 32 + j * 8 + g][kb + q + 4];
                mma_tf32(sacc[j], aq[ks][0], aq[ks][1], aq[ks][2], aq[ks][3], b0, b1);
            }
        }
        // per k16 chunk: E (fp32), row sums, pack to fp16 A-frags, AV mma
#pragma unroll
        for (int c = 0; c < 2; c++) {
            const float4 sa = sacc[2 * c], sb = sacc[2 * c + 1];
            float e00 = fexp(sa.x * SC), e01 = fexp(sa.y * SC);
            float e02 = fexp(sa.z * SC), e03 = fexp(sa.w * SC);
            float e10 = fexp(sb.x * SC), e11 = fexp(sb.y * SC);
            float e12 = fexp(sb.z * SC), e13 = fexp(sb.w * SC);
            rs0 += e00 + e01 + e10 + e11;
            rs1 += e02 + e03 + e12 + e13;
            uint32_t a0 = h2u(__floats2half2_rn(e00, e01));  // (g,   k 2q..2q+1)
            uint32_t a1 = h2u(__floats2half2_rn(e02, e03));  // (g+8, k 2q..2q+1)
            uint32_t a2 = h2u(__floats2half2_rn(e10, e11));  // (g,   k 2q+8..9)
            uint32_t a3 = h2u(__floats2half2_rn(e12, e13));  // (g+8, k 2q+8..9)
            const int kh = (wn * 16 + c * 8 + q) * 2;        // half index base
#pragma unroll
            for (int jj = 0; jj < 4; jj++) {
                uint32_t b0 = *(const uint32_t*)&Vh[cur][jj * 8 + g][kh];
                uint32_t b1 = *(const uint32_t*)&Vh[cur][jj * 8 + g][kh + 8];
                mma_f16(macc[jj], a0, a1, a2, a3, b0, b1);
            }
        }
        asm volatile("cp.async.wait_group 0;" ::: "memory");
        __syncthreads();
    }
    // row sums: reduce over q, publish per wn half
    rs0 += __shfl_xor_sync(0xffffffffu, rs0, 1);
    rs0 += __shfl_xor_sync(0xffffffffu, rs0, 2);
    rs1 += __shfl_xor_sync(0xffffffffu, rs1, 1);
    rs1 += __shfl_xor_sync(0xffffffffu, rs1, 2);
    if (q == 0) {
        sRS[wn][wm * 16 + g] = rs0;
        sRS[wn][wm * 16 + g + 8] = rs1;
    }
    // wn=0 parks its AV partials
    if (wn == 0) {
#pragma unroll
        for (int jj = 0; jj < 4; jj++) {
            *(float2*)&redM[wm][g][jj * 8 + 2 * q] = make_float2(macc[jj].x, macc[jj].y);
            *(float2*)&redM[wm][g + 8][jj * 8 + 2 * q] = make_float2(macc[jj].z, macc[jj].w);
        }
    }
    __syncthreads();
    // wn=1 combines, normalizes, writes
    if (wn == 1) {
        const int r0 = wm * 16 + g, r1 = r0 + 8;
        const float i0 = __frcp_rn(sRS[0][r0] + sRS[1][r0]);
        const float i1 = __frcp_rn(sRS[0][r1] + sRS[1][r1]);
#pragma unroll
        for (int jj = 0; jj < 4; jj++) {
            float2 p0 = *(float2*)&redM[wm][g][jj * 8 + 2 * q];
            float2 p1 = *(float2*)&redM[wm][g + 8][jj * 8 + 2 * q];
            const int c = f * HD + jj * 8 + 2 * q;
            *(float2*)&OUT[(size_t)(l0 + r0) * CC + c] =
                make_float2((macc[jj].x + p0.x) * i0, (macc[jj].y + p0.y) * i0);
            *(float2*)&OUT[(size_t)(l0 + r1) * CC + c] =
                make_float2((macc[jj].z + p1.x) * i1, (macc[jj].w + p1.y) * i1);
        }
    }
}

// ---------------------------------------------------------------------------
// conv weight repack OIHW -> [k9][o][i], fp16
// ---------------------------------------------------------------------------
__global__ void repack_kernel(const float* __restrict__ w) {
    int i = blockIdx.x * 256 + threadIdx.x;
    int o = i / (CM * 9);
    int rem = i % (CM * 9);
    int ci = rem / 9;
    int k9 = rem % 9;
    g_WRh[(size_t)k9 * CC * CM + (size_t)o * CM + ci] = __float2half(w[i]);
}

// ---------------------------------------------------------------------------
// 3x3 SAME conv on padded fp16 input [66][66][CM] -> [64,64,CC], fp16 mma.
// Block = one output row (64 px) x 64 oc, 256 thr; kc = 64 channels.
// grid (CC/64, 64)
// ---------------------------------------------------------------------------
__global__ void conv3p(const __half* __restrict__ Gp,
                       const float* __restrict__ bias,
                       float* __restrict__ Out) {
    __shared__ __align__(16) __half As[66][72];
    __shared__ __align__(16) __half Bs[3][64][72];
    const int py = blockIdx.y;
    const int n0 = blockIdx.x * 64;
    const int t = threadIdx.x;
    const int warp = t >> 5, lane = t & 31;
    const int wm = warp >> 1, wn = warp & 1;
    const int g = lane >> 2, q = lane & 3;

    float4 acc[4] = {};
    for (int ky = 0; ky < 3; ky++) {
        const __half* arow = Gp + (size_t)(py + ky) * GPW * CM;
        const __half* wky = g_WRh + (size_t)(ky * 3) * CC * CM;
        for (int kc = 0; kc < 8; kc++) {
            const int k0 = kc * 64;
            // A: 66 rows x 64 halfs = 528 16B chunks
#pragma unroll
            for (int i = 0; i < 3; i++) {
                int idx = t + i * 256;
                if (idx < 528) {
                    int row = idx >> 3, c8 = (idx & 7) * 8;
                    *(uint4*)&As[row][c8] =
                        *(const uint4*)(arow + (size_t)row * CM + k0 + c8);
                }
            }
            // B: 3 kx x 64 oc x 64 halfs = 1536 chunks
#pragma unroll
            for (int i = 0; i < 6; i++) {
                int idx = t + i * 256;
                int kx = idx >> 9, w = idx & 511;
                int row = w >> 3, c8 = (w & 7) * 8;
                *(uint4*)&Bs[kx][row][c8] =
                    *(const uint4*)(wky + (size_t)kx * CC * CM +
                                    (size_t)(n0 + row) * CM + k0 + c8);
            }
            __syncthreads();
#pragma unroll
            for (int kx = 0; kx < 3; kx++) {
#pragma unroll
                for (int c = 0; c < 4; c++) {
                    const int kh = (c * 8 + q) * 2;  // half index
                    uint32_t a0 = *(const uint32_t*)&As[wm * 16 + g + kx][kh];
                    uint32_t a1 = *(const uint32_t*)&As[wm * 16 + g + 8 + kx][kh];
                    uint32_t a2 = *(const uint32_t*)&As[wm * 16 + g + kx][kh + 8];
                    uint32_t a3 = *(const uint32_t*)&As[wm * 16 + g + 8 + kx][kh + 8];
#pragma unroll
                    for (int j = 0; j < 4; j++) {
                        uint32_t b0 = *(const uint32_t*)&Bs[kx][wn * 32 + j * 8 + g][kh];
                        uint32_t b1 = *(const uint32_t*)&Bs[kx][wn * 32 + j * 8 + g][kh + 8];
                        mma_f16(acc[j], a0, a1, a2, a3, b0, b1);
                    }
                }
            }
            __syncthreads();
        }
    }
    const int p0 = wm * 16 + g, p1 = p0 + 8;
#pragma unroll
    for (int j = 0; j < 4; j++) {
        const int c = n0 + wn * 32 + j * 8 + q * 2;
        float bx = bias[c], by = bias[c + 1];
        *(float2*)&Out[((size_t)py * 64 + p0) * CC + c] =
            make_float2(acc[j].x + bx, acc[j].y + by);
        *(float2*)&Out[((size_t)py * 64 + p1) * CC + c] =
            make_float2(acc[j].z + bx, acc[j].w + by);
    }
}

// ---------------------------------------------------------------------------
// LayerNorm (256 threads = CC, one row per block)
// ---------------------------------------------------------------------------
__device__ __forceinline__ float block_sum_256(float v, volatile float* red) {
#pragma unroll
    for (int o = 16; o > 0; o >>= 1) v += __shfl_xor_sync(0xffffffffu, v, o);
    if ((threadIdx.x & 31) == 0) red[threadIdx.x >> 5] = v;
    __syncthreads();
    float s = red[0] + red[1] + red[2] + red[3] + red[4] + red[5] + red[6] + red[7];
    __syncthreads();
    return s;
}

__global__ void ln_concat_kernel(const float* __restrict__ Min,
                                 const float* __restrict__ Xin,
                                 const float* __restrict__ g,
                                 const float* __restrict__ b,
                                 float* __restrict__ Y) {
    __shared__ float red[8];
    const int r = blockIdx.x;
    const int t = threadIdx.x;
    float v = Min[(size_t)r * CC + t];
    float mean = block_sum_256(v, red) * (1.0f / CC);
    float d = v - mean;
    float var = block_sum_256(d * d, red) * (1.0f / CC);
    float o = d * rsqrtf(var + 1e-5f) * g[t] + b[t];
    Y[(size_t)r * CM + 256 + t] = o;
    Y[(size_t)r * CM + t] = Xin[(size_t)r * CC + t];
}

__global__ void ln_res_kernel(const float* __restrict__ Cin,
                              const float* __restrict__ Xin,
                              const float* __restrict__ g,
                              const float* __restrict__ b,
                              float* __restrict__ Out) {
    __shared__ float red[8];
    const int r = blockIdx.x;
    const int t = threadIdx.x;
    float v = Cin[(size_t)r * CC + t];
    float mean = block_sum_256(v, red) * (1.0f / CC);
    float d = v - mean;
    float var = block_sum_256(d * d, red) * (1.0f / CC);
    float o = d * rsqrtf(var + 1e-5f) * g[t] + b[t];
    Out[(size_t)r * CC + t] = o + Xin[(size_t)r * CC + t];
}

// ---------------------------------------------------------------------------
// Launch
// ---------------------------------------------------------------------------
extern "C" void kernel_launch(void* const* d_in, const int* in_sizes, int n_in,
                              void* d_out, int out_size) {
    const float* x0 = (const float*)d_in[0];
    const float* x1 = (const float*)d_in[1];
    const float* proj_w = (const float*)d_in[6];
    const float* proj_b = (const float*)d_in[7];
    const float* merge_w = (const float*)d_in[8];
    const float* merge_b = (const float*)d_in[9];
    const float* n0g = (const float*)d_in[10];
    const float* n0b = (const float*)d_in[11];
    const float* lin_w = (const float*)d_in[12];
    const float* lin_b = (const float*)d_in[13];
    const float* conv_w = (const float*)d_in[14];
    const float* conv_b = (const float*)d_in[15];
    const float* n1g = (const float*)d_in[16];
    const float* n1b = (const float*)d_in[17];
    float* out = (float*)d_out;

    void *P0, *P1, *VT0p, *VT1p, *M0p, *M1p, *MM0p, *MM1p, *Y0p, *Y1p,
         *GP0p, *GP1p, *CV0p, *CV1p;
    cudaGetSymbolAddress(&P0, g_P0);
    cudaGetSymbolAddress(&P1, g_P1);
    cudaGetSymbolAddress(&VT0p, g_VT0);
    cudaGetSymbolAddress(&VT1p, g_VT1);
    cudaGetSymbolAddress(&M0p, g_M0);
    cudaGetSymbolAddress(&M1p, g_M1);
    cudaGetSymbolAddress(&MM0p, g_MM0);
    cudaGetSymbolAddress(&MM1p, g_MM1);
    cudaGetSymbolAddress(&Y0p, g_Y0);
    cudaGetSymbolAddress(&Y1p, g_Y1);
    cudaGetSymbolAddress(&GP0p, g_GP0);
    cudaGetSymbolAddress(&GP1p, g_GP1);
    cudaGetSymbolAddress(&CV0p, g_CV0);
    cudaGetSymbolAddress(&CV1p, g_CV1);

    // zero padded conv buffers (borders)
    cudaMemsetAsync(GP0p, 0, (size_t)GPW * GPW * CM * 2);
    cudaMemsetAsync(GP1p, 0, (size_t)GPW * GPW * CM * 2);

    repack_kernel<<<(CC * CM * 9) / 256, 256>>>(conv_w);

    // proj -> tf32 P
    gemm_tc<0, 2><<<dim3(CM / 64, LQ / 64), 256>>>(x0, CC, proj_w, CC, P0, CM, CC, proj_b);
    gemm_tc<0, 2><<<dim3(CM / 64, LQ / 64), 256>>>(x1, CC, proj_w, CC, P1, CM, CC, proj_b);

    // v halves -> fp16 transposed VT
    vt_pack<<<dim3(LQ / 64, NH), 256>>>((const uint32_t*)P0, (__half*)VT0p);
    vt_pack<<<dim3(LQ / 64, NH), 256>>>((const uint32_t*)P1, (__half*)VT1p);

    // dual one-sided flash attention in one launch (z = direction)
    attn_one<<<dim3(LQ / 64, NH, 2), 256>>>(
        (const uint32_t*)P0, (const uint32_t*)P1,
        (const __half*)VT0p, (const __half*)VT1p, (float*)M0p, (float*)M1p);

    // merge
    gemm_tc<0, 0><<<dim3(CC / 64, LQ / 64), 256>>>((const float*)M0p, CC, merge_w, CC, MM0p, CC, CC, merge_b);
    gemm_tc<0, 0><<<dim3(CC / 64, LQ / 64), 256>>>((const float*)M1p, CC, merge_w, CC, MM1p, CC, CC, merge_b);

    // concat with LN
    ln_concat_kernel<<<LQ, 256>>>((const float*)MM0p, x0, n0g, n0b, (float*)Y0p);
    ln_concat_kernel<<<LQ, 256>>>((const float*)MM1p, x1, n0g, n0b, (float*)Y1p);

    // lin + gelu -> padded fp16
    gemm_tc<1, 1><<<dim3(CM / 64, LQ / 64), 256>>>((const float*)Y0p, CM, lin_w, CM, GP0p, CM, CM, lin_b);
    gemm_tc<1, 1><<<dim3(CM / 64, LQ / 64), 256>>>((const float*)Y1p, CM, lin_w, CM, GP1p, CM, CM, lin_b);

    // conv (fp16)
    conv3p<<<dim3(CC / 64, 64), 256>>>((const __half*)GP0p, conv_b, (float*)CV0p);
    conv3p<<<dim3(CC / 64, 64), 256>>>((const __half*)GP1p, conv_b, (float*)CV1p);

    // LN + residual
    ln_res_kernel<<<LQ, 256>>>((const float*)CV0p, x0, n1g, n1b, out);
    ln_res_kernel<<<LQ, 256>>>((const float*)CV1p, x1, n1g, n1b, out + (size_t)LQ * CC);
}

// round 10
// speedup vs baseline: 9.4579x; 1.1974x over previous
#include <cuda_runtime.h>
#include <cuda_fp16.h>
#include <math.h>
#include <stdint.h>

#define LQ 4096
#define CC 256
#define NH 8
#define HD 32
#define CM 512
#define GPW 66   // padded conv width

// ---------------------------------------------------------------------------
// Scratch
// ---------------------------------------------------------------------------
static __device__ __align__(16) __half g_P0h[LQ * CM];       // proj(x0), fp16
static __device__ __align__(16) __half g_P1h[LQ * CM];       // proj(x1), fp16
static __device__ __align__(16) __half g_VT0[NH * HD * LQ];  // v0 transposed [f*HD+d][s]
static __device__ __align__(16) __half g_VT1[NH * HD * LQ];  // v1 transposed
static __device__ float    g_M0[LQ * CC];
static __device__ float    g_M1[LQ * CC];
static __device__ float    g_MM0[LQ * CC];
static __device__ float    g_MM1[LQ * CC];
static __device__ float    g_Y0[LQ * CM];
static __device__ float    g_Y1[LQ * CM];
static __device__ __align__(16) __half g_GP0[GPW * GPW * CM];  // padded gelu(lin), fp16
static __device__ __align__(16) __half g_GP1[GPW * GPW * CM];
static __device__ float    g_CV0[LQ * CC];
static __device__ float    g_CV1[LQ * CC];
static __device__ __align__(16) __half g_WRh[9 * CC * CM];     // conv weights [k9][o][i], fp16

// ---------------------------------------------------------------------------
// helpers
// ---------------------------------------------------------------------------
__device__ __forceinline__ void mma_f16(float4& d, uint32_t a0, uint32_t a1,
                                        uint32_t a2, uint32_t a3,
                                        uint32_t b0, uint32_t b1) {
    asm volatile(
        "mma.sync.aligned.m16n8k16.row.col.f32.f16.f16.f32 "
        "{%0,%1,%2,%3}, {%4,%5,%6,%7}, {%8,%9}, {%0,%1,%2,%3};"
        : "+f"(d.x), "+f"(d.y), "+f"(d.z), "+f"(d.w)
        : "r"(a0), "r"(a1), "r"(a2), "r"(a3), "r"(b0), "r"(b1));
}

__device__ __forceinline__ uint32_t h2u(__half2 h) {
    return *reinterpret_cast<uint32_t*>(&h);
}

// Polynomial exp on FMA pipe (no MUFU).
__device__ __forceinline__ float fexp(float x) {
    float t = x * 1.4426950408889634f;
    t = fminf(fmaxf(t, -126.0f), 126.0f);
    float r = rintf(t);
    float f = t - r;
    float p = 1.33335581e-3f;
    p = fmaf(p, f, 9.61812911e-3f);
    p = fmaf(p, f, 5.55041087e-2f);
    p = fmaf(p, f, 2.40226507e-1f);
    p = fmaf(p, f, 6.93147181e-1f);
    p = fmaf(p, f, 1.0f);
    return p * __int_as_float(((int)r + 127) << 23);
}

__device__ __forceinline__ uint32_t sptr(const void* p) {
    return (uint32_t)__cvta_generic_to_shared(p);
}
#define CP16(dst, src) \
    asm volatile("cp.async.cg.shared.global [%0], [%1], 16;" :: "r"(dst), "l"(src))

// ---------------------------------------------------------------------------
// fp16 GEMM: C = A @ B^T + bias, fp32 accumulate. A,B fp32 in (converted
// inline). MODE: 0 = fp32 C, 1 = fp16 C into padded conv layout (with GELU),
// 2 = fp16 C plain. Block 64x64, 256 thr, BK=16 (one k16 mma step).
// ---------------------------------------------------------------------------
template <int GELU, int MODE>
__global__ void gemm_f16k(const float* __restrict__ A, int lda,
                          const float* __restrict__ B, int ldb,
                          void* __restrict__ Cv, int ldc,
                          int K, const float* __restrict__ bias) {
    __shared__ __align__(16) __half As[64][40];
    __shared__ __align__(16) __half Bs[64][40];
    const int m0 = blockIdx.y * 64;
    const int n0 = blockIdx.x * 64;
    const int t = threadIdx.x;
    const int warp = t >> 5, lane = t & 31;
    const int wm = warp >> 1, wn = warp & 1;
    const int g = lane >> 2, q = lane & 3;
    const int lr = t >> 2, lq = t & 3;

    float4 acc[4] = {};
    for (int k0 = 0; k0 < K; k0 += 16) {
        float4 av = *(const float4*)(A + (size_t)(m0 + lr) * lda + k0 + lq * 4);
        float4 bv = *(const float4*)(B + (size_t)(n0 + lr) * ldb + k0 + lq * 4);
        uint2 au = {h2u(__floats2half2_rn(av.x, av.y)), h2u(__floats2half2_rn(av.z, av.w))};
        uint2 bu = {h2u(__floats2half2_rn(bv.x, bv.y)), h2u(__floats2half2_rn(bv.z, bv.w))};
        *(uint2*)&As[lr][lq * 4] = au;
        *(uint2*)&Bs[lr][lq * 4] = bu;
        __syncthreads();
        uint32_t a0 = *(const uint32_t*)&As[wm * 16 + g][2 * q];
        uint32_t a1 = *(const uint32_t*)&As[wm * 16 + g + 8][2 * q];
        uint32_t a2 = *(const uint32_t*)&As[wm * 16 + g][2 * q + 8];
        uint32_t a3 = *(const uint32_t*)&As[wm * 16 + g + 8][2 * q + 8];
#pragma unroll
        for (int j = 0; j < 4; j++) {
            uint32_t b0 = *(const uint32_t*)&Bs[wn * 32 + j * 8 + g][2 * q];
            uint32_t b1 = *(const uint32_t*)&Bs[wn * 32 + j * 8 + g][2 * q + 8];
            mma_f16(acc[j], a0, a1, a2, a3, b0, b1);
        }
        __syncthreads();
    }
    const int r0 = m0 + wm * 16 + g, r1 = r0 + 8;
#pragma unroll
    for (int j = 0; j < 4; j++) {
        const int c = n0 + wn * 32 + j * 8 + q * 2;
        float bx = bias ? bias[c] : 0.f, by = bias ? bias[c + 1] : 0.f;
        float v00 = acc[j].x + bx, v01 = acc[j].y + by;
        float v10 = acc[j].z + bx, v11 = acc[j].w + by;
        if (GELU) {
            v00 = 0.5f * v00 * (1.0f + erff(v00 * 0.70710678118f));
            v01 = 0.5f * v01 * (1.0f + erff(v01 * 0.70710678118f));
            v10 = 0.5f * v10 * (1.0f + erff(v10 * 0.70710678118f));
            v11 = 0.5f * v11 * (1.0f + erff(v11 * 0.70710678118f));
        }
        if (MODE == 0) {
            float* C = (float*)Cv;
            *(float2*)&C[(size_t)r0 * ldc + c] = make_float2(v00, v01);
            *(float2*)&C[(size_t)r1 * ldc + c] = make_float2(v10, v11);
        } else if (MODE == 1) {
            __half* C = (__half*)Cv;
            size_t o0 = ((size_t)((r0 >> 6) + 1) * GPW + (r0 & 63) + 1) * CM + c;
            size_t o1 = ((size_t)((r1 >> 6) + 1) * GPW + (r1 & 63) + 1) * CM + c;
            *(__half2*)&C[o0] = __floats2half2_rn(v00, v01);
            *(__half2*)&C[o1] = __floats2half2_rn(v10, v11);
        } else {
            __half* C = (__half*)Cv;
            *(__half2*)&C[(size_t)r0 * ldc + c] = __floats2half2_rn(v00, v01);
            *(__half2*)&C[(size_t)r1 * ldc + c] = __floats2half2_rn(v10, v11);
        }
    }
}

// ---------------------------------------------------------------------------
// VT pack: P's v-half (fp16) -> fp16 transposed VT[f*HD+d][s]
// grid (LQ/64, NH), 256 thr.
// ---------------------------------------------------------------------------
__global__ void vt_pack(const __half* __restrict__ P, __half* __restrict__ VT) {
    __shared__ __half Sh[64][33];
    const int s0 = blockIdx.x * 64, f = blockIdx.y;
    const int t = threadIdx.x;
    {
        int r = t >> 2, dg = (t & 3) * 8;
        const __half* src = P + (size_t)(s0 + r) * CM + 256 + f * HD + dg;
        uint4 u = *(const uint4*)src;
        const __half* h = (const __half*)&u;
#pragma unroll
        for (int i = 0; i < 8; i++) Sh[r][dg + i] = h[i];
    }
    __syncthreads();
    {
        int d = t >> 3, sg = (t & 7) * 8;
        __half2 p0 = __halves2half2(Sh[sg + 0][d], Sh[sg + 1][d]);
        __half2 p1 = __halves2half2(Sh[sg + 2][d], Sh[sg + 3][d]);
        __half2 p2 = __halves2half2(Sh[sg + 4][d], Sh[sg + 5][d]);
        __half2 p3 = __halves2half2(Sh[sg + 6][d], Sh[sg + 7][d]);
        uint4 u = {h2u(p0), h2u(p1), h2u(p2), h2u(p3)};
        *(uint4*)(VT + (size_t)(f * HD + d) * LQ + s0 + sg) = u;
    }
}

// ---------------------------------------------------------------------------
// One-sided flash attention, all-fp16 operands (fp32 accum), register E.
// grid (LQ/64, NH, 2), 256 thr.
// ---------------------------------------------------------------------------
__global__ __launch_bounds__(256, 3) void attn_one(
        const __half* __restrict__ P0, const __half* __restrict__ P1,
        const __half* __restrict__ VT0, const __half* __restrict__ VT1,
        float* __restrict__ M0, float* __restrict__ M1) {
    __shared__ __align__(16) __half Kb[2][64][56];   // [s][k halfs], 112B rows
    __shared__ __align__(16) __half Aq[64][56];      // q tile
    __shared__ __align__(16) __half Vh[2][32][72];   // [d][k=s halfs]
    __shared__ float sRS[2][64];
    __shared__ __align__(8) float redM[4][16][34];
    const int f = blockIdx.y;
    const int l0 = blockIdx.x * 64;
    const int dir = blockIdx.z;
    const __half* A = (dir ? P1 : P0) + f * HD;
    const __half* B = (dir ? P0 : P1) + f * HD;
    const __half* VTf = (dir ? VT0 : VT1) + (size_t)f * HD * LQ;
    float* OUT = dir ? M1 : M0;
    const int t = threadIdx.x;
    const int warp = t >> 5, lane = t & 31;
    const int wm = warp >> 1, wn = warp & 1;
    const int g = lane >> 2, q = lane & 3;
    const int krow = t >> 2, kc8 = (t & 3) * 8;      // K/q tile loader
    const int vd = t >> 3, vc8 = (t & 7) * 8;        // V tile loader

    // prefetch s-tile 0 (async) + stage q tile (sync)
    CP16(sptr(&Kb[0][krow][kc8]), B + (size_t)krow * CM + kc8);
    CP16(sptr(&Vh[0][vd][vc8]), VTf + (size_t)vd * LQ + vc8);
    asm volatile("cp.async.commit_group;");
    *(uint4*)&Aq[krow][kc8] = *(const uint4*)(A + (size_t)(l0 + krow) * CM + kc8);
    __syncthreads();
    uint32_t aq[2][4];
#pragma unroll
    for (int ks = 0; ks < 2; ks++) {
        const int kb = ks * 16;
        aq[ks][0] = *(const uint32_t*)&Aq[wm * 16 + g][kb + 2 * q];
        aq[ks][1] = *(const uint32_t*)&Aq[wm * 16 + g + 8][kb + 2 * q];
        aq[ks][2] = *(const uint32_t*)&Aq[wm * 16 + g][kb + 2 * q + 8];
        aq[ks][3] = *(const uint32_t*)&Aq[wm * 16 + g + 8][kb + 2 * q + 8];
    }
    asm volatile("cp.async.wait_group 0;" ::: "memory");
    __syncthreads();

    const float SC = 0.17677669529663687f;
    float4 macc[4] = {};
    float rs0 = 0.f, rs1 = 0.f;

    for (int it = 0; it < 64; it++) {
        const int cur = it & 1;
        if (it < 63) {
            CP16(sptr(&Kb[cur ^ 1][krow][kc8]),
                 B + (size_t)((it + 1) * 64 + krow) * CM + kc8);
            CP16(sptr(&Vh[cur ^ 1][vd][vc8]),
                 VTf + (size_t)vd * LQ + (it + 1) * 64 + vc8);
            asm volatile("cp.async.commit_group;");
        }
        // S = qA @ qB^T (rows wm*16.., cols wn*32 + j*8), fp16
        float4 sacc[4] = {};
#pragma unroll
        for (int ks = 0; ks < 2; ks++) {
            const int kb = ks * 16;
#pragma unroll
            for (int j = 0; j < 4; j++) {
                uint32_t b0 = *(const uint32_t*)&Kb[cur][wn * 32 + j * 8 + g][kb + 2 * q];
                uint32_t b1 = *(const uint32_t*)&Kb[cur][wn * 32 + j * 8 + g][kb + 2 * q + 8];
                mma_f16(sacc[j], aq[ks][0], aq[ks][1], aq[ks][2], aq[ks][3], b0, b1);
            }
        }
        // per k16 chunk: E (fp32), row sums, pack to fp16 A-frags, AV mma
#pragma unroll
        for (int c = 0; c < 2; c++) {
            const float4 sa = sacc[2 * c], sb = sacc[2 * c + 1];
            float e00 = fexp(sa.x * SC), e01 = fexp(sa.y * SC);
            float e02 = fexp(sa.z * SC), e03 = fexp(sa.w * SC);
            float e10 = fexp(sb.x * SC), e11 = fexp(sb.y * SC);
            float e12 = fexp(sb.z * SC), e13 = fexp(sb.w * SC);
            rs0 += e00 + e01 + e10 + e11;
            rs1 += e02 + e03 + e12 + e13;
            uint32_t a0 = h2u(__floats2half2_rn(e00, e01));
            uint32_t a1 = h2u(__floats2half2_rn(e02, e03));
            uint32_t a2 = h2u(__floats2half2_rn(e10, e11));
            uint32_t a3 = h2u(__floats2half2_rn(e12, e13));
            const int kh = (wn * 16 + c * 8 + q) * 2;
#pragma unroll
            for (int jj = 0; jj < 4; jj++) {
                uint32_t b0 = *(const uint32_t*)&Vh[cur][jj * 8 + g][kh];
                uint32_t b1 = *(const uint32_t*)&Vh[cur][jj * 8 + g][kh + 8];
                mma_f16(macc[jj], a0, a1, a2, a3, b0, b1);
            }
        }
        asm volatile("cp.async.wait_group 0;" ::: "memory");
        __syncthreads();
    }
    // row sums: reduce over q, publish per wn half
    rs0 += __shfl_xor_sync(0xffffffffu, rs0, 1);
    rs0 += __shfl_xor_sync(0xffffffffu, rs0, 2);
    rs1 += __shfl_xor_sync(0xffffffffu, rs1, 1);
    rs1 += __shfl_xor_sync(0xffffffffu, rs1, 2);
    if (q == 0) {
        sRS[wn][wm * 16 + g] = rs0;
        sRS[wn][wm * 16 + g + 8] = rs1;
    }
    // wn=0 parks its AV partials
    if (wn == 0) {
#pragma unroll
        for (int jj = 0; jj < 4; jj++) {
            *(float2*)&redM[wm][g][jj * 8 + 2 * q] = make_float2(macc[jj].x, macc[jj].y);
            *(float2*)&redM[wm][g + 8][jj * 8 + 2 * q] = make_float2(macc[jj].z, macc[jj].w);
        }
    }
    __syncthreads();
    // wn=1 combines, normalizes, writes
    if (wn == 1) {
        const int r0 = wm * 16 + g, r1 = r0 + 8;
        const float i0 = __frcp_rn(sRS[0][r0] + sRS[1][r0]);
        const float i1 = __frcp_rn(sRS[0][r1] + sRS[1][r1]);
#pragma unroll
        for (int jj = 0; jj < 4; jj++) {
            float2 p0 = *(float2*)&redM[wm][g][jj * 8 + 2 * q];
            float2 p1 = *(float2*)&redM[wm][g + 8][jj * 8 + 2 * q];
            const int c = f * HD + jj * 8 + 2 * q;
            *(float2*)&OUT[(size_t)(l0 + r0) * CC + c] =
                make_float2((macc[jj].x + p0.x) * i0, (macc[jj].y + p0.y) * i0);
            *(float2*)&OUT[(size_t)(l0 + r1) * CC + c] =
                make_float2((macc[jj].z + p1.x) * i1, (macc[jj].w + p1.y) * i1);
        }
    }
}

// ---------------------------------------------------------------------------
// conv weight repack OIHW -> [k9][o][i], fp16
// ---------------------------------------------------------------------------
__global__ void repack_kernel(const float* __restrict__ w) {
    int i = blockIdx.x * 256 + threadIdx.x;
    int o = i / (CM * 9);
    int rem = i % (CM * 9);
    int ci = rem / 9;
    int k9 = rem % 9;
    g_WRh[(size_t)k9 * CC * CM + (size_t)o * CM + ci] = __float2half(w[i]);
}

// ---------------------------------------------------------------------------
// 3x3 SAME conv on padded fp16 input [66][66][CM] -> [64,64,CC], fp16 mma.
// grid (CC/64, 64)
// ---------------------------------------------------------------------------
__global__ void conv3p(const __half* __restrict__ Gp,
                       const float* __restrict__ bias,
                       float* __restrict__ Out) {
    __shared__ __align__(16) __half As[66][72];
    __shared__ __align__(16) __half Bs[3][64][72];
    const int py = blockIdx.y;
    const int n0 = blockIdx.x * 64;
    const int t = threadIdx.x;
    const int warp = t >> 5, lane = t & 31;
    const int wm = warp >> 1, wn = warp & 1;
    const int g = lane >> 2, q = lane & 3;

    float4 acc[4] = {};
    for (int ky = 0; ky < 3; ky++) {
        const __half* arow = Gp + (size_t)(py + ky) * GPW * CM;
        const __half* wky = g_WRh + (size_t)(ky * 3) * CC * CM;
        for (int kc = 0; kc < 8; kc++) {
            const int k0 = kc * 64;
#pragma unroll
            for (int i = 0; i < 3; i++) {
                int idx = t + i * 256;
                if (idx < 528) {
                    int row = idx >> 3, c8 = (idx & 7) * 8;
                    *(uint4*)&As[row][c8] =
                        *(const uint4*)(arow + (size_t)row * CM + k0 + c8);
                }
            }
#pragma unroll
            for (int i = 0; i < 6; i++) {
                int idx = t + i * 256;
                int kx = idx >> 9, w = idx & 511;
                int row = w >> 3, c8 = (w & 7) * 8;
                *(uint4*)&Bs[kx][row][c8] =
                    *(const uint4*)(wky + (size_t)kx * CC * CM +
                                    (size_t)(n0 + row) * CM + k0 + c8);
            }
            __syncthreads();
#pragma unroll
            for (int kx = 0; kx < 3; kx++) {
#pragma unroll
                for (int c = 0; c < 4; c++) {
                    const int kh = (c * 8 + q) * 2;
                    uint32_t a0 = *(const uint32_t*)&As[wm * 16 + g + kx][kh];
                    uint32_t a1 = *(const uint32_t*)&As[wm * 16 + g + 8 + kx][kh];
                    uint32_t a2 = *(const uint32_t*)&As[wm * 16 + g + kx][kh + 8];
                    uint32_t a3 = *(const uint32_t*)&As[wm * 16 + g + 8 + kx][kh + 8];
#pragma unroll
                    for (int j = 0; j < 4; j++) {
                        uint32_t b0 = *(const uint32_t*)&Bs[kx][wn * 32 + j * 8 + g][kh];
                        uint32_t b1 = *(const uint32_t*)&Bs[kx][wn * 32 + j * 8 + g][kh + 8];
                        mma_f16(acc[j], a0, a1, a2, a3, b0, b1);
                    }
                }
            }
            __syncthreads();
        }
    }
    const int p0 = wm * 16 + g, p1 = p0 + 8;
#pragma unroll
    for (int j = 0; j < 4; j++) {
        const int c = n0 + wn * 32 + j * 8 + q * 2;
        float bx = bias[c], by = bias[c + 1];
        *(float2*)&Out[((size_t)py * 64 + p0) * CC + c] =
            make_float2(acc[j].x + bx, acc[j].y + by);
        *(float2*)&Out[((size_t)py * 64 + p1) * CC + c] =
            make_float2(acc[j].z + bx, acc[j].w + by);
    }
}

// ---------------------------------------------------------------------------
// LayerNorm (256 threads = CC, one row per block)
// ---------------------------------------------------------------------------
__device__ __forceinline__ float block_sum_256(float v, volatile float* red) {
#pragma unroll
    for (int o = 16; o > 0; o >>= 1) v += __shfl_xor_sync(0xffffffffu, v, o);
    if ((threadIdx.x & 31) == 0) red[threadIdx.x >> 5] = v;
    __syncthreads();
    float s = red[0] + red[1] + red[2] + red[3] + red[4] + red[5] + red[6] + red[7];
    __syncthreads();
    return s;
}

__global__ void ln_concat_kernel(const float* __restrict__ Min,
                                 const float* __restrict__ Xin,
                                 const float* __restrict__ g,
                                 const float* __restrict__ b,
                                 float* __restrict__ Y) {
    __shared__ float red[8];
    const int r = blockIdx.x;
    const int t = threadIdx.x;
    float v = Min[(size_t)r * CC + t];
    float mean = block_sum_256(v, red) * (1.0f / CC);
    float d = v - mean;
    float var = block_sum_256(d * d, red) * (1.0f / CC);
    float o = d * rsqrtf(var + 1e-5f) * g[t] + b[t];
    Y[(size_t)r * CM + 256 + t] = o;
    Y[(size_t)r * CM + t] = Xin[(size_t)r * CC + t];
}

__global__ void ln_res_kernel(const float* __restrict__ Cin,
                              const float* __restrict__ Xin,
                              const float* __restrict__ g,
                              const float* __restrict__ b,
                              float* __restrict__ Out) {
    __shared__ float red[8];
    const int r = blockIdx.x;
    const int t = threadIdx.x;
    float v = Cin[(size_t)r * CC + t];
    float mean = block_sum_256(v, red) * (1.0f / CC);
    float d = v - mean;
    float var = block_sum_256(d * d, red) * (1.0f / CC);
    float o = d * rsqrtf(var + 1e-5f) * g[t] + b[t];
    Out[(size_t)r * CC + t] = o + Xin[(size_t)r * CC + t];
}

// ---------------------------------------------------------------------------
// Launch
// ---------------------------------------------------------------------------
extern "C" void kernel_launch(void* const* d_in, const int* in_sizes, int n_in,
                              void* d_out, int out_size) {
    const float* x0 = (const float*)d_in[0];
    const float* x1 = (const float*)d_in[1];
    const float* proj_w = (const float*)d_in[6];
    const float* proj_b = (const float*)d_in[7];
    const float* merge_w = (const float*)d_in[8];
    const float* merge_b = (const float*)d_in[9];
    const float* n0g = (const float*)d_in[10];
    const float* n0b = (const float*)d_in[11];
    const float* lin_w = (const float*)d_in[12];
    const float* lin_b = (const float*)d_in[13];
    const float* conv_w = (const float*)d_in[14];
    const float* conv_b = (const float*)d_in[15];
    const float* n1g = (const float*)d_in[16];
    const float* n1b = (const float*)d_in[17];
    float* out = (float*)d_out;

    void *P0, *P1, *VT0p, *VT1p, *M0p, *M1p, *MM0p, *MM1p, *Y0p, *Y1p,
         *GP0p, *GP1p, *CV0p, *CV1p;
    cudaGetSymbolAddress(&P0, g_P0h);
    cudaGetSymbolAddress(&P1, g_P1h);
    cudaGetSymbolAddress(&VT0p, g_VT0);
    cudaGetSymbolAddress(&VT1p, g_VT1);
    cudaGetSymbolAddress(&M0p, g_M0);
    cudaGetSymbolAddress(&M1p, g_M1);
    cudaGetSymbolAddress(&MM0p, g_MM0);
    cudaGetSymbolAddress(&MM1p, g_MM1);
    cudaGetSymbolAddress(&Y0p, g_Y0);
    cudaGetSymbolAddress(&Y1p, g_Y1);
    cudaGetSymbolAddress(&GP0p, g_GP0);
    cudaGetSymbolAddress(&GP1p, g_GP1);
    cudaGetSymbolAddress(&CV0p, g_CV0);
    cudaGetSymbolAddress(&CV1p, g_CV1);

    // zero padded conv buffers (borders)
    cudaMemsetAsync(GP0p, 0, (size_t)GPW * GPW * CM * 2);
    cudaMemsetAsync(GP1p, 0, (size_t)GPW * GPW * CM * 2);

    repack_kernel<<<(CC * CM * 9) / 256, 256>>>(conv_w);

    // proj -> fp16 P
    gemm_f16k<0, 2><<<dim3(CM / 64, LQ / 64), 256>>>(x0, CC, proj_w, CC, P0, CM, CC, proj_b);
    gemm_f16k<0, 2><<<dim3(CM / 64, LQ / 64), 256>>>(x1, CC, proj_w, CC, P1, CM, CC, proj_b);

    // v halves -> fp16 transposed VT
    vt_pack<<<dim3(LQ / 64, NH), 256>>>((const __half*)P0, (__half*)VT0p);
    vt_pack<<<dim3(LQ / 64, NH), 256>>>((const __half*)P1, (__half*)VT1p);

    // dual one-sided flash attention in one launch (z = direction)
    attn_one<<<dim3(LQ / 64, NH, 2), 256>>>(
        (const __half*)P0, (const __half*)P1,
        (const __half*)VT0p, (const __half*)VT1p, (float*)M0p, (float*)M1p);

    // merge
    gemm_f16k<0, 0><<<dim3(CC / 64, LQ / 64), 256>>>((const float*)M0p, CC, merge_w, CC, MM0p, CC, CC, merge_b);
    gemm_f16k<0, 0><<<dim3(CC / 64, LQ / 64), 256>>>((const float*)M1p, CC, merge_w, CC, MM1p, CC, CC, merge_b);

    // concat with LN
    ln_concat_kernel<<<LQ, 256>>>((const float*)MM0p, x0, n0g, n0b, (float*)Y0p);
    ln_concat_kernel<<<LQ, 256>>>((const float*)MM1p, x1, n0g, n0b, (float*)Y1p);

    // lin + gelu -> padded fp16
    gemm_f16k<1, 1><<<dim3(CM / 64, LQ / 64), 256>>>((const float*)Y0p, CM, lin_w, CM, GP0p, CM, CM, lin_b);
    gemm_f16k<1, 1><<<dim3(CM / 64, LQ / 64), 256>>>((const float*)Y1p, CM, lin_w, CM, GP1p, CM, CM, lin_b);

    // conv (fp16)
    conv3p<<<dim3(CC / 64, 64), 256>>>((const __half*)GP0p, conv_b, (float*)CV0p);
    conv3p<<<dim3(CC / 64, 64), 256>>>((const __half*)GP1p, conv_b, (float*)CV1p);

    // LN + residual
    ln_res_kernel<<<LQ, 256>>>((const float*)CV0p, x0, n1g, n1b, out);
    ln_res_kernel<<<LQ, 256>>>((const float*)CV1p, x1, n1g, n1b, out + (size_t)LQ * CC);
}

// round 11
// speedup vs baseline: 11.2726x; 1.1919x over previous
#include <cuda_runtime.h>
#include <cuda_fp16.h>
#include <math.h>
#include <stdint.h>

#define LQ 4096
#define CC 256
#define NH 8
#define HD 32
#define CM 512
#define GPW 66   // padded conv width

// ---------------------------------------------------------------------------
// Scratch
// ---------------------------------------------------------------------------
static __device__ __align__(16) __half g_P0h[LQ * CM];       // proj(x0), fp16
static __device__ __align__(16) __half g_P1h[LQ * CM];       // proj(x1), fp16
static __device__ __align__(16) __half g_VT0[NH * HD * LQ];  // v0 transposed [f*HD+d][s]
static __device__ __align__(16) __half g_VT1[NH * HD * LQ];  // v1 transposed
static __device__ float    g_M0[LQ * CC];
static __device__ float    g_M1[LQ * CC];
static __device__ float    g_MM0[LQ * CC];
static __device__ float    g_MM1[LQ * CC];
static __device__ float    g_Y0[LQ * CM];
static __device__ float    g_Y1[LQ * CM];
static __device__ __align__(16) __half g_GP0[GPW * GPW * CM];  // padded gelu(lin), fp16
static __device__ __align__(16) __half g_GP1[GPW * GPW * CM];
static __device__ float    g_CV0[LQ * CC];
static __device__ float    g_CV1[LQ * CC];
static __device__ __align__(16) __half g_WRh[9 * CC * CM];     // conv weights [k9][o][i], fp16

// ---------------------------------------------------------------------------
// helpers
// ---------------------------------------------------------------------------
__device__ __forceinline__ void mma_f16(float4& d, uint32_t a0, uint32_t a1,
                                        uint32_t a2, uint32_t a3,
                                        uint32_t b0, uint32_t b1) {
    asm volatile(
        "mma.sync.aligned.m16n8k16.row.col.f32.f16.f16.f32 "
        "{%0,%1,%2,%3}, {%4,%5,%6,%7}, {%8,%9}, {%0,%1,%2,%3};"
        : "+f"(d.x), "+f"(d.y), "+f"(d.z), "+f"(d.w)
        : "r"(a0), "r"(a1), "r"(a2), "r"(a3), "r"(b0), "r"(b1));
}

__device__ __forceinline__ uint32_t h2u(__half2 h) {
    return *reinterpret_cast<uint32_t*>(&h);
}
__device__ __forceinline__ __half2 u2h(uint32_t u) {
    return *reinterpret_cast<__half2*>(&u);
}

__device__ __forceinline__ uint32_t sptr(const void* p) {
    return (uint32_t)__cvta_generic_to_shared(p);
}
#define CP16(dst, src) \
    asm volatile("cp.async.cg.shared.global [%0], [%1], 16;" :: "r"(dst), "l"(src))

// ---------------------------------------------------------------------------
// fp16 GEMM: C = A @ B^T + bias, fp32 accumulate. A,B fp32 in (converted
// inline). MODE: 0 = fp32 C, 1 = fp16 C into padded conv layout (with GELU),
// 2 = fp16 C plain. Block 64x64, 256 thr, BK=32 (two k16 steps per phase).
// ---------------------------------------------------------------------------
template <int GELU, int MODE>
__global__ void gemm_f16k(const float* __restrict__ A, int lda,
                          const float* __restrict__ B, int ldb,
                          void* __restrict__ Cv, int ldc,
                          int K, const float* __restrict__ bias) {
    __shared__ __align__(16) __half As[64][72];
    __shared__ __align__(16) __half Bs[64][72];
    const int m0 = blockIdx.y * 64;
    const int n0 = blockIdx.x * 64;
    const int t = threadIdx.x;
    const int warp = t >> 5, lane = t & 31;
    const int wm = warp >> 1, wn = warp & 1;
    const int g = lane >> 2, q = lane & 3;
    const int lr = t >> 2, c8 = (t & 3) * 8;

    float4 acc[4] = {};
    for (int k0 = 0; k0 < K; k0 += 32) {
        float4 av0 = *(const float4*)(A + (size_t)(m0 + lr) * lda + k0 + c8);
        float4 av1 = *(const float4*)(A + (size_t)(m0 + lr) * lda + k0 + c8 + 4);
        float4 bv0 = *(const float4*)(B + (size_t)(n0 + lr) * ldb + k0 + c8);
        float4 bv1 = *(const float4*)(B + (size_t)(n0 + lr) * ldb + k0 + c8 + 4);
        uint4 au = {h2u(__floats2half2_rn(av0.x, av0.y)), h2u(__floats2half2_rn(av0.z, av0.w)),
                    h2u(__floats2half2_rn(av1.x, av1.y)), h2u(__floats2half2_rn(av1.z, av1.w))};
        uint4 bu = {h2u(__floats2half2_rn(bv0.x, bv0.y)), h2u(__floats2half2_rn(bv0.z, bv0.w)),
                    h2u(__floats2half2_rn(bv1.x, bv1.y)), h2u(__floats2half2_rn(bv1.z, bv1.w))};
        *(uint4*)&As[lr][c8] = au;
        *(uint4*)&Bs[lr][c8] = bu;
        __syncthreads();
#pragma unroll
        for (int ks = 0; ks < 2; ks++) {
            const int kb = ks * 16;
            uint32_t a0 = *(const uint32_t*)&As[wm * 16 + g][kb + 2 * q];
            uint32_t a1 = *(const uint32_t*)&As[wm * 16 + g + 8][kb + 2 * q];
            uint32_t a2 = *(const uint32_t*)&As[wm * 16 + g][kb + 2 * q + 8];
            uint32_t a3 = *(const uint32_t*)&As[wm * 16 + g + 8][kb + 2 * q + 8];
#pragma unroll
            for (int j = 0; j < 4; j++) {
                uint32_t b0 = *(const uint32_t*)&Bs[wn * 32 + j * 8 + g][kb + 2 * q];
                uint32_t b1 = *(const uint32_t*)&Bs[wn * 32 + j * 8 + g][kb + 2 * q + 8];
                mma_f16(acc[j], a0, a1, a2, a3, b0, b1);
            }
        }
        __syncthreads();
    }
    const int r0 = m0 + wm * 16 + g, r1 = r0 + 8;
#pragma unroll
    for (int j = 0; j < 4; j++) {
        const int c = n0 + wn * 32 + j * 8 + q * 2;
        float bx = bias ? bias[c] : 0.f, by = bias ? bias[c + 1] : 0.f;
        float v00 = acc[j].x + bx, v01 = acc[j].y + by;
        float v10 = acc[j].z + bx, v11 = acc[j].w + by;
        if (GELU) {
            v00 = 0.5f * v00 * (1.0f + erff(v00 * 0.70710678118f));
            v01 = 0.5f * v01 * (1.0f + erff(v01 * 0.70710678118f));
            v10 = 0.5f * v10 * (1.0f + erff(v10 * 0.70710678118f));
            v11 = 0.5f * v11 * (1.0f + erff(v11 * 0.70710678118f));
        }
        if (MODE == 0) {
            float* C = (float*)Cv;
            *(float2*)&C[(size_t)r0 * ldc + c] = make_float2(v00, v01);
            *(float2*)&C[(size_t)r1 * ldc + c] = make_float2(v10, v11);
        } else if (MODE == 1) {
            __half* C = (__half*)Cv;
            size_t o0 = ((size_t)((r0 >> 6) + 1) * GPW + (r0 & 63) + 1) * CM + c;
            size_t o1 = ((size_t)((r1 >> 6) + 1) * GPW + (r1 & 63) + 1) * CM + c;
            *(__half2*)&C[o0] = __floats2half2_rn(v00, v01);
            *(__half2*)&C[o1] = __floats2half2_rn(v10, v11);
        } else {
            __half* C = (__half*)Cv;
            *(__half2*)&C[(size_t)r0 * ldc + c] = __floats2half2_rn(v00, v01);
            *(__half2*)&C[(size_t)r1 * ldc + c] = __floats2half2_rn(v10, v11);
        }
    }
}

// ---------------------------------------------------------------------------
// VT pack: P's v-half (fp16) -> fp16 transposed VT[f*HD+d][s]
// grid (LQ/64, NH), 256 thr.
// ---------------------------------------------------------------------------
__global__ void vt_pack(const __half* __restrict__ P, __half* __restrict__ VT) {
    __shared__ __half Sh[64][33];
    const int s0 = blockIdx.x * 64, f = blockIdx.y;
    const int t = threadIdx.x;
    {
        int r = t >> 2, dg = (t & 3) * 8;
        const __half* src = P + (size_t)(s0 + r) * CM + 256 + f * HD + dg;
        uint4 u = *(const uint4*)src;
        const __half* h = (const __half*)&u;
#pragma unroll
        for (int i = 0; i < 8; i++) Sh[r][dg + i] = h[i];
    }
    __syncthreads();
    {
        int d = t >> 3, sg = (t & 7) * 8;
        __half2 p0 = __halves2half2(Sh[sg + 0][d], Sh[sg + 1][d]);
        __half2 p1 = __halves2half2(Sh[sg + 2][d], Sh[sg + 3][d]);
        __half2 p2 = __halves2half2(Sh[sg + 4][d], Sh[sg + 5][d]);
        __half2 p3 = __halves2half2(Sh[sg + 6][d], Sh[sg + 7][d]);
        uint4 u = {h2u(p0), h2u(p1), h2u(p2), h2u(p3)};
        *(uint4*)(VT + (size_t)(f * HD + d) * LQ + s0 + sg) = u;
    }
}

// ---------------------------------------------------------------------------
// One-sided flash attention, all-fp16, E via MUFU ex2.f16x2.
// SC*log2e folded into q A-frags at staging; S-mma emits log2-domain scores;
// h2exp2 output half2s ARE the AV A-fragments. grid (LQ/64, NH, 2), 256 thr.
// ---------------------------------------------------------------------------
__global__ __launch_bounds__(256, 3) void attn_one(
        const __half* __restrict__ P0, const __half* __restrict__ P1,
        const __half* __restrict__ VT0, const __half* __restrict__ VT1,
        float* __restrict__ M0, float* __restrict__ M1) {
    __shared__ __align__(16) __half Kb[2][64][56];   // [s][k halfs], 112B rows
    __shared__ __align__(16) __half Aq[64][56];      // q tile
    __shared__ __align__(16) __half Vh[2][32][72];   // [d][k=s halfs]
    __shared__ float sRS[2][64];
    __shared__ __align__(8) float redM[4][16][34];
    const int f = blockIdx.y;
    const int l0 = blockIdx.x * 64;
    const int dir = blockIdx.z;
    const __half* A = (dir ? P1 : P0) + f * HD;
    const __half* B = (dir ? P0 : P1) + f * HD;
    const __half* VTf = (dir ? VT0 : VT1) + (size_t)f * HD * LQ;
    float* OUT = dir ? M1 : M0;
    const int t = threadIdx.x;
    const int warp = t >> 5, lane = t & 31;
    const int wm = warp >> 1, wn = warp & 1;
    const int g = lane >> 2, q = lane & 3;
    const int krow = t >> 2, kc8 = (t & 3) * 8;      // K/q tile loader
    const int vd = t >> 3, vc8 = (t & 7) * 8;        // V tile loader

    // prefetch s-tile 0 (async) + stage q tile (sync)
    CP16(sptr(&Kb[0][krow][kc8]), B + (size_t)krow * CM + kc8);
    CP16(sptr(&Vh[0][vd][vc8]), VTf + (size_t)vd * LQ + vc8);
    asm volatile("cp.async.commit_group;");
    *(uint4*)&Aq[krow][kc8] = *(const uint4*)(A + (size_t)(l0 + krow) * CM + kc8);
    __syncthreads();
    // q frags, scaled by SC*log2e so S-mma yields log2-domain scores
    const __half2 scl = __float2half2_rn(0.17677669529663687f * 1.4426950408889634f);
    uint32_t aq[2][4];
#pragma unroll
    for (int ks = 0; ks < 2; ks++) {
        const int kb = ks * 16;
        aq[ks][0] = h2u(__hmul2(*(const __half2*)&Aq[wm * 16 + g][kb + 2 * q], scl));
        aq[ks][1] = h2u(__hmul2(*(const __half2*)&Aq[wm * 16 + g + 8][kb + 2 * q], scl));
        aq[ks][2] = h2u(__hmul2(*(const __half2*)&Aq[wm * 16 + g][kb + 2 * q + 8], scl));
        aq[ks][3] = h2u(__hmul2(*(const __half2*)&Aq[wm * 16 + g + 8][kb + 2 * q + 8], scl));
    }
    asm volatile("cp.async.wait_group 0;" ::: "memory");
    __syncthreads();

    float4 macc[4] = {};
    float rs0 = 0.f, rs1 = 0.f;

    for (int it = 0; it < 64; it++) {
        const int cur = it & 1;
        if (it < 63) {
            CP16(sptr(&Kb[cur ^ 1][krow][kc8]),
                 B + (size_t)((it + 1) * 64 + krow) * CM + kc8);
            CP16(sptr(&Vh[cur ^ 1][vd][vc8]),
                 VTf + (size_t)vd * LQ + (it + 1) * 64 + vc8);
            asm volatile("cp.async.commit_group;");
        }
        // T = (SC*log2e)*S  (rows wm*16.., cols wn*32 + j*8)
        float4 sacc[4] = {};
#pragma unroll
        for (int ks = 0; ks < 2; ks++) {
            const int kb = ks * 16;
#pragma unroll
            for (int j = 0; j < 4; j++) {
                uint32_t b0 = *(const uint32_t*)&Kb[cur][wn * 32 + j * 8 + g][kb + 2 * q];
                uint32_t b1 = *(const uint32_t*)&Kb[cur][wn * 32 + j * 8 + g][kb + 2 * q + 8];
                mma_f16(sacc[j], aq[ks][0], aq[ks][1], aq[ks][2], aq[ks][3], b0, b1);
            }
        }
        // E = 2^T in fp16 (MUFU), outputs are AV A-frags directly
        __half2 hsg = __float2half2_rn(0.f), hsg8 = __float2half2_rn(0.f);
#pragma unroll
        for (int c = 0; c < 2; c++) {
            const float4 sa = sacc[2 * c], sb = sacc[2 * c + 1];
            __half2 E0 = h2exp2(__floats2half2_rn(sa.x, sa.y));  // (g,   k 2q,2q+1)
            __half2 E1 = h2exp2(__floats2half2_rn(sa.z, sa.w));  // (g+8, k 2q,2q+1)
            __half2 E2 = h2exp2(__floats2half2_rn(sb.x, sb.y));  // (g,   k 2q+8,9)
            __half2 E3 = h2exp2(__floats2half2_rn(sb.z, sb.w));  // (g+8, k 2q+8,9)
            hsg = __hadd2(hsg, __hadd2(E0, E2));
            hsg8 = __hadd2(hsg8, __hadd2(E1, E3));
            const int kh = (wn * 16 + c * 8 + q) * 2;
#pragma unroll
            for (int jj = 0; jj < 4; jj++) {
                uint32_t b0 = *(const uint32_t*)&Vh[cur][jj * 8 + g][kh];
                uint32_t b1 = *(const uint32_t*)&Vh[cur][jj * 8 + g][kh + 8];
                mma_f16(macc[jj], h2u(E0), h2u(E1), h2u(E2), h2u(E3), b0, b1);
            }
        }
        float2 f0 = __half22float2(hsg);
        float2 f1 = __half22float2(hsg8);
        rs0 += f0.x + f0.y;
        rs1 += f1.x + f1.y;
        asm volatile("cp.async.wait_group 0;" ::: "memory");
        __syncthreads();
    }
    // row sums: reduce over q, publish per wn half
    rs0 += __shfl_xor_sync(0xffffffffu, rs0, 1);
    rs0 += __shfl_xor_sync(0xffffffffu, rs0, 2);
    rs1 += __shfl_xor_sync(0xffffffffu, rs1, 1);
    rs1 += __shfl_xor_sync(0xffffffffu, rs1, 2);
    if (q == 0) {
        sRS[wn][wm * 16 + g] = rs0;
        sRS[wn][wm * 16 + g + 8] = rs1;
    }
    // wn=0 parks its AV partials
    if (wn == 0) {
#pragma unroll
        for (int jj = 0; jj < 4; jj++) {
            *(float2*)&redM[wm][g][jj * 8 + 2 * q] = make_float2(macc[jj].x, macc[jj].y);
            *(float2*)&redM[wm][g + 8][jj * 8 + 2 * q] = make_float2(macc[jj].z, macc[jj].w);
        }
    }
    __syncthreads();
    // wn=1 combines, normalizes, writes
    if (wn == 1) {
        const int r0 = wm * 16 + g, r1 = r0 + 8;
        const float i0 = __frcp_rn(sRS[0][r0] + sRS[1][r0]);
        const float i1 = __frcp_rn(sRS[0][r1] + sRS[1][r1]);
#pragma unroll
        for (int jj = 0; jj < 4; jj++) {
            float2 p0 = *(float2*)&redM[wm][g][jj * 8 + 2 * q];
            float2 p1 = *(float2*)&redM[wm][g + 8][jj * 8 + 2 * q];
            const int c = f * HD + jj * 8 + 2 * q;
            *(float2*)&OUT[(size_t)(l0 + r0) * CC + c] =
                make_float2((macc[jj].x + p0.x) * i0, (macc[jj].y + p0.y) * i0);
            *(float2*)&OUT[(size_t)(l0 + r1) * CC + c] =
                make_float2((macc[jj].z + p1.x) * i1, (macc[jj].w + p1.y) * i1);
        }
    }
}

// ---------------------------------------------------------------------------
// conv weight repack OIHW -> [k9][o][i], fp16
// ---------------------------------------------------------------------------
__global__ void repack_kernel(const float* __restrict__ w) {
    int i = blockIdx.x * 256 + threadIdx.x;
    int o = i / (CM * 9);
    int rem = i % (CM * 9);
    int ci = rem / 9;
    int k9 = rem % 9;
    g_WRh[(size_t)k9 * CC * CM + (size_t)o * CM + ci] = __float2half(w[i]);
}

// ---------------------------------------------------------------------------
// 3x3 SAME conv on padded fp16 input [66][66][CM] -> [64,64,CC], fp16 mma.
// grid (CC/64, 64)
// ---------------------------------------------------------------------------
__global__ void conv3p(const __half* __restrict__ Gp,
                       const float* __restrict__ bias,
                       float* __restrict__ Out) {
    __shared__ __align__(16) __half As[66][72];
    __shared__ __align__(16) __half Bs[3][64][72];
    const int py = blockIdx.y;
    const int n0 = blockIdx.x * 64;
    const int t = threadIdx.x;
    const int warp = t >> 5, lane = t & 31;
    const int wm = warp >> 1, wn = warp & 1;
    const int g = lane >> 2, q = lane & 3;

    float4 acc[4] = {};
    for (int ky = 0; ky < 3; ky++) {
        const __half* arow = Gp + (size_t)(py + ky) * GPW * CM;
        const __half* wky = g_WRh + (size_t)(ky * 3) * CC * CM;
        for (int kc = 0; kc < 8; kc++) {
            const int k0 = kc * 64;
#pragma unroll
            for (int i = 0; i < 3; i++) {
                int idx = t + i * 256;
                if (idx < 528) {
                    int row = idx >> 3, c8 = (idx & 7) * 8;
                    *(uint4*)&As[row][c8] =
                        *(const uint4*)(arow + (size_t)row * CM + k0 + c8);
                }
            }
#pragma unroll
            for (int i = 0; i < 6; i++) {
                int idx = t + i * 256;
                int kx = idx >> 9, w = idx & 511;
                int row = w >> 3, c8 = (w & 7) * 8;
                *(uint4*)&Bs[kx][row][c8] =
                    *(const uint4*)(wky + (size_t)kx * CC * CM +
                                    (size_t)(n0 + row) * CM + k0 + c8);
            }
            __syncthreads();
#pragma unroll
            for (int kx = 0; kx < 3; kx++) {
#pragma unroll
                for (int c = 0; c < 4; c++) {
                    const int kh = (c * 8 + q) * 2;
                    uint32_t a0 = *(const uint32_t*)&As[wm * 16 + g + kx][kh];
                    uint32_t a1 = *(const uint32_t*)&As[wm * 16 + g + 8 + kx][kh];
                    uint32_t a2 = *(const uint32_t*)&As[wm * 16 + g + kx][kh + 8];
                    uint32_t a3 = *(const uint32_t*)&As[wm * 16 + g + 8 + kx][kh + 8];
#pragma unroll
                    for (int j = 0; j < 4; j++) {
                        uint32_t b0 = *(const uint32_t*)&Bs[kx][wn * 32 + j * 8 + g][kh];
                        uint32_t b1 = *(const uint32_t*)&Bs[kx][wn * 32 + j * 8 + g][kh + 8];
                        mma_f16(acc[j], a0, a1, a2, a3, b0, b1);
                    }
                }
            }
            __syncthreads();
        }
    }
    const int p0 = wm * 16 + g, p1 = p0 + 8;
#pragma unroll
    for (int j = 0; j < 4; j++) {
        const int c = n0 + wn * 32 + j * 8 + q * 2;
        float bx = bias[c], by = bias[c + 1];
        *(float2*)&Out[((size_t)py * 64 + p0) * CC + c] =
            make_float2(acc[j].x + bx, acc[j].y + by);
        *(float2*)&Out[((size_t)py * 64 + p1) * CC + c] =
            make_float2(acc[j].z + bx, acc[j].w + by);
    }
}

// ---------------------------------------------------------------------------
// LayerNorm (256 threads = CC, one row per block)
// ---------------------------------------------------------------------------
__device__ __forceinline__ float block_sum_256(float v, volatile float* red) {
#pragma unroll
    for (int o = 16; o > 0; o >>= 1) v += __shfl_xor_sync(0xffffffffu, v, o);
    if ((threadIdx.x & 31) == 0) red[threadIdx.x >> 5] = v;
    __syncthreads();
    float s = red[0] + red[1] + red[2] + red[3] + red[4] + red[5] + red[6] + red[7];
    __syncthreads();
    return s;
}

__global__ void ln_concat_kernel(const float* __restrict__ Min,
                                 const float* __restrict__ Xin,
                                 const float* __restrict__ g,
                                 const float* __restrict__ b,
                                 float* __restrict__ Y) {
    __shared__ float red[8];
    const int r = blockIdx.x;
    const int t = threadIdx.x;
    float v = Min[(size_t)r * CC + t];
    float mean = block_sum_256(v, red) * (1.0f / CC);
    float d = v - mean;
    float var = block_sum_256(d * d, red) * (1.0f / CC);
    float o = d * rsqrtf(var + 1e-5f) * g[t] + b[t];
    Y[(size_t)r * CM + 256 + t] = o;
    Y[(size_t)r * CM + t] = Xin[(size_t)r * CC + t];
}

__global__ void ln_res_kernel(const float* __restrict__ Cin,
                              const float* __restrict__ Xin,
                              const float* __restrict__ g,
                              const float* __restrict__ b,
                              float* __restrict__ Out) {
    __shared__ float red[8];
    const int r = blockIdx.x;
    const int t = threadIdx.x;
    float v = Cin[(size_t)r * CC + t];
    float mean = block_sum_256(v, red) * (1.0f / CC);
    float d = v - mean;
    float var = block_sum_256(d * d, red) * (1.0f / CC);
    float o = d * rsqrtf(var + 1e-5f) * g[t] + b[t];
    Out[(size_t)r * CC + t] = o + Xin[(size_t)r * CC + t];
}

// ---------------------------------------------------------------------------
// Launch
// ---------------------------------------------------------------------------
extern "C" void kernel_launch(void* const* d_in, const int* in_sizes, int n_in,
                              void* d_out, int out_size) {
    const float* x0 = (const float*)d_in[0];
    const float* x1 = (const float*)d_in[1];
    const float* proj_w = (const float*)d_in[6];
    const float* proj_b = (const float*)d_in[7];
    const float* merge_w = (const float*)d_in[8];
    const float* merge_b = (const float*)d_in[9];
    const float* n0g = (const float*)d_in[10];
    const float* n0b = (const float*)d_in[11];
    const float* lin_w = (const float*)d_in[12];
    const float* lin_b = (const float*)d_in[13];
    const float* conv_w = (const float*)d_in[14];
    const float* conv_b = (const float*)d_in[15];
    const float* n1g = (const float*)d_in[16];
    const float* n1b = (const float*)d_in[17];
    float* out = (float*)d_out;

    void *P0, *P1, *VT0p, *VT1p, *M0p, *M1p, *MM0p, *MM1p, *Y0p, *Y1p,
         *GP0p, *GP1p, *CV0p, *CV1p;
    cudaGetSymbolAddress(&P0, g_P0h);
    cudaGetSymbolAddress(&P1, g_P1h);
    cudaGetSymbolAddress(&VT0p, g_VT0);
    cudaGetSymbolAddress(&VT1p, g_VT1);
    cudaGetSymbolAddress(&M0p, g_M0);
    cudaGetSymbolAddress(&M1p, g_M1);
    cudaGetSymbolAddress(&MM0p, g_MM0);
    cudaGetSymbolAddress(&MM1p, g_MM1);
    cudaGetSymbolAddress(&Y0p, g_Y0);
    cudaGetSymbolAddress(&Y1p, g_Y1);
    cudaGetSymbolAddress(&GP0p, g_GP0);
    cudaGetSymbolAddress(&GP1p, g_GP1);
    cudaGetSymbolAddress(&CV0p, g_CV0);
    cudaGetSymbolAddress(&CV1p, g_CV1);

    // zero padded conv buffers (borders)
    cudaMemsetAsync(GP0p, 0, (size_t)GPW * GPW * CM * 2);
    cudaMemsetAsync(GP1p, 0, (size_t)GPW * GPW * CM * 2);

    repack_kernel<<<(CC * CM * 9) / 256, 256>>>(conv_w);

    // proj -> fp16 P
    gemm_f16k<0, 2><<<dim3(CM / 64, LQ / 64), 256>>>(x0, CC, proj_w, CC, P0, CM, CC, proj_b);
    gemm_f16k<0, 2><<<dim3(CM / 64, LQ / 64), 256>>>(x1, CC, proj_w, CC, P1, CM, CC, proj_b);

    // v halves -> fp16 transposed VT
    vt_pack<<<dim3(LQ / 64, NH), 256>>>((const __half*)P0, (__half*)VT0p);
    vt_pack<<<dim3(LQ / 64, NH), 256>>>((const __half*)P1, (__half*)VT1p);

    // dual one-sided flash attention in one launch (z = direction)
    attn_one<<<dim3(LQ / 64, NH, 2), 256>>>(
        (const __half*)P0, (const __half*)P1,
        (const __half*)VT0p, (const __half*)VT1p, (float*)M0p, (float*)M1p);

    // merge
    gemm_f16k<0, 0><<<dim3(CC / 64, LQ / 64), 256>>>((const float*)M0p, CC, merge_w, CC, MM0p, CC, CC, merge_b);
    gemm_f16k<0, 0><<<dim3(CC / 64, LQ / 64), 256>>>((const float*)M1p, CC, merge_w, CC, MM1p, CC, CC, merge_b);

    // concat with LN
    ln_concat_kernel<<<LQ, 256>>>((const float*)MM0p, x0, n0g, n0b, (float*)Y0p);
    ln_concat_kernel<<<LQ, 256>>>((const float*)MM1p, x1, n0g, n0b, (float*)Y1p);

    // lin + gelu -> padded fp16
    gemm_f16k<1, 1><<<dim3(CM / 64, LQ / 64), 256>>>((const float*)Y0p, CM, lin_w, CM, GP0p, CM, CM, lin_b);
    gemm_f16k<1, 1><<<dim3(CM / 64, LQ / 64), 256>>>((const float*)Y1p, CM, lin_w, CM, GP1p, CM, CM, lin_b);

    // conv (fp16)
    conv3p<<<dim3(CC / 64, 64), 256>>>((const __half*)GP0p, conv_b, (float*)CV0p);
    conv3p<<<dim3(CC / 64, 64), 256>>>((const __half*)GP1p, conv_b, (float*)CV1p);

    // LN + residual
    ln_res_kernel<<<LQ, 256>>>((const float*)CV0p, x0, n1g, n1b, out);
    ln_res_kernel<<<LQ, 256>>>((const float*)CV1p, x1, n1g, n1b, out + (size_t)LQ * CC);
}

// round 12
// speedup vs baseline: 12.3097x; 1.0920x over previous
#include <cuda_runtime.h>
#include <cuda_fp16.h>
#include <math.h>
#include <stdint.h>

#define LQ 4096
#define CC 256
#define NH 8
#define HD 32
#define CM 512
#define GPW 66   // padded conv width

// ---------------------------------------------------------------------------
// Scratch
// ---------------------------------------------------------------------------
static __device__ __align__(16) __half g_P0h[LQ * CM];       // proj(x0), fp16
static __device__ __align__(16) __half g_P1h[LQ * CM];       // proj(x1), fp16
static __device__ __align__(16) __half g_VT0[NH * HD * LQ];  // v0 transposed [f*HD+d][s]
static __device__ __align__(16) __half g_VT1[NH * HD * LQ];  // v1 transposed
static __device__ float    g_M0[LQ * CC];
static __device__ float    g_M1[LQ * CC];
static __device__ float    g_MM0[LQ * CC];
static __device__ float    g_MM1[LQ * CC];
static __device__ float    g_Y0[LQ * CM];
static __device__ float    g_Y1[LQ * CM];
static __device__ __align__(16) __half g_GP0[GPW * GPW * CM];  // padded gelu(lin), fp16
static __device__ __align__(16) __half g_GP1[GPW * GPW * CM];
static __device__ float    g_CV0[LQ * CC];
static __device__ float    g_CV1[LQ * CC];
static __device__ __align__(16) __half g_WRh[9 * CC * CM];     // conv weights [k9][o][i], fp16

// ---------------------------------------------------------------------------
// helpers
// ---------------------------------------------------------------------------
__device__ __forceinline__ void mma_f16(float4& d, uint32_t a0, uint32_t a1,
                                        uint32_t a2, uint32_t a3,
                                        uint32_t b0, uint32_t b1) {
    asm volatile(
        "mma.sync.aligned.m16n8k16.row.col.f32.f16.f16.f32 "
        "{%0,%1,%2,%3}, {%4,%5,%6,%7}, {%8,%9}, {%0,%1,%2,%3};"
        : "+f"(d.x), "+f"(d.y), "+f"(d.z), "+f"(d.w)
        : "r"(a0), "r"(a1), "r"(a2), "r"(a3), "r"(b0), "r"(b1));
}

__device__ __forceinline__ uint32_t h2u(__half2 h) {
    return *reinterpret_cast<uint32_t*>(&h);
}

__device__ __forceinline__ uint32_t sptr(const void* p) {
    return (uint32_t)__cvta_generic_to_shared(p);
}
#define CP16(dst, src) \
    asm volatile("cp.async.cg.shared.global [%0], [%1], 16;" :: "r"(dst), "l"(src))

// ---------------------------------------------------------------------------
// fp16 GEMM: C = A @ B^T + bias, fp32 accumulate; blockIdx.z picks (A,C) pair.
// MODE: 0 = fp32 C, 1 = fp16 C into padded conv layout (with GELU),
// 2 = fp16 C plain. Block 64x64, 256 thr, BK=32 (two k16 steps per phase).
// ---------------------------------------------------------------------------
template <int GELU, int MODE>
__global__ void gemm_f16k(const float* __restrict__ A1, const float* __restrict__ A2,
                          int lda,
                          const float* __restrict__ B, int ldb,
                          void* __restrict__ Cv1, void* __restrict__ Cv2, int ldc,
                          int K, const float* __restrict__ bias) {
    __shared__ __align__(16) __half As[64][72];
    __shared__ __align__(16) __half Bs[64][72];
    const float* A = blockIdx.z ? A2 : A1;
    void* Cv = blockIdx.z ? Cv2 : Cv1;
    const int m0 = blockIdx.y * 64;
    const int n0 = blockIdx.x * 64;
    const int t = threadIdx.x;
    const int warp = t >> 5, lane = t & 31;
    const int wm = warp >> 1, wn = warp & 1;
    const int g = lane >> 2, q = lane & 3;
    const int lr = t >> 2, c8 = (t & 3) * 8;

    float4 acc[4] = {};
    for (int k0 = 0; k0 < K; k0 += 32) {
        float4 av0 = *(const float4*)(A + (size_t)(m0 + lr) * lda + k0 + c8);
        float4 av1 = *(const float4*)(A + (size_t)(m0 + lr) * lda + k0 + c8 + 4);
        float4 bv0 = *(const float4*)(B + (size_t)(n0 + lr) * ldb + k0 + c8);
        float4 bv1 = *(const float4*)(B + (size_t)(n0 + lr) * ldb + k0 + c8 + 4);
        uint4 au = {h2u(__floats2half2_rn(av0.x, av0.y)), h2u(__floats2half2_rn(av0.z, av0.w)),
                    h2u(__floats2half2_rn(av1.x, av1.y)), h2u(__floats2half2_rn(av1.z, av1.w))};
        uint4 bu = {h2u(__floats2half2_rn(bv0.x, bv0.y)), h2u(__floats2half2_rn(bv0.z, bv0.w)),
                    h2u(__floats2half2_rn(bv1.x, bv1.y)), h2u(__floats2half2_rn(bv1.z, bv1.w))};
        *(uint4*)&As[lr][c8] = au;
        *(uint4*)&Bs[lr][c8] = bu;
        __syncthreads();
#pragma unroll
        for (int ks = 0; ks < 2; ks++) {
            const int kb = ks * 16;
            uint32_t a0 = *(const uint32_t*)&As[wm * 16 + g][kb + 2 * q];
            uint32_t a1 = *(const uint32_t*)&As[wm * 16 + g + 8][kb + 2 * q];
            uint32_t a2 = *(const uint32_t*)&As[wm * 16 + g][kb + 2 * q + 8];
            uint32_t a3 = *(const uint32_t*)&As[wm * 16 + g + 8][kb + 2 * q + 8];
#pragma unroll
            for (int j = 0; j < 4; j++) {
                uint32_t b0 = *(const uint32_t*)&Bs[wn * 32 + j * 8 + g][kb + 2 * q];
                uint32_t b1 = *(const uint32_t*)&Bs[wn * 32 + j * 8 + g][kb + 2 * q + 8];
                mma_f16(acc[j], a0, a1, a2, a3, b0, b1);
            }
        }
        __syncthreads();
    }
    const int r0 = m0 + wm * 16 + g, r1 = r0 + 8;
#pragma unroll
    for (int j = 0; j < 4; j++) {
        const int c = n0 + wn * 32 + j * 8 + q * 2;
        float bx = bias ? bias[c] : 0.f, by = bias ? bias[c + 1] : 0.f;
        float v00 = acc[j].x + bx, v01 = acc[j].y + by;
        float v10 = acc[j].z + bx, v11 = acc[j].w + by;
        if (GELU) {
            v00 = 0.5f * v00 * (1.0f + erff(v00 * 0.70710678118f));
            v01 = 0.5f * v01 * (1.0f + erff(v01 * 0.70710678118f));
            v10 = 0.5f * v10 * (1.0f + erff(v10 * 0.70710678118f));
            v11 = 0.5f * v11 * (1.0f + erff(v11 * 0.70710678118f));
        }
        if (MODE == 0) {
            float* C = (float*)Cv;
            *(float2*)&C[(size_t)r0 * ldc + c] = make_float2(v00, v01);
            *(float2*)&C[(size_t)r1 * ldc + c] = make_float2(v10, v11);
        } else if (MODE == 1) {
            __half* C = (__half*)Cv;
            size_t o0 = ((size_t)((r0 >> 6) + 1) * GPW + (r0 & 63) + 1) * CM + c;
            size_t o1 = ((size_t)((r1 >> 6) + 1) * GPW + (r1 & 63) + 1) * CM + c;
            *(__half2*)&C[o0] = __floats2half2_rn(v00, v01);
            *(__half2*)&C[o1] = __floats2half2_rn(v10, v11);
        } else {
            __half* C = (__half*)Cv;
            *(__half2*)&C[(size_t)r0 * ldc + c] = __floats2half2_rn(v00, v01);
            *(__half2*)&C[(size_t)r1 * ldc + c] = __floats2half2_rn(v10, v11);
        }
    }
}

// ---------------------------------------------------------------------------
// VT pack: P's v-half (fp16) -> fp16 transposed VT[f*HD+d][s]; z picks pair.
// grid (LQ/64, NH, 2), 256 thr.
// ---------------------------------------------------------------------------
__global__ void vt_pack(const __half* __restrict__ Pa, const __half* __restrict__ Pb,
                        __half* __restrict__ VTa, __half* __restrict__ VTb) {
    __shared__ __half Sh[64][33];
    const __half* P = blockIdx.z ? Pb : Pa;
    __half* VT = blockIdx.z ? VTb : VTa;
    const int s0 = blockIdx.x * 64, f = blockIdx.y;
    const int t = threadIdx.x;
    {
        int r = t >> 2, dg = (t & 3) * 8;
        const __half* src = P + (size_t)(s0 + r) * CM + 256 + f * HD + dg;
        uint4 u = *(const uint4*)src;
        const __half* h = (const __half*)&u;
#pragma unroll
        for (int i = 0; i < 8; i++) Sh[r][dg + i] = h[i];
    }
    __syncthreads();
    {
        int d = t >> 3, sg = (t & 7) * 8;
        __half2 p0 = __halves2half2(Sh[sg + 0][d], Sh[sg + 1][d]);
        __half2 p1 = __halves2half2(Sh[sg + 2][d], Sh[sg + 3][d]);
        __half2 p2 = __halves2half2(Sh[sg + 4][d], Sh[sg + 5][d]);
        __half2 p3 = __halves2half2(Sh[sg + 6][d], Sh[sg + 7][d]);
        uint4 u = {h2u(p0), h2u(p1), h2u(p2), h2u(p3)};
        *(uint4*)(VT + (size_t)(f * HD + d) * LQ + s0 + sg) = u;
    }
}

// ---------------------------------------------------------------------------
// One-sided flash attention, all-fp16, E via MUFU ex2, 2 l-tiles per block.
// grid (LQ/128, NH, 2), 256 thr. K/V stream amortized over 128 q-rows.
// ---------------------------------------------------------------------------
__global__ __launch_bounds__(256, 2) void attn_one(
        const __half* __restrict__ P0, const __half* __restrict__ P1,
        const __half* __restrict__ VT0, const __half* __restrict__ VT1,
        float* __restrict__ M0, float* __restrict__ M1) {
    __shared__ __align__(16) __half Kb[2][64][56];   // [s][k halfs]
    __shared__ __align__(16) __half Vh[2][32][72];   // [d][k=s halfs]
    __shared__ float sRS[2][128];
    __shared__ __align__(8) float redM[4][16][34];
    const int f = blockIdx.y;
    const int l0 = blockIdx.x * 128;
    const int dir = blockIdx.z;
    const __half* A = (dir ? P1 : P0) + f * HD;
    const __half* B = (dir ? P0 : P1) + f * HD;
    const __half* VTf = (dir ? VT0 : VT1) + (size_t)f * HD * LQ;
    float* OUT = dir ? M1 : M0;
    const int t = threadIdx.x;
    const int warp = t >> 5, lane = t & 31;
    const int wm = warp >> 1, wn = warp & 1;
    const int g = lane >> 2, q = lane & 3;
    const int krow = t >> 2, kc8 = (t & 3) * 8;      // K/q tile loader
    const int vd = t >> 3, vc8 = (t & 7) * 8;        // V tile loader

    // prefetch s-tile 0 (async)
    CP16(sptr(&Kb[0][krow][kc8]), B + (size_t)krow * CM + kc8);
    CP16(sptr(&Vh[0][vd][vc8]), VTf + (size_t)vd * LQ + vc8);
    asm volatile("cp.async.commit_group;");
    // stage q through Kb[1], two halves; scale folded in (SC*log2e)
    const __half2 scl = __float2half2_rn(0.17677669529663687f * 1.4426950408889634f);
    uint32_t aq[2][2][4];
#pragma unroll
    for (int h = 0; h < 2; h++) {
        *(uint4*)&Kb[1][krow][kc8] =
            *(const uint4*)(A + (size_t)(l0 + h * 64 + krow) * CM + kc8);
        __syncthreads();
#pragma unroll
        for (int ks = 0; ks < 2; ks++) {
            const int kb = ks * 16;
            aq[h][ks][0] = h2u(__hmul2(*(const __half2*)&Kb[1][wm * 16 + g][kb + 2 * q], scl));
            aq[h][ks][1] = h2u(__hmul2(*(const __half2*)&Kb[1][wm * 16 + g + 8][kb + 2 * q], scl));
            aq[h][ks][2] = h2u(__hmul2(*(const __half2*)&Kb[1][wm * 16 + g][kb + 2 * q + 8], scl));
            aq[h][ks][3] = h2u(__hmul2(*(const __half2*)&Kb[1][wm * 16 + g + 8][kb + 2 * q + 8], scl));
        }
        __syncthreads();
    }
    asm volatile("cp.async.wait_group 0;" ::: "memory");
    __syncthreads();

    float4 macc[2][4] = {};
    float rs[2][2] = {};

    for (int it = 0; it < 64; it++) {
        const int cur = it & 1;
        if (it < 63) {
            CP16(sptr(&Kb[cur ^ 1][krow][kc8]),
                 B + (size_t)((it + 1) * 64 + krow) * CM + kc8);
            CP16(sptr(&Vh[cur ^ 1][vd][vc8]),
                 VTf + (size_t)vd * LQ + (it + 1) * 64 + vc8);
            asm volatile("cp.async.commit_group;");
        }
#pragma unroll
        for (int h = 0; h < 2; h++) {
            // T = (SC*log2e)*S
            float4 sacc[4] = {};
#pragma unroll
            for (int ks = 0; ks < 2; ks++) {
                const int kb = ks * 16;
#pragma unroll
                for (int j = 0; j < 4; j++) {
                    uint32_t b0 = *(const uint32_t*)&Kb[cur][wn * 32 + j * 8 + g][kb + 2 * q];
                    uint32_t b1 = *(const uint32_t*)&Kb[cur][wn * 32 + j * 8 + g][kb + 2 * q + 8];
                    mma_f16(sacc[j], aq[h][ks][0], aq[h][ks][1], aq[h][ks][2], aq[h][ks][3], b0, b1);
                }
            }
            // E = 2^T (MUFU fp16); E half2s are the AV A-frags
            __half2 hsg = __float2half2_rn(0.f), hsg8 = __float2half2_rn(0.f);
#pragma unroll
            for (int c = 0; c < 2; c++) {
                const float4 sa = sacc[2 * c], sb = sacc[2 * c + 1];
                __half2 E0 = h2exp2(__floats2half2_rn(sa.x, sa.y));
                __half2 E1 = h2exp2(__floats2half2_rn(sa.z, sa.w));
                __half2 E2 = h2exp2(__floats2half2_rn(sb.x, sb.y));
                __half2 E3 = h2exp2(__floats2half2_rn(sb.z, sb.w));
                hsg = __hadd2(hsg, __hadd2(E0, E2));
                hsg8 = __hadd2(hsg8, __hadd2(E1, E3));
                const int kh = (wn * 16 + c * 8 + q) * 2;
#pragma unroll
                for (int jj = 0; jj < 4; jj++) {
                    uint32_t b0 = *(const uint32_t*)&Vh[cur][jj * 8 + g][kh];
                    uint32_t b1 = *(const uint32_t*)&Vh[cur][jj * 8 + g][kh + 8];
                    mma_f16(macc[h][jj], h2u(E0), h2u(E1), h2u(E2), h2u(E3), b0, b1);
                }
            }
            float2 f0 = __half22float2(hsg);
            float2 f1 = __half22float2(hsg8);
            rs[h][0] += f0.x + f0.y;
            rs[h][1] += f1.x + f1.y;
        }
        asm volatile("cp.async.wait_group 0;" ::: "memory");
        __syncthreads();
    }
    // row sums: reduce over q, publish per wn half
#pragma unroll
    for (int h = 0; h < 2; h++) {
        float r0v = rs[h][0], r1v = rs[h][1];
        r0v += __shfl_xor_sync(0xffffffffu, r0v, 1);
        r0v += __shfl_xor_sync(0xffffffffu, r0v, 2);
        r1v += __shfl_xor_sync(0xffffffffu, r1v, 1);
        r1v += __shfl_xor_sync(0xffffffffu, r1v, 2);
        if (q == 0) {
            sRS[wn][h * 64 + wm * 16 + g] = r0v;
            sRS[wn][h * 64 + wm * 16 + g + 8] = r1v;
        }
    }
    // cross-wn AV reduction, one half at a time (redM reused)
#pragma unroll
    for (int h = 0; h < 2; h++) {
        if (wn == 0) {
#pragma unroll
            for (int jj = 0; jj < 4; jj++) {
                *(float2*)&redM[wm][g][jj * 8 + 2 * q] = make_float2(macc[h][jj].x, macc[h][jj].y);
                *(float2*)&redM[wm][g + 8][jj * 8 + 2 * q] = make_float2(macc[h][jj].z, macc[h][jj].w);
            }
        }
        __syncthreads();
        if (wn == 1) {
            const int r0 = h * 64 + wm * 16 + g, r1 = r0 + 8;
            const float i0 = __frcp_rn(sRS[0][r0] + sRS[1][r0]);
            const float i1 = __frcp_rn(sRS[0][r1] + sRS[1][r1]);
#pragma unroll
            for (int jj = 0; jj < 4; jj++) {
                float2 p0 = *(float2*)&redM[wm][g][jj * 8 + 2 * q];
                float2 p1 = *(float2*)&redM[wm][g + 8][jj * 8 + 2 * q];
                const int c = f * HD + jj * 8 + 2 * q;
                *(float2*)&OUT[(size_t)(l0 + r0) * CC + c] =
                    make_float2((macc[h][jj].x + p0.x) * i0, (macc[h][jj].y + p0.y) * i0);
                *(float2*)&OUT[(size_t)(l0 + r1) * CC + c] =
                    make_float2((macc[h][jj].z + p1.x) * i1, (macc[h][jj].w + p1.y) * i1);
            }
        }
        __syncthreads();
    }
}

// ---------------------------------------------------------------------------
// conv weight repack OIHW -> [k9][o][i], fp16
// ---------------------------------------------------------------------------
__global__ void repack_kernel(const float* __restrict__ w) {
    int i = blockIdx.x * 256 + threadIdx.x;
    int o = i / (CM * 9);
    int rem = i % (CM * 9);
    int ci = rem / 9;
    int k9 = rem % 9;
    g_WRh[(size_t)k9 * CC * CM + (size_t)o * CM + ci] = __float2half(w[i]);
}

// ---------------------------------------------------------------------------
// 3x3 SAME conv on padded fp16 input [66][66][CM] -> [64,64,CC]; z picks pair.
// grid (CC/64, 64, 2)
// ---------------------------------------------------------------------------
__global__ void conv3p(const __half* __restrict__ Gp1, const __half* __restrict__ Gp2,
                       const float* __restrict__ bias,
                       float* __restrict__ Out1, float* __restrict__ Out2) {
    __shared__ __align__(16) __half As[66][72];
    __shared__ __align__(16) __half Bs[3][64][72];
    const __half* Gp = blockIdx.z ? Gp2 : Gp1;
    float* Out = blockIdx.z ? Out2 : Out1;
    const int py = blockIdx.y;
    const int n0 = blockIdx.x * 64;
    const int t = threadIdx.x;
    const int warp = t >> 5, lane = t & 31;
    const int wm = warp >> 1, wn = warp & 1;
    const int g = lane >> 2, q = lane & 3;

    float4 acc[4] = {};
    for (int ky = 0; ky < 3; ky++) {
        const __half* arow = Gp + (size_t)(py + ky) * GPW * CM;
        const __half* wky = g_WRh + (size_t)(ky * 3) * CC * CM;
        for (int kc = 0; kc < 8; kc++) {
            const int k0 = kc * 64;
#pragma unroll
            for (int i = 0; i < 3; i++) {
                int idx = t + i * 256;
                if (idx < 528) {
                    int row = idx >> 3, c8 = (idx & 7) * 8;
                    *(uint4*)&As[row][c8] =
                        *(const uint4*)(arow + (size_t)row * CM + k0 + c8);
                }
            }
#pragma unroll
            for (int i = 0; i < 6; i++) {
                int idx = t + i * 256;
                int kx = idx >> 9, w = idx & 511;
                int row = w >> 3, c8 = (w & 7) * 8;
                *(uint4*)&Bs[kx][row][c8] =
                    *(const uint4*)(wky + (size_t)kx * CC * CM +
                                    (size_t)(n0 + row) * CM + k0 + c8);
            }
            __syncthreads();
#pragma unroll
            for (int kx = 0; kx < 3; kx++) {
#pragma unroll
                for (int c = 0; c < 4; c++) {
                    const int kh = (c * 8 + q) * 2;
                    uint32_t a0 = *(const uint32_t*)&As[wm * 16 + g + kx][kh];
                    uint32_t a1 = *(const uint32_t*)&As[wm * 16 + g + 8 + kx][kh];
                    uint32_t a2 = *(const uint32_t*)&As[wm * 16 + g + kx][kh + 8];
                    uint32_t a3 = *(const uint32_t*)&As[wm * 16 + g + 8 + kx][kh + 8];
#pragma unroll
                    for (int j = 0; j < 4; j++) {
                        uint32_t b0 = *(const uint32_t*)&Bs[kx][wn * 32 + j * 8 + g][kh];
                        uint32_t b1 = *(const uint32_t*)&Bs[kx][wn * 32 + j * 8 + g][kh + 8];
                        mma_f16(acc[j], a0, a1, a2, a3, b0, b1);
                    }
                }
            }
            __syncthreads();
        }
    }
    const int p0 = wm * 16 + g, p1 = p0 + 8;
#pragma unroll
    for (int j = 0; j < 4; j++) {
        const int c = n0 + wn * 32 + j * 8 + q * 2;
        float bx = bias[c], by = bias[c + 1];
        *(float2*)&Out[((size_t)py * 64 + p0) * CC + c] =
            make_float2(acc[j].x + bx, acc[j].y + by);
        *(float2*)&Out[((size_t)py * 64 + p1) * CC + c] =
            make_float2(acc[j].z + bx, acc[j].w + by);
    }
}

// ---------------------------------------------------------------------------
// LayerNorm (256 threads = CC, one row per block; blockIdx.y picks pair)
// ---------------------------------------------------------------------------
__device__ __forceinline__ float block_sum_256(float v, volatile float* red) {
#pragma unroll
    for (int o = 16; o > 0; o >>= 1) v += __shfl_xor_sync(0xffffffffu, v, o);
    if ((threadIdx.x & 31) == 0) red[threadIdx.x >> 5] = v;
    __syncthreads();
    float s = red[0] + red[1] + red[2] + red[3] + red[4] + red[5] + red[6] + red[7];
    __syncthreads();
    return s;
}

__global__ void ln_concat_kernel(const float* __restrict__ Min1, const float* __restrict__ Min2,
                                 const float* __restrict__ Xin1, const float* __restrict__ Xin2,
                                 const float* __restrict__ g,
                                 const float* __restrict__ b,
                                 float* __restrict__ Y1, float* __restrict__ Y2) {
    __shared__ float red[8];
    const float* Min = blockIdx.y ? Min2 : Min1;
    const float* Xin = blockIdx.y ? Xin2 : Xin1;
    float* Y = blockIdx.y ? Y2 : Y1;
    const int r = blockIdx.x;
    const int t = threadIdx.x;
    float v = Min[(size_t)r * CC + t];
    float mean = block_sum_256(v, red) * (1.0f / CC);
    float d = v - mean;
    float var = block_sum_256(d * d, red) * (1.0f / CC);
    float o = d * rsqrtf(var + 1e-5f) * g[t] + b[t];
    Y[(size_t)r * CM + 256 + t] = o;
    Y[(size_t)r * CM + t] = Xin[(size_t)r * CC + t];
}

__global__ void ln_res_kernel(const float* __restrict__ Cin1, const float* __restrict__ Cin2,
                              const float* __restrict__ Xin1, const float* __restrict__ Xin2,
                              const float* __restrict__ g,
                              const float* __restrict__ b,
                              float* __restrict__ Out1, float* __restrict__ Out2) {
    __shared__ float red[8];
    const float* Cin = blockIdx.y ? Cin2 : Cin1;
    const float* Xin = blockIdx.y ? Xin2 : Xin1;
    float* Out = blockIdx.y ? Out2 : Out1;
    const int r = blockIdx.x;
    const int t = threadIdx.x;
    float v = Cin[(size_t)r * CC + t];
    float mean = block_sum_256(v, red) * (1.0f / CC);
    float d = v - mean;
    float var = block_sum_256(d * d, red) * (1.0f / CC);
    float o = d * rsqrtf(var + 1e-5f) * g[t] + b[t];
    Out[(size_t)r * CC + t] = o + Xin[(size_t)r * CC + t];
}

// ---------------------------------------------------------------------------
// Launch
// ---------------------------------------------------------------------------
extern "C" void kernel_launch(void* const* d_in, const int* in_sizes, int n_in,
                              void* d_out, int out_size) {
    const float* x0 = (const float*)d_in[0];
    const float* x1 = (const float*)d_in[1];
    const float* proj_w = (const float*)d_in[6];
    const float* proj_b = (const float*)d_in[7];
    const float* merge_w = (const float*)d_in[8];
    const float* merge_b = (const float*)d_in[9];
    const float* n0g = (const float*)d_in[10];
    const float* n0b = (const float*)d_in[11];
    const float* lin_w = (const float*)d_in[12];
    const float* lin_b = (const float*)d_in[13];
    const float* conv_w = (const float*)d_in[14];
    const float* conv_b = (const float*)d_in[15];
    const float* n1g = (const float*)d_in[16];
    const float* n1b = (const float*)d_in[17];
    float* out = (float*)d_out;

    void *P0, *P1, *VT0p, *VT1p, *M0p, *M1p, *MM0p, *MM1p, *Y0p, *Y1p,
         *GP0p, *GP1p, *CV0p, *CV1p;
    cudaGetSymbolAddress(&P0, g_P0h);
    cudaGetSymbolAddress(&P1, g_P1h);
    cudaGetSymbolAddress(&VT0p, g_VT0);
    cudaGetSymbolAddress(&VT1p, g_VT1);
    cudaGetSymbolAddress(&M0p, g_M0);
    cudaGetSymbolAddress(&M1p, g_M1);
    cudaGetSymbolAddress(&MM0p, g_MM0);
    cudaGetSymbolAddress(&MM1p, g_MM1);
    cudaGetSymbolAddress(&Y0p, g_Y0);
    cudaGetSymbolAddress(&Y1p, g_Y1);
    cudaGetSymbolAddress(&GP0p, g_GP0);
    cudaGetSymbolAddress(&GP1p, g_GP1);
    cudaGetSymbolAddress(&CV0p, g_CV0);
    cudaGetSymbolAddress(&CV1p, g_CV1);

    // zero padded conv buffers (borders)
    cudaMemsetAsync(GP0p, 0, (size_t)GPW * GPW * CM * 2);
    cudaMemsetAsync(GP1p, 0, (size_t)GPW * GPW * CM * 2);

    repack_kernel<<<(CC * CM * 9) / 256, 256>>>(conv_w);

    // proj -> fp16 P (both tensors, z)
    gemm_f16k<0, 2><<<dim3(CM / 64, LQ / 64, 2), 256>>>(
        x0, x1, CC, proj_w, CC, P0, P1, CM, CC, proj_b);

    // v halves -> fp16 transposed VT (both, z)
    vt_pack<<<dim3(LQ / 64, NH, 2), 256>>>(
        (const __half*)P0, (const __half*)P1, (__half*)VT0p, (__half*)VT1p);

    // dual one-sided flash attention, 2 l-tiles/block
    attn_one<<<dim3(LQ / 128, NH, 2), 256>>>(
        (const __half*)P0, (const __half*)P1,
        (const __half*)VT0p, (const __half*)VT1p, (float*)M0p, (float*)M1p);

    // merge (both, z)
    gemm_f16k<0, 0><<<dim3(CC / 64, LQ / 64, 2), 256>>>(
        (const float*)M0p, (const float*)M1p, CC, merge_w, CC, MM0p, MM1p, CC, CC, merge_b);

    // concat with LN (both, y)
    ln_concat_kernel<<<dim3(LQ, 2), 256>>>(
        (const float*)MM0p, (const float*)MM1p, x0, x1, n0g, n0b, (float*)Y0p, (float*)Y1p);

    // lin + gelu -> padded fp16 (both, z)
    gemm_f16k<1, 1><<<dim3(CM / 64, LQ / 64, 2), 256>>>(
        (const float*)Y0p, (const float*)Y1p, CM, lin_w, CM, GP0p, GP1p, CM, CM, lin_b);

    // conv (both, z)
    conv3p<<<dim3(CC / 64, 64, 2), 256>>>(
        (const __half*)GP0p, (const __half*)GP1p, conv_b, (float*)CV0p, (float*)CV1p);

    // LN + residual (both, y)
    ln_res_kernel<<<dim3(LQ, 2), 256>>>(
        (const float*)CV0p, (const float*)CV1p, x0, x1, n1g, n1b,
        out, out + (size_t)LQ * CC);
}

// round 13
// speedup vs baseline: 13.8270x; 1.1233x over previous
#include <cuda_runtime.h>
#include <cuda_fp16.h>
#include <math.h>
#include <stdint.h>

#define LQ 4096
#define CC 256
#define NH 8
#define HD 32
#define CM 512
#define GPW 66   // padded conv width

// ---------------------------------------------------------------------------
// Scratch
// ---------------------------------------------------------------------------
static __device__ __align__(16) __half g_X0h[LQ * CC];       // x0 fp16
static __device__ __align__(16) __half g_X1h[LQ * CC];       // x1 fp16
static __device__ __align__(16) __half g_PWh[CM * CC];       // proj_w fp16
static __device__ __align__(16) __half g_MWh[CC * CC];       // merge_w fp16
static __device__ __align__(16) __half g_LWh[CM * CM];       // lin_w fp16
static __device__ __align__(16) __half g_P0h[LQ * CM];       // proj(x0), fp16
static __device__ __align__(16) __half g_P1h[LQ * CM];       // proj(x1), fp16
static __device__ __align__(16) __half g_VT0[NH * HD * LQ];  // v0 transposed [f*HD+d][s]
static __device__ __align__(16) __half g_VT1[NH * HD * LQ];  // v1 transposed
static __device__ __align__(16) __half g_M0h[LQ * CC];       // attn out fp16
static __device__ __align__(16) __half g_M1h[LQ * CC];
static __device__ float    g_MM0[LQ * CC];
static __device__ float    g_MM1[LQ * CC];
static __device__ __align__(16) __half g_Y0h[LQ * CM];       // concat fp16
static __device__ __align__(16) __half g_Y1h[LQ * CM];
static __device__ __align__(16) __half g_GP0[GPW * GPW * CM];  // padded gelu(lin), fp16
static __device__ __align__(16) __half g_GP1[GPW * GPW * CM];
static __device__ float    g_CV0[LQ * CC];
static __device__ float    g_CV1[LQ * CC];
static __device__ __align__(16) __half g_WRh[9 * CC * CM];     // conv weights [k9][o][i], fp16

// ---------------------------------------------------------------------------
// helpers
// ---------------------------------------------------------------------------
__device__ __forceinline__ void mma_f16(float4& d, uint32_t a0, uint32_t a1,
                                        uint32_t a2, uint32_t a3,
                                        uint32_t b0, uint32_t b1) {
    asm volatile(
        "mma.sync.aligned.m16n8k16.row.col.f32.f16.f16.f32 "
        "{%0,%1,%2,%3}, {%4,%5,%6,%7}, {%8,%9}, {%0,%1,%2,%3};"
        : "+f"(d.x), "+f"(d.y), "+f"(d.z), "+f"(d.w)
        : "r"(a0), "r"(a1), "r"(a2), "r"(a3), "r"(b0), "r"(b1));
}

__device__ __forceinline__ uint32_t h2u(__half2 h) {
    return *reinterpret_cast<uint32_t*>(&h);
}

__device__ __forceinline__ uint32_t sptr(const void* p) {
    return (uint32_t)__cvta_generic_to_shared(p);
}
#define CP16(dst, src) \
    asm volatile("cp.async.cg.shared.global [%0], [%1], 16;" :: "r"(dst), "l"(src))

// ---------------------------------------------------------------------------
// One-shot fp16 packing of weights + inputs (grid-stride free layout)
// ---------------------------------------------------------------------------
__global__ void pack_misc(const float* __restrict__ pw, const float* __restrict__ mw,
                          const float* __restrict__ lw,
                          const float* __restrict__ x0, const float* __restrict__ x1) {
    size_t i = (size_t)blockIdx.x * 256 + threadIdx.x;
    if (i < CM * CC) { g_PWh[i] = __float2half(pw[i]); return; }
    i -= CM * CC;
    if (i < CC * CC) { g_MWh[i] = __float2half(mw[i]); return; }
    i -= CC * CC;
    if (i < CM * CM) { g_LWh[i] = __float2half(lw[i]); return; }
    i -= CM * CM;
    if (i < (size_t)LQ * CC) { g_X0h[i] = __float2half(x0[i]); return; }
    i -= (size_t)LQ * CC;
    g_X1h[i] = __float2half(x1[i]);
}
#define PACK_TOTAL (CM * CC + CC * CC + CM * CM + 2 * LQ * CC)

// conv weight repack OIHW -> [k9][o][i], fp16
__global__ void repack_kernel(const float* __restrict__ w) {
    int i = blockIdx.x * 256 + threadIdx.x;
    int o = i / (CM * 9);
    int rem = i % (CM * 9);
    int ci = rem / 9;
    int k9 = rem % 9;
    g_WRh[(size_t)k9 * CC * CM + (size_t)o * CM + ci] = __float2half(w[i]);
}

// ---------------------------------------------------------------------------
// All-fp16 GEMM: C = A @ B^T + bias, fp32 accumulate, cp.async double-buffer.
// blockIdx.z picks (A,C) pair. MODE: 0 = fp32 C, 1 = fp16 C padded conv
// (+GELU), 2 = fp16 C plain. Block 64x64, 256 thr, BK=32.
// ---------------------------------------------------------------------------
template <int GELU, int MODE>
__global__ void gemm_h(const __half* __restrict__ A1, const __half* __restrict__ A2,
                       int lda,
                       const __half* __restrict__ B, int ldb,
                       void* __restrict__ Cv1, void* __restrict__ Cv2, int ldc,
                       int K, const float* __restrict__ bias) {
    __shared__ __align__(16) __half As[2][64][72];
    __shared__ __align__(16) __half Bs[2][64][72];
    const __half* A = blockIdx.z ? A2 : A1;
    void* Cv = blockIdx.z ? Cv2 : Cv1;
    const int m0 = blockIdx.y * 64;
    const int n0 = blockIdx.x * 64;
    const int t = threadIdx.x;
    const int warp = t >> 5, lane = t & 31;
    const int wm = warp >> 1, wn = warp & 1;
    const int g = lane >> 2, q = lane & 3;
    const int lr = t >> 2, c8 = (t & 3) * 8;
    const int nphase = K >> 5;

    // prefetch phase 0
    CP16(sptr(&As[0][lr][c8]), A + (size_t)(m0 + lr) * lda + c8);
    CP16(sptr(&Bs[0][lr][c8]), B + (size_t)(n0 + lr) * ldb + c8);
    asm volatile("cp.async.commit_group;");
    asm volatile("cp.async.wait_group 0;" ::: "memory");
    __syncthreads();

    float4 acc[4] = {};
    for (int p = 0; p < nphase; p++) {
        const int cur = p & 1;
        if (p + 1 < nphase) {
            const int k0 = (p + 1) * 32;
            CP16(sptr(&As[cur ^ 1][lr][c8]), A + (size_t)(m0 + lr) * lda + k0 + c8);
            CP16(sptr(&Bs[cur ^ 1][lr][c8]), B + (size_t)(n0 + lr) * ldb + k0 + c8);
            asm volatile("cp.async.commit_group;");
        }
#pragma unroll
        for (int ks = 0; ks < 2; ks++) {
            const int kb = ks * 16;
            uint32_t a0 = *(const uint32_t*)&As[cur][wm * 16 + g][kb + 2 * q];
            uint32_t a1 = *(const uint32_t*)&As[cur][wm * 16 + g + 8][kb + 2 * q];
            uint32_t a2 = *(const uint32_t*)&As[cur][wm * 16 + g][kb + 2 * q + 8];
            uint32_t a3 = *(const uint32_t*)&As[cur][wm * 16 + g + 8][kb + 2 * q + 8];
#pragma unroll
            for (int j = 0; j < 4; j++) {
                uint32_t b0 = *(const uint32_t*)&Bs[cur][wn * 32 + j * 8 + g][kb + 2 * q];
                uint32_t b1 = *(const uint32_t*)&Bs[cur][wn * 32 + j * 8 + g][kb + 2 * q + 8];
                mma_f16(acc[j], a0, a1, a2, a3, b0, b1);
            }
        }
        asm volatile("cp.async.wait_group 0;" ::: "memory");
        __syncthreads();
    }
    const int r0 = m0 + wm * 16 + g, r1 = r0 + 8;
#pragma unroll
    for (int j = 0; j < 4; j++) {
        const int c = n0 + wn * 32 + j * 8 + q * 2;
        float bx = bias ? bias[c] : 0.f, by = bias ? bias[c + 1] : 0.f;
        float v00 = acc[j].x + bx, v01 = acc[j].y + by;
        float v10 = acc[j].z + bx, v11 = acc[j].w + by;
        if (GELU) {
            v00 = 0.5f * v00 * (1.0f + erff(v00 * 0.70710678118f));
            v01 = 0.5f * v01 * (1.0f + erff(v01 * 0.70710678118f));
            v10 = 0.5f * v10 * (1.0f + erff(v10 * 0.70710678118f));
            v11 = 0.5f * v11 * (1.0f + erff(v11 * 0.70710678118f));
        }
        if (MODE == 0) {
            float* C = (float*)Cv;
            *(float2*)&C[(size_t)r0 * ldc + c] = make_float2(v00, v01);
            *(float2*)&C[(size_t)r1 * ldc + c] = make_float2(v10, v11);
        } else if (MODE == 1) {
            __half* C = (__half*)Cv;
            size_t o0 = ((size_t)((r0 >> 6) + 1) * GPW + (r0 & 63) + 1) * CM + c;
            size_t o1 = ((size_t)((r1 >> 6) + 1) * GPW + (r1 & 63) + 1) * CM + c;
            *(__half2*)&C[o0] = __floats2half2_rn(v00, v01);
            *(__half2*)&C[o1] = __floats2half2_rn(v10, v11);
        } else {
            __half* C = (__half*)Cv;
            *(__half2*)&C[(size_t)r0 * ldc + c] = __floats2half2_rn(v00, v01);
            *(__half2*)&C[(size_t)r1 * ldc + c] = __floats2half2_rn(v10, v11);
        }
    }
}

// ---------------------------------------------------------------------------
// VT pack: P's v-half (fp16) -> fp16 transposed VT[f*HD+d][s]; z picks pair.
// ---------------------------------------------------------------------------
__global__ void vt_pack(const __half* __restrict__ Pa, const __half* __restrict__ Pb,
                        __half* __restrict__ VTa, __half* __restrict__ VTb) {
    __shared__ __half Sh[64][33];
    const __half* P = blockIdx.z ? Pb : Pa;
    __half* VT = blockIdx.z ? VTb : VTa;
    const int s0 = blockIdx.x * 64, f = blockIdx.y;
    const int t = threadIdx.x;
    {
        int r = t >> 2, dg = (t & 3) * 8;
        const __half* src = P + (size_t)(s0 + r) * CM + 256 + f * HD + dg;
        uint4 u = *(const uint4*)src;
        const __half* h = (const __half*)&u;
#pragma unroll
        for (int i = 0; i < 8; i++) Sh[r][dg + i] = h[i];
    }
    __syncthreads();
    {
        int d = t >> 3, sg = (t & 7) * 8;
        __half2 p0 = __halves2half2(Sh[sg + 0][d], Sh[sg + 1][d]);
        __half2 p1 = __halves2half2(Sh[sg + 2][d], Sh[sg + 3][d]);
        __half2 p2 = __halves2half2(Sh[sg + 4][d], Sh[sg + 5][d]);
        __half2 p3 = __halves2half2(Sh[sg + 6][d], Sh[sg + 7][d]);
        uint4 u = {h2u(p0), h2u(p1), h2u(p2), h2u(p3)};
        *(uint4*)(VT + (size_t)(f * HD + d) * LQ + s0 + sg) = u;
    }
}

// ---------------------------------------------------------------------------
// One-sided flash attention, fp16, MUFU ex2, 2 l-tiles/block, fp16 M out.
// grid (LQ/128, NH, 2), 256 thr.
// ---------------------------------------------------------------------------
__global__ __launch_bounds__(256, 2) void attn_one(
        const __half* __restrict__ P0, const __half* __restrict__ P1,
        const __half* __restrict__ VT0, const __half* __restrict__ VT1,
        __half* __restrict__ M0, __half* __restrict__ M1) {
    __shared__ __align__(16) __half Kb[2][64][56];
    __shared__ __align__(16) __half Vh[2][32][72];
    __shared__ float sRS[2][128];
    __shared__ __align__(8) float redM[4][16][34];
    const int f = blockIdx.y;
    const int l0 = blockIdx.x * 128;
    const int dir = blockIdx.z;
    const __half* A = (dir ? P1 : P0) + f * HD;
    const __half* B = (dir ? P0 : P1) + f * HD;
    const __half* VTf = (dir ? VT0 : VT1) + (size_t)f * HD * LQ;
    __half* OUT = dir ? M1 : M0;
    const int t = threadIdx.x;
    const int warp = t >> 5, lane = t & 31;
    const int wm = warp >> 1, wn = warp & 1;
    const int g = lane >> 2, q = lane & 3;
    const int krow = t >> 2, kc8 = (t & 3) * 8;
    const int vd = t >> 3, vc8 = (t & 7) * 8;

    CP16(sptr(&Kb[0][krow][kc8]), B + (size_t)krow * CM + kc8);
    CP16(sptr(&Vh[0][vd][vc8]), VTf + (size_t)vd * LQ + vc8);
    asm volatile("cp.async.commit_group;");
    const __half2 scl = __float2half2_rn(0.17677669529663687f * 1.4426950408889634f);
    uint32_t aq[2][2][4];
#pragma unroll
    for (int h = 0; h < 2; h++) {
        *(uint4*)&Kb[1][krow][kc8] =
            *(const uint4*)(A + (size_t)(l0 + h * 64 + krow) * CM + kc8);
        __syncthreads();
#pragma unroll
        for (int ks = 0; ks < 2; ks++) {
            const int kb = ks * 16;
            aq[h][ks][0] = h2u(__hmul2(*(const __half2*)&Kb[1][wm * 16 + g][kb + 2 * q], scl));
            aq[h][ks][1] = h2u(__hmul2(*(const __half2*)&Kb[1][wm * 16 + g + 8][kb + 2 * q], scl));
            aq[h][ks][2] = h2u(__hmul2(*(const __half2*)&Kb[1][wm * 16 + g][kb + 2 * q + 8], scl));
            aq[h][ks][3] = h2u(__hmul2(*(const __half2*)&Kb[1][wm * 16 + g + 8][kb + 2 * q + 8], scl));
        }
        __syncthreads();
    }
    asm volatile("cp.async.wait_group 0;" ::: "memory");
    __syncthreads();

    float4 macc[2][4] = {};
    float rs[2][2] = {};

    for (int it = 0; it < 64; it++) {
        const int cur = it & 1;
        if (it < 63) {
            CP16(sptr(&Kb[cur ^ 1][krow][kc8]),
                 B + (size_t)((it + 1) * 64 + krow) * CM + kc8);
            CP16(sptr(&Vh[cur ^ 1][vd][vc8]),
                 VTf + (size_t)vd * LQ + (it + 1) * 64 + vc8);
            asm volatile("cp.async.commit_group;");
        }
#pragma unroll
        for (int h = 0; h < 2; h++) {
            float4 sacc[4] = {};
#pragma unroll
            for (int ks = 0; ks < 2; ks++) {
                const int kb = ks * 16;
#pragma unroll
                for (int j = 0; j < 4; j++) {
                    uint32_t b0 = *(const uint32_t*)&Kb[cur][wn * 32 + j * 8 + g][kb + 2 * q];
                    uint32_t b1 = *(const uint32_t*)&Kb[cur][wn * 32 + j * 8 + g][kb + 2 * q + 8];
                    mma_f16(sacc[j], aq[h][ks][0], aq[h][ks][1], aq[h][ks][2], aq[h][ks][3], b0, b1);
                }
            }
            __half2 hsg = __float2half2_rn(0.f), hsg8 = __float2half2_rn(0.f);
#pragma unroll
            for (int c = 0; c < 2; c++) {
                const float4 sa = sacc[2 * c], sb = sacc[2 * c + 1];
                __half2 E0 = h2exp2(__floats2half2_rn(sa.x, sa.y));
                __half2 E1 = h2exp2(__floats2half2_rn(sa.z, sa.w));
                __half2 E2 = h2exp2(__floats2half2_rn(sb.x, sb.y));
                __half2 E3 = h2exp2(__floats2half2_rn(sb.z, sb.w));
                hsg = __hadd2(hsg, __hadd2(E0, E2));
                hsg8 = __hadd2(hsg8, __hadd2(E1, E3));
                const int kh = (wn * 16 + c * 8 + q) * 2;
#pragma unroll
                for (int jj = 0; jj < 4; jj++) {
                    uint32_t b0 = *(const uint32_t*)&Vh[cur][jj * 8 + g][kh];
                    uint32_t b1 = *(const uint32_t*)&Vh[cur][jj * 8 + g][kh + 8];
                    mma_f16(macc[h][jj], h2u(E0), h2u(E1), h2u(E2), h2u(E3), b0, b1);
                }
            }
            float2 f0 = __half22float2(hsg);
            float2 f1 = __half22float2(hsg8);
            rs[h][0] += f0.x + f0.y;
            rs[h][1] += f1.x + f1.y;
        }
        asm volatile("cp.async.wait_group 0;" ::: "memory");
        __syncthreads();
    }
#pragma unroll
    for (int h = 0; h < 2; h++) {
        float r0v = rs[h][0], r1v = rs[h][1];
        r0v += __shfl_xor_sync(0xffffffffu, r0v, 1);
        r0v += __shfl_xor_sync(0xffffffffu, r0v, 2);
        r1v += __shfl_xor_sync(0xffffffffu, r1v, 1);
        r1v += __shfl_xor_sync(0xffffffffu, r1v, 2);
        if (q == 0) {
            sRS[wn][h * 64 + wm * 16 + g] = r0v;
            sRS[wn][h * 64 + wm * 16 + g + 8] = r1v;
        }
    }
#pragma unroll
    for (int h = 0; h < 2; h++) {
        if (wn == 0) {
#pragma unroll
            for (int jj = 0; jj < 4; jj++) {
                *(float2*)&redM[wm][g][jj * 8 + 2 * q] = make_float2(macc[h][jj].x, macc[h][jj].y);
                *(float2*)&redM[wm][g + 8][jj * 8 + 2 * q] = make_float2(macc[h][jj].z, macc[h][jj].w);
            }
        }
        __syncthreads();
        if (wn == 1) {
            const int r0 = h * 64 + wm * 16 + g, r1 = r0 + 8;
            const float i0 = __frcp_rn(sRS[0][r0] + sRS[1][r0]);
            const float i1 = __frcp_rn(sRS[0][r1] + sRS[1][r1]);
#pragma unroll
            for (int jj = 0; jj < 4; jj++) {
                float2 p0 = *(float2*)&redM[wm][g][jj * 8 + 2 * q];
                float2 p1 = *(float2*)&redM[wm][g + 8][jj * 8 + 2 * q];
                const int c = f * HD + jj * 8 + 2 * q;
                *(__half2*)&OUT[(size_t)(l0 + r0) * CC + c] =
                    __floats2half2_rn((macc[h][jj].x + p0.x) * i0, (macc[h][jj].y + p0.y) * i0);
                *(__half2*)&OUT[(size_t)(l0 + r1) * CC + c] =
                    __floats2half2_rn((macc[h][jj].z + p1.x) * i1, (macc[h][jj].w + p1.y) * i1);
            }
        }
        __syncthreads();
    }
}

// ---------------------------------------------------------------------------
// 3x3 SAME conv, padded fp16 input, cp.async double-buffered (dyn smem).
// grid (CC/64, 64, 2), 256 thr.
// ---------------------------------------------------------------------------
struct ConvSmem {
    __half As[2][66][72];
    __half Bs[2][3][64][72];
};

__global__ void conv3p(const __half* __restrict__ Gp1, const __half* __restrict__ Gp2,
                       const float* __restrict__ bias,
                       float* __restrict__ Out1, float* __restrict__ Out2) {
    extern __shared__ __align__(16) char smem_raw[];
    ConvSmem& S = *reinterpret_cast<ConvSmem*>(smem_raw);
    const __half* Gp = blockIdx.z ? Gp2 : Gp1;
    float* Out = blockIdx.z ? Out2 : Out1;
    const int py = blockIdx.y;
    const int n0 = blockIdx.x * 64;
    const int t = threadIdx.x;
    const int warp = t >> 5, lane = t & 31;
    const int wm = warp >> 1, wn = warp & 1;
    const int g = lane >> 2, q = lane & 3;

    // prefetch macro: phase p = ky*8 + kc
#define CONV_PREFETCH(p, buf)                                                     \
    {                                                                             \
        const int ky = (p) >> 3, kc = (p) & 7, k0 = kc * 64;                      \
        const __half* arow = Gp + (size_t)(py + ky) * GPW * CM;                   \
        const __half* wky = g_WRh + (size_t)(ky * 3) * CC * CM;                   \
        _Pragma("unroll")                                                         \
        for (int i = 0; i < 3; i++) {                                             \
            int idx = t + i * 256;                                                \
            if (idx < 528) {                                                      \
                int row = idx >> 3, c8 = (idx & 7) * 8;                           \
                CP16(sptr(&S.As[buf][row][c8]), arow + (size_t)row * CM + k0 + c8); \
            }                                                                     \
        }                                                                         \
        _Pragma("unroll")                                                         \
        for (int i = 0; i < 6; i++) {                                             \
            int idx = t + i * 256;                                                \
            int kx = idx >> 9, w = idx & 511;                                     \
            int row = w >> 3, c8 = (w & 7) * 8;                                   \
            CP16(sptr(&S.Bs[buf][kx][row][c8]),                                   \
                 wky + (size_t)kx * CC * CM + (size_t)(n0 + row) * CM + k0 + c8); \
        }                                                                         \
    }

    CONV_PREFETCH(0, 0);
    asm volatile("cp.async.commit_group;");
    asm volatile("cp.async.wait_group 0;" ::: "memory");
    __syncthreads();

    float4 acc[4] = {};
    for (int p = 0; p < 24; p++) {
        const int cur = p & 1;
        if (p < 23) {
            CONV_PREFETCH(p + 1, cur ^ 1);
            asm volatile("cp.async.commit_group;");
        }
#pragma unroll
        for (int kx = 0; kx < 3; kx++) {
#pragma unroll
            for (int c = 0; c < 4; c++) {
                const int kh = (c * 8 + q) * 2;
                uint32_t a0 = *(const uint32_t*)&S.As[cur][wm * 16 + g + kx][kh];
                uint32_t a1 = *(const uint32_t*)&S.As[cur][wm * 16 + g + 8 + kx][kh];
                uint32_t a2 = *(const uint32_t*)&S.As[cur][wm * 16 + g + kx][kh + 8];
                uint32_t a3 = *(const uint32_t*)&S.As[cur][wm * 16 + g + 8 + kx][kh + 8];
#pragma unroll
                for (int j = 0; j < 4; j++) {
                    uint32_t b0 = *(const uint32_t*)&S.Bs[cur][kx][wn * 32 + j * 8 + g][kh];
                    uint32_t b1 = *(const uint32_t*)&S.Bs[cur][kx][wn * 32 + j * 8 + g][kh + 8];
                    mma_f16(acc[j], a0, a1, a2, a3, b0, b1);
                }
            }
        }
        asm volatile("cp.async.wait_group 0;" ::: "memory");
        __syncthreads();
    }
    const int p0 = wm * 16 + g, p1 = p0 + 8;
#pragma unroll
    for (int j = 0; j < 4; j++) {
        const int c = n0 + wn * 32 + j * 8 + q * 2;
        float bx = bias[c], by = bias[c + 1];
        *(float2*)&Out[((size_t)py * 64 + p0) * CC + c] =
            make_float2(acc[j].x + bx, acc[j].y + by);
        *(float2*)&Out[((size_t)py * 64 + p1) * CC + c] =
            make_float2(acc[j].z + bx, acc[j].w + by);
    }
}

// ---------------------------------------------------------------------------
// LayerNorm (256 threads = CC, one row per block; blockIdx.y picks pair)
// ---------------------------------------------------------------------------
__device__ __forceinline__ float block_sum_256(float v, volatile float* red) {
#pragma unroll
    for (int o = 16; o > 0; o >>= 1) v += __shfl_xor_sync(0xffffffffu, v, o);
    if ((threadIdx.x & 31) == 0) red[threadIdx.x >> 5] = v;
    __syncthreads();
    float s = red[0] + red[1] + red[2] + red[3] + red[4] + red[5] + red[6] + red[7];
    __syncthreads();
    return s;
}

__global__ void ln_concat_kernel(const float* __restrict__ Min1, const float* __restrict__ Min2,
                                 const float* __restrict__ Xin1, const float* __restrict__ Xin2,
                                 const float* __restrict__ g,
                                 const float* __restrict__ b,
                                 __half* __restrict__ Y1, __half* __restrict__ Y2) {
    __shared__ float red[8];
    const float* Min = blockIdx.y ? Min2 : Min1;
    const float* Xin = blockIdx.y ? Xin2 : Xin1;
    __half* Y = blockIdx.y ? Y2 : Y1;
    const int r = blockIdx.x;
    const int t = threadIdx.x;
    float v = Min[(size_t)r * CC + t];
    float mean = block_sum_256(v, red) * (1.0f / CC);
    float d = v - mean;
    float var = block_sum_256(d * d, red) * (1.0f / CC);
    float o = d * rsqrtf(var + 1e-5f) * g[t] + b[t];
    Y[(size_t)r * CM + 256 + t] = __float2half(o);
    Y[(size_t)r * CM + t] = __float2half(Xin[(size_t)r * CC + t]);
}

__global__ void ln_res_kernel(const float* __restrict__ Cin1, const float* __restrict__ Cin2,
                              const float* __restrict__ Xin1, const float* __restrict__ Xin2,
                              const float* __restrict__ g,
                              const float* __restrict__ b,
                              float* __restrict__ Out1, float* __restrict__ Out2) {
    __shared__ float red[8];
    const float* Cin = blockIdx.y ? Cin2 : Cin1;
    const float* Xin = blockIdx.y ? Xin2 : Xin1;
    float* Out = blockIdx.y ? Out2 : Out1;
    const int r = blockIdx.x;
    const int t = threadIdx.x;
    float v = Cin[(size_t)r * CC + t];
    float mean = block_sum_256(v, red) * (1.0f / CC);
    float d = v - mean;
    float var = block_sum_256(d * d, red) * (1.0f / CC);
    float o = d * rsqrtf(var + 1e-5f) * g[t] + b[t];
    Out[(size_t)r * CC + t] = o + Xin[(size_t)r * CC + t];
}

// ---------------------------------------------------------------------------
// Launch
// ---------------------------------------------------------------------------
extern "C" void kernel_launch(void* const* d_in, const int* in_sizes, int n_in,
                              void* d_out, int out_size) {
    const float* x0 = (const float*)d_in[0];
    const float* x1 = (const float*)d_in[1];
    const float* proj_w = (const float*)d_in[6];
    const float* proj_b = (const float*)d_in[7];
    const float* merge_w = (const float*)d_in[8];
    const float* merge_b = (const float*)d_in[9];
    const float* n0g = (const float*)d_in[10];
    const float* n0b = (const float*)d_in[11];
    const float* lin_w = (const float*)d_in[12];
    const float* lin_b = (const float*)d_in[13];
    const float* conv_w = (const float*)d_in[14];
    const float* conv_b = (const float*)d_in[15];
    const float* n1g = (const float*)d_in[16];
    const float* n1b = (const float*)d_in[17];
    float* out = (float*)d_out;

    void *X0h, *X1h, *PWh, *MWh, *LWh, *P0, *P1, *VT0p, *VT1p, *M0p, *M1p,
         *MM0p, *MM1p, *Y0p, *Y1p, *GP0p, *GP1p, *CV0p, *CV1p;
    cudaGetSymbolAddress(&X0h, g_X0h);
    cudaGetSymbolAddress(&X1h, g_X1h);
    cudaGetSymbolAddress(&PWh, g_PWh);
    cudaGetSymbolAddress(&MWh, g_MWh);
    cudaGetSymbolAddress(&LWh, g_LWh);
    cudaGetSymbolAddress(&P0, g_P0h);
    cudaGetSymbolAddress(&P1, g_P1h);
    cudaGetSymbolAddress(&VT0p, g_VT0);
    cudaGetSymbolAddress(&VT1p, g_VT1);
    cudaGetSymbolAddress(&M0p, g_M0h);
    cudaGetSymbolAddress(&M1p, g_M1h);
    cudaGetSymbolAddress(&MM0p, g_MM0);
    cudaGetSymbolAddress(&MM1p, g_MM1);
    cudaGetSymbolAddress(&Y0p, g_Y0h);
    cudaGetSymbolAddress(&Y1p, g_Y1h);
    cudaGetSymbolAddress(&GP0p, g_GP0);
    cudaGetSymbolAddress(&GP1p, g_GP1);
    cudaGetSymbolAddress(&CV0p, g_CV0);
    cudaGetSymbolAddress(&CV1p, g_CV1);

    cudaFuncSetAttribute(conv3p, cudaFuncAttributeMaxDynamicSharedMemorySize,
                         (int)sizeof(ConvSmem));

    // zero padded conv buffers (borders)
    cudaMemsetAsync(GP0p, 0, (size_t)GPW * GPW * CM * 2);
    cudaMemsetAsync(GP1p, 0, (size_t)GPW * GPW * CM * 2);

    repack_kernel<<<(CC * CM * 9) / 256, 256>>>(conv_w);
    pack_misc<<<(PACK_TOTAL + 255) / 256, 256>>>(proj_w, merge_w, lin_w, x0, x1);

    // proj (both tensors)
    gemm_h<0, 2><<<dim3(CM / 64, LQ / 64, 2), 256>>>(
        (const __half*)X0h, (const __half*)X1h, CC, (const __half*)PWh, CC,
        P0, P1, CM, CC, proj_b);

    vt_pack<<<dim3(LQ / 64, NH, 2), 256>>>(
        (const __half*)P0, (const __half*)P1, (__half*)VT0p, (__half*)VT1p);

    attn_one<<<dim3(LQ / 128, NH, 2), 256>>>(
        (const __half*)P0, (const __half*)P1,
        (const __half*)VT0p, (const __half*)VT1p, (__half*)M0p, (__half*)M1p);

    // merge
    gemm_h<0, 0><<<dim3(CC / 64, LQ / 64, 2), 256>>>(
        (const __half*)M0p, (const __half*)M1p, CC, (const __half*)MWh, CC,
        MM0p, MM1p, CC, CC, merge_b);

    ln_concat_kernel<<<dim3(LQ, 2), 256>>>(
        (const float*)MM0p, (const float*)MM1p, x0, x1, n0g, n0b,
        (__half*)Y0p, (__half*)Y1p);

    // lin + gelu -> padded fp16
    gemm_h<1, 1><<<dim3(CM / 64, LQ / 64, 2), 256>>>(
        (const __half*)Y0p, (const __half*)Y1p, CM, (const __half*)LWh, CM,
        GP0p, GP1p, CM, CM, lin_b);

    conv3p<<<dim3(CC / 64, 64, 2), 256, sizeof(ConvSmem)>>>(
        (const __half*)GP0p, (const __half*)GP1p, conv_b, (float*)CV0p, (float*)CV1p);

    ln_res_kernel<<<dim3(LQ, 2), 256>>>(
        (const float*)CV0p, (const float*)CV1p, x0, x1, n1g, n1b,
        out, out + (size_t)LQ * CC);
}

// round 14
// speedup vs baseline: 13.8531x; 1.0019x over previous
#include <cuda_runtime.h>
#include <cuda_fp16.h>
#include <math.h>
#include <stdint.h>

#define LQ 4096
#define CC 256
#define NH 8
#define HD 32
#define CM 512
#define GPW 66   // padded conv width

// ---------------------------------------------------------------------------
// Scratch
// ---------------------------------------------------------------------------
static __device__ __align__(16) __half g_X0h[LQ * CC];       // x0 fp16
static __device__ __align__(16) __half g_X1h[LQ * CC];       // x1 fp16
static __device__ __align__(16) __half g_PWh[CM * CC];       // proj_w fp16
static __device__ __align__(16) __half g_MWh[CC * CC];       // merge_w fp16
static __device__ __align__(16) __half g_LWh[CM * CM];       // lin_w fp16
static __device__ __align__(16) __half g_P0h[LQ * CM];       // proj(x0), fp16
static __device__ __align__(16) __half g_P1h[LQ * CM];       // proj(x1), fp16
static __device__ __align__(16) __half g_VT0[NH * HD * LQ];  // v0 transposed [f*HD+d][s]
static __device__ __align__(16) __half g_VT1[NH * HD * LQ];  // v1 transposed
static __device__ __align__(16) __half g_M0h[LQ * CC];       // attn out fp16
static __device__ __align__(16) __half g_M1h[LQ * CC];
static __device__ float    g_MM0[LQ * CC];
static __device__ float    g_MM1[LQ * CC];
static __device__ __align__(16) __half g_Y0h[LQ * CM];       // concat fp16
static __device__ __align__(16) __half g_Y1h[LQ * CM];
static __device__ __align__(16) __half g_GP0[GPW * GPW * CM];  // padded gelu(lin), fp16
static __device__ __align__(16) __half g_GP1[GPW * GPW * CM];
static __device__ float    g_CV0[LQ * CC];
static __device__ float    g_CV1[LQ * CC];
static __device__ __align__(16) __half g_WRh[9 * CC * CM];     // conv weights [k9][o][i], fp16

// ---------------------------------------------------------------------------
// helpers
// ---------------------------------------------------------------------------
__device__ __forceinline__ void mma_f16(float4& d, uint32_t a0, uint32_t a1,
                                        uint32_t a2, uint32_t a3,
                                        uint32_t b0, uint32_t b1) {
    asm volatile(
        "mma.sync.aligned.m16n8k16.row.col.f32.f16.f16.f32 "
        "{%0,%1,%2,%3}, {%4,%5,%6,%7}, {%8,%9}, {%0,%1,%2,%3};"
        : "+f"(d.x), "+f"(d.y), "+f"(d.z), "+f"(d.w)
        : "r"(a0), "r"(a1), "r"(a2), "r"(a3), "r"(b0), "r"(b1));
}

__device__ __forceinline__ uint32_t h2u(__half2 h) {
    return *reinterpret_cast<uint32_t*>(&h);
}

__device__ __forceinline__ uint32_t sptr(const void* p) {
    return (uint32_t)__cvta_generic_to_shared(p);
}

__device__ __forceinline__ uint4 ldsm4(uint32_t a) {
    uint4 r;
    asm volatile("ldmatrix.sync.aligned.m8n8.x4.shared.b16 {%0,%1,%2,%3}, [%4];"
                 : "=r"(r.x), "=r"(r.y), "=r"(r.z), "=r"(r.w) : "r"(a));
    return r;
}

#define CP16(dst, src) \
    asm volatile("cp.async.cg.shared.global [%0], [%1], 16;" :: "r"(dst), "l"(src))

// ---------------------------------------------------------------------------
// One-shot fp16 packing of weights + inputs
// ---------------------------------------------------------------------------
__global__ void pack_misc(const float* __restrict__ pw, const float* __restrict__ mw,
                          const float* __restrict__ lw,
                          const float* __restrict__ x0, const float* __restrict__ x1) {
    size_t i = (size_t)blockIdx.x * 256 + threadIdx.x;
    if (i < CM * CC) { g_PWh[i] = __float2half(pw[i]); return; }
    i -= CM * CC;
    if (i < CC * CC) { g_MWh[i] = __float2half(mw[i]); return; }
    i -= CC * CC;
    if (i < CM * CM) { g_LWh[i] = __float2half(lw[i]); return; }
    i -= CM * CM;
    if (i < (size_t)LQ * CC) { g_X0h[i] = __float2half(x0[i]); return; }
    i -= (size_t)LQ * CC;
    g_X1h[i] = __float2half(x1[i]);
}
#define PACK_TOTAL (CM * CC + CC * CC + CM * CM + 2 * LQ * CC)

__global__ void repack_kernel(const float* __restrict__ w) {
    int i = blockIdx.x * 256 + threadIdx.x;
    int o = i / (CM * 9);
    int rem = i % (CM * 9);
    int ci = rem / 9;
    int k9 = rem % 9;
    g_WRh[(size_t)k9 * CC * CM + (size_t)o * CM + ci] = __float2half(w[i]);
}

// ---------------------------------------------------------------------------
// All-fp16 GEMM, cp.async double-buffer. blockIdx.z picks (A,C) pair.
// MODE: 0 = fp32 C, 1 = fp16 C padded conv (+GELU), 2 = fp16 C plain.
// ---------------------------------------------------------------------------
template <int GELU, int MODE>
__global__ void gemm_h(const __half* __restrict__ A1, const __half* __restrict__ A2,
                       int lda,
                       const __half* __restrict__ B, int ldb,
                       void* __restrict__ Cv1, void* __restrict__ Cv2, int ldc,
                       int K, const float* __restrict__ bias) {
    __shared__ __align__(16) __half As[2][64][72];
    __shared__ __align__(16) __half Bs[2][64][72];
    const __half* A = blockIdx.z ? A2 : A1;
    void* Cv = blockIdx.z ? Cv2 : Cv1;
    const int m0 = blockIdx.y * 64;
    const int n0 = blockIdx.x * 64;
    const int t = threadIdx.x;
    const int warp = t >> 5, lane = t & 31;
    const int wm = warp >> 1, wn = warp & 1;
    const int g = lane >> 2, q = lane & 3;
    const int lr = t >> 2, c8 = (t & 3) * 8;
    const int nphase = K >> 5;

    CP16(sptr(&As[0][lr][c8]), A + (size_t)(m0 + lr) * lda + c8);
    CP16(sptr(&Bs[0][lr][c8]), B + (size_t)(n0 + lr) * ldb + c8);
    asm volatile("cp.async.commit_group;");
    asm volatile("cp.async.wait_group 0;" ::: "memory");
    __syncthreads();

    float4 acc[4] = {};
    for (int p = 0; p < nphase; p++) {
        const int cur = p & 1;
        if (p + 1 < nphase) {
            const int k0 = (p + 1) * 32;
            CP16(sptr(&As[cur ^ 1][lr][c8]), A + (size_t)(m0 + lr) * lda + k0 + c8);
            CP16(sptr(&Bs[cur ^ 1][lr][c8]), B + (size_t)(n0 + lr) * ldb + k0 + c8);
            asm volatile("cp.async.commit_group;");
        }
#pragma unroll
        for (int ks = 0; ks < 2; ks++) {
            const int kb = ks * 16;
            uint32_t a0 = *(const uint32_t*)&As[cur][wm * 16 + g][kb + 2 * q];
            uint32_t a1 = *(const uint32_t*)&As[cur][wm * 16 + g + 8][kb + 2 * q];
            uint32_t a2 = *(const uint32_t*)&As[cur][wm * 16 + g][kb + 2 * q + 8];
            uint32_t a3 = *(const uint32_t*)&As[cur][wm * 16 + g + 8][kb + 2 * q + 8];
#pragma unroll
            for (int j = 0; j < 4; j++) {
                uint32_t b0 = *(const uint32_t*)&Bs[cur][wn * 32 + j * 8 + g][kb + 2 * q];
                uint32_t b1 = *(const uint32_t*)&Bs[cur][wn * 32 + j * 8 + g][kb + 2 * q + 8];
                mma_f16(acc[j], a0, a1, a2, a3, b0, b1);
            }
        }
        asm volatile("cp.async.wait_group 0;" ::: "memory");
        __syncthreads();
    }
    const int r0 = m0 + wm * 16 + g, r1 = r0 + 8;
#pragma unroll
    for (int j = 0; j < 4; j++) {
        const int c = n0 + wn * 32 + j * 8 + q * 2;
        float bx = bias ? bias[c] : 0.f, by = bias ? bias[c + 1] : 0.f;
        float v00 = acc[j].x + bx, v01 = acc[j].y + by;
        float v10 = acc[j].z + bx, v11 = acc[j].w + by;
        if (GELU) {
            v00 = 0.5f * v00 * (1.0f + erff(v00 * 0.70710678118f));
            v01 = 0.5f * v01 * (1.0f + erff(v01 * 0.70710678118f));
            v10 = 0.5f * v10 * (1.0f + erff(v10 * 0.70710678118f));
            v11 = 0.5f * v11 * (1.0f + erff(v11 * 0.70710678118f));
        }
        if (MODE == 0) {
            float* C = (float*)Cv;
            *(float2*)&C[(size_t)r0 * ldc + c] = make_float2(v00, v01);
            *(float2*)&C[(size_t)r1 * ldc + c] = make_float2(v10, v11);
        } else if (MODE == 1) {
            __half* C = (__half*)Cv;
            size_t o0 = ((size_t)((r0 >> 6) + 1) * GPW + (r0 & 63) + 1) * CM + c;
            size_t o1 = ((size_t)((r1 >> 6) + 1) * GPW + (r1 & 63) + 1) * CM + c;
            *(__half2*)&C[o0] = __floats2half2_rn(v00, v01);
            *(__half2*)&C[o1] = __floats2half2_rn(v10, v11);
        } else {
            __half* C = (__half*)Cv;
            *(__half2*)&C[(size_t)r0 * ldc + c] = __floats2half2_rn(v00, v01);
            *(__half2*)&C[(size_t)r1 * ldc + c] = __floats2half2_rn(v10, v11);
        }
    }
}

// ---------------------------------------------------------------------------
// VT pack: P's v-half (fp16) -> fp16 transposed VT[f*HD+d][s]; z picks pair.
// ---------------------------------------------------------------------------
__global__ void vt_pack(const __half* __restrict__ Pa, const __half* __restrict__ Pb,
                        __half* __restrict__ VTa, __half* __restrict__ VTb) {
    __shared__ __half Sh[64][33];
    const __half* P = blockIdx.z ? Pb : Pa;
    __half* VT = blockIdx.z ? VTb : VTa;
    const int s0 = blockIdx.x * 64, f = blockIdx.y;
    const int t = threadIdx.x;
    {
        int r = t >> 2, dg = (t & 3) * 8;
        const __half* src = P + (size_t)(s0 + r) * CM + 256 + f * HD + dg;
        uint4 u = *(const uint4*)src;
        const __half* h = (const __half*)&u;
#pragma unroll
        for (int i = 0; i < 8; i++) Sh[r][dg + i] = h[i];
    }
    __syncthreads();
    {
        int d = t >> 3, sg = (t & 7) * 8;
        __half2 p0 = __halves2half2(Sh[sg + 0][d], Sh[sg + 1][d]);
        __half2 p1 = __halves2half2(Sh[sg + 2][d], Sh[sg + 3][d]);
        __half2 p2 = __halves2half2(Sh[sg + 4][d], Sh[sg + 5][d]);
        __half2 p3 = __halves2half2(Sh[sg + 6][d], Sh[sg + 7][d]);
        uint4 u = {h2u(p0), h2u(p1), h2u(p2), h2u(p3)};
        *(uint4*)(VT + (size_t)(f * HD + d) * LQ + s0 + sg) = u;
    }
}

// ---------------------------------------------------------------------------
// One-sided flash attention: fp16, MUFU ex2, 2 l-tiles/block, LDSM B-frags
// shared across the two l-halves. grid (LQ/128, NH, 2), 256 thr.
// ---------------------------------------------------------------------------
#define KBUF (64 * 56 * 2)   // bytes per Kb buffer
#define VBUF (32 * 72 * 2)   // bytes per Vh buffer

__global__ __launch_bounds__(256, 2) void attn_one(
        const __half* __restrict__ P0, const __half* __restrict__ P1,
        const __half* __restrict__ VT0, const __half* __restrict__ VT1,
        __half* __restrict__ M0, __half* __restrict__ M1) {
    __shared__ __align__(16) __half Kb[2][64][56];
    __shared__ __align__(16) __half Vh[2][32][72];
    __shared__ float sRS[2][128];
    __shared__ __align__(8) float redM[4][16][34];
    const int f = blockIdx.y;
    const int l0 = blockIdx.x * 128;
    const int dir = blockIdx.z;
    const __half* A = (dir ? P1 : P0) + f * HD;
    const __half* B = (dir ? P0 : P1) + f * HD;
    const __half* VTf = (dir ? VT0 : VT1) + (size_t)f * HD * LQ;
    __half* OUT = dir ? M1 : M0;
    const int t = threadIdx.x;
    const int warp = t >> 5, lane = t & 31;
    const int wm = warp >> 1, wn = warp & 1;
    const int g = lane >> 2, q = lane & 3;
    const int krow = t >> 2, kc8 = (t & 3) * 8;
    const int vd = t >> 3, vc8 = (t & 7) * 8;
    const int blk = lane >> 3, rowin = lane & 7;

    // LDSM base addresses (buffer 0; add cur*K/VBUF at use)
    uint32_t sa[2][2], va[2][2];
#pragma unroll
    for (int ks = 0; ks < 2; ks++)
#pragma unroll
        for (int grp = 0; grp < 2; grp++)
            sa[ks][grp] = sptr(&Kb[0][wn * 32 + grp * 16 + (blk >> 1) * 8 + rowin]
                                    [ks * 16 + (blk & 1) * 8]);
#pragma unroll
    for (int c = 0; c < 2; c++)
#pragma unroll
        for (int grp = 0; grp < 2; grp++)
            va[c][grp] = sptr(&Vh[0][grp * 16 + (blk >> 1) * 8 + rowin]
                                   [wn * 32 + c * 16 + (blk & 1) * 8]);

    // prefetch s-tile 0 (async)
    CP16(sptr(&Kb[0][krow][kc8]), B + (size_t)krow * CM + kc8);
    CP16(sptr(&Vh[0][vd][vc8]), VTf + (size_t)vd * LQ + vc8);
    asm volatile("cp.async.commit_group;");
    // stage q through Kb[1] (two halves), scale SC*log2e folded in
    const __half2 scl = __float2half2_rn(0.17677669529663687f * 1.4426950408889634f);
    uint32_t aq[2][2][4];
#pragma unroll
    for (int h = 0; h < 2; h++) {
        *(uint4*)&Kb[1][krow][kc8] =
            *(const uint4*)(A + (size_t)(l0 + h * 64 + krow) * CM + kc8);
        __syncthreads();
#pragma unroll
        for (int ks = 0; ks < 2; ks++) {
            const int kb = ks * 16;
            aq[h][ks][0] = h2u(__hmul2(*(const __half2*)&Kb[1][wm * 16 + g][kb + 2 * q], scl));
            aq[h][ks][1] = h2u(__hmul2(*(const __half2*)&Kb[1][wm * 16 + g + 8][kb + 2 * q], scl));
            aq[h][ks][2] = h2u(__hmul2(*(const __half2*)&Kb[1][wm * 16 + g][kb + 2 * q + 8], scl));
            aq[h][ks][3] = h2u(__hmul2(*(const __half2*)&Kb[1][wm * 16 + g + 8][kb + 2 * q + 8], scl));
        }
        __syncthreads();
    }
    asm volatile("cp.async.wait_group 0;" ::: "memory");
    __syncthreads();

    float4 macc[2][4] = {};
    float rs[2][2] = {};

    for (int it = 0; it < 64; it++) {
        const int cur = it & 1;
        if (it < 63) {
            CP16(sptr(&Kb[cur ^ 1][krow][kc8]),
                 B + (size_t)((it + 1) * 64 + krow) * CM + kc8);
            CP16(sptr(&Vh[cur ^ 1][vd][vc8]),
                 VTf + (size_t)vd * LQ + (it + 1) * 64 + vc8);
            asm volatile("cp.async.commit_group;");
        }
        const uint32_t ko = cur * KBUF, vo = cur * VBUF;
        // S phase: both halves; E parked as packed half2 A-frags
        uint32_t Ef[2][2][4];
#pragma unroll
        for (int h = 0; h < 2; h++) {
            float4 sacc[4] = {};
#pragma unroll
            for (int ks = 0; ks < 2; ks++) {
                uint4 f0 = ldsm4(sa[ks][0] + ko);
                uint4 f1 = ldsm4(sa[ks][1] + ko);
                mma_f16(sacc[0], aq[h][ks][0], aq[h][ks][1], aq[h][ks][2], aq[h][ks][3], f0.x, f0.y);
                mma_f16(sacc[1], aq[h][ks][0], aq[h][ks][1], aq[h][ks][2], aq[h][ks][3], f0.z, f0.w);
                mma_f16(sacc[2], aq[h][ks][0], aq[h][ks][1], aq[h][ks][2], aq[h][ks][3], f1.x, f1.y);
                mma_f16(sacc[3], aq[h][ks][0], aq[h][ks][1], aq[h][ks][2], aq[h][ks][3], f1.z, f1.w);
            }
            __half2 hsg = __float2half2_rn(0.f), hsg8 = __float2half2_rn(0.f);
#pragma unroll
            for (int c = 0; c < 2; c++) {
                const float4 sav = sacc[2 * c], sbv = sacc[2 * c + 1];
                __half2 E0 = h2exp2(__floats2half2_rn(sav.x, sav.y));
                __half2 E1 = h2exp2(__floats2half2_rn(sav.z, sav.w));
                __half2 E2 = h2exp2(__floats2half2_rn(sbv.x, sbv.y));
                __half2 E3 = h2exp2(__floats2half2_rn(sbv.z, sbv.w));
                hsg = __hadd2(hsg, __hadd2(E0, E2));
                hsg8 = __hadd2(hsg8, __hadd2(E1, E3));
                Ef[h][c][0] = h2u(E0); Ef[h][c][1] = h2u(E1);
                Ef[h][c][2] = h2u(E2); Ef[h][c][3] = h2u(E3);
            }
            float2 f0 = __half22float2(hsg);
            float2 f1 = __half22float2(hsg8);
            rs[h][0] += f0.x + f0.y;
            rs[h][1] += f1.x + f1.y;
        }
        // AV phase: V frags loaded once, used by both halves
#pragma unroll
        for (int c = 0; c < 2; c++) {
            uint4 v0 = ldsm4(va[c][0] + vo);
            uint4 v1 = ldsm4(va[c][1] + vo);
#pragma unroll
            for (int h = 0; h < 2; h++) {
                mma_f16(macc[h][0], Ef[h][c][0], Ef[h][c][1], Ef[h][c][2], Ef[h][c][3], v0.x, v0.y);
                mma_f16(macc[h][1], Ef[h][c][0], Ef[h][c][1], Ef[h][c][2], Ef[h][c][3], v0.z, v0.w);
                mma_f16(macc[h][2], Ef[h][c][0], Ef[h][c][1], Ef[h][c][2], Ef[h][c][3], v1.x, v1.y);
                mma_f16(macc[h][3], Ef[h][c][0], Ef[h][c][1], Ef[h][c][2], Ef[h][c][3], v1.z, v1.w);
            }
        }
        asm volatile("cp.async.wait_group 0;" ::: "memory");
        __syncthreads();
    }
#pragma unroll
    for (int h = 0; h < 2; h++) {
        float r0v = rs[h][0], r1v = rs[h][1];
        r0v += __shfl_xor_sync(0xffffffffu, r0v, 1);
        r0v += __shfl_xor_sync(0xffffffffu, r0v, 2);
        r1v += __shfl_xor_sync(0xffffffffu, r1v, 1);
        r1v += __shfl_xor_sync(0xffffffffu, r1v, 2);
        if (q == 0) {
            sRS[wn][h * 64 + wm * 16 + g] = r0v;
            sRS[wn][h * 64 + wm * 16 + g + 8] = r1v;
        }
    }
#pragma unroll
    for (int h = 0; h < 2; h++) {
        if (wn == 0) {
#pragma unroll
            for (int jj = 0; jj < 4; jj++) {
                *(float2*)&redM[wm][g][jj * 8 + 2 * q] = make_float2(macc[h][jj].x, macc[h][jj].y);
                *(float2*)&redM[wm][g + 8][jj * 8 + 2 * q] = make_float2(macc[h][jj].z, macc[h][jj].w);
            }
        }
        __syncthreads();
        if (wn == 1) {
            const int r0 = h * 64 + wm * 16 + g, r1 = r0 + 8;
            const float i0 = __frcp_rn(sRS[0][r0] + sRS[1][r0]);
            const float i1 = __frcp_rn(sRS[0][r1] + sRS[1][r1]);
#pragma unroll
            for (int jj = 0; jj < 4; jj++) {
                float2 p0 = *(float2*)&redM[wm][g][jj * 8 + 2 * q];
                float2 p1 = *(float2*)&redM[wm][g + 8][jj * 8 + 2 * q];
                const int c = f * HD + jj * 8 + 2 * q;
                *(__half2*)&OUT[(size_t)(l0 + r0) * CC + c] =
                    __floats2half2_rn((macc[h][jj].x + p0.x) * i0, (macc[h][jj].y + p0.y) * i0);
                *(__half2*)&OUT[(size_t)(l0 + r1) * CC + c] =
                    __floats2half2_rn((macc[h][jj].z + p1.x) * i1, (macc[h][jj].w + p1.y) * i1);
            }
        }
        __syncthreads();
    }
}

// ---------------------------------------------------------------------------
// 3x3 SAME conv, padded fp16 input, cp.async double-buffered (dyn smem).
// ---------------------------------------------------------------------------
struct ConvSmem {
    __half As[2][66][72];
    __half Bs[2][3][64][72];
};

__global__ void conv3p(const __half* __restrict__ Gp1, const __half* __restrict__ Gp2,
                       const float* __restrict__ bias,
                       float* __restrict__ Out1, float* __restrict__ Out2) {
    extern __shared__ __align__(16) char smem_raw[];
    ConvSmem& S = *reinterpret_cast<ConvSmem*>(smem_raw);
    const __half* Gp = blockIdx.z ? Gp2 : Gp1;
    float* Out = blockIdx.z ? Out2 : Out1;
    const int py = blockIdx.y;
    const int n0 = blockIdx.x * 64;
    const int t = threadIdx.x;
    const int warp = t >> 5, lane = t & 31;
    const int wm = warp >> 1, wn = warp & 1;
    const int g = lane >> 2, q = lane & 3;

#define CONV_PREFETCH(p, buf)                                                     \
    {                                                                             \
        const int ky = (p) >> 3, kc = (p) & 7, k0 = kc * 64;                      \
        const __half* arow = Gp + (size_t)(py + ky) * GPW * CM;                   \
        const __half* wky = g_WRh + (size_t)(ky * 3) * CC * CM;                   \
        _Pragma("unroll")                                                         \
        for (int i = 0; i < 3; i++) {                                             \
            int idx = t + i * 256;                                                \
            if (idx < 528) {                                                      \
                int row = idx >> 3, c8 = (idx & 7) * 8;                           \
                CP16(sptr(&S.As[buf][row][c8]), arow + (size_t)row * CM + k0 + c8); \
            }                                                                     \
        }                                                                         \
        _Pragma("unroll")                                                         \
        for (int i = 0; i < 6; i++) {                                             \
            int idx = t + i * 256;                                                \
            int kx = idx >> 9, w = idx & 511;                                     \
            int row = w >> 3, c8 = (w & 7) * 8;                                   \
            CP16(sptr(&S.Bs[buf][kx][row][c8]),                                   \
                 wky + (size_t)kx * CC * CM + (size_t)(n0 + row) * CM + k0 + c8); \
        }                                                                         \
    }

    CONV_PREFETCH(0, 0);
    asm volatile("cp.async.commit_group;");
    asm volatile("cp.async.wait_group 0;" ::: "memory");
    __syncthreads();

    float4 acc[4] = {};
    for (int p = 0; p < 24; p++) {
        const int cur = p & 1;
        if (p < 23) {
            CONV_PREFETCH(p + 1, cur ^ 1);
            asm volatile("cp.async.commit_group;");
        }
#pragma unroll
        for (int kx = 0; kx < 3; kx++) {
#pragma unroll
            for (int c = 0; c < 4; c++) {
                const int kh = (c * 8 + q) * 2;
                uint32_t a0 = *(const uint32_t*)&S.As[cur][wm * 16 + g + kx][kh];
                uint32_t a1 = *(const uint32_t*)&S.As[cur][wm * 16 + g + 8 + kx][kh];
                uint32_t a2 = *(const uint32_t*)&S.As[cur][wm * 16 + g + kx][kh + 8];
                uint32_t a3 = *(const uint32_t*)&S.As[cur][wm * 16 + g + 8 + kx][kh + 8];
#pragma unroll
                for (int j = 0; j < 4; j++) {
                    uint32_t b0 = *(const uint32_t*)&S.Bs[cur][kx][wn * 32 + j * 8 + g][kh];
                    uint32_t b1 = *(const uint32_t*)&S.Bs[cur][kx][wn * 32 + j * 8 + g][kh + 8];
                    mma_f16(acc[j], a0, a1, a2, a3, b0, b1);
                }
            }
        }
        asm volatile("cp.async.wait_group 0;" ::: "memory");
        __syncthreads();
    }
    const int p0 = wm * 16 + g, p1 = p0 + 8;
#pragma unroll
    for (int j = 0; j < 4; j++) {
        const int c = n0 + wn * 32 + j * 8 + q * 2;
        float bx = bias[c], by = bias[c + 1];
        *(float2*)&Out[((size_t)py * 64 + p0) * CC + c] =
            make_float2(acc[j].x + bx, acc[j].y + by);
        *(float2*)&Out[((size_t)py * 64 + p1) * CC + c] =
            make_float2(acc[j].z + bx, acc[j].w + by);
    }
}

// ---------------------------------------------------------------------------
// LayerNorm (256 threads = CC, one row per block; blockIdx.y picks pair)
// ---------------------------------------------------------------------------
__device__ __forceinline__ float block_sum_256(float v, volatile float* red) {
#pragma unroll
    for (int o = 16; o > 0; o >>= 1) v += __shfl_xor_sync(0xffffffffu, v, o);
    if ((threadIdx.x & 31) == 0) red[threadIdx.x >> 5] = v;
    __syncthreads();
    float s = red[0] + red[1] + red[2] + red[3] + red[4] + red[5] + red[6] + red[7];
    __syncthreads();
    return s;
}

__global__ void ln_concat_kernel(const float* __restrict__ Min1, const float* __restrict__ Min2,
                                 const float* __restrict__ Xin1, const float* __restrict__ Xin2,
                                 const float* __restrict__ g,
                                 const float* __restrict__ b,
                                 __half* __restrict__ Y1, __half* __restrict__ Y2) {
    __shared__ float red[8];
    const float* Min = blockIdx.y ? Min2 : Min1;
    const float* Xin = blockIdx.y ? Xin2 : Xin1;
    __half* Y = blockIdx.y ? Y2 : Y1;
    const int r = blockIdx.x;
    const int t = threadIdx.x;
    float v = Min[(size_t)r * CC + t];
    float mean = block_sum_256(v, red) * (1.0f / CC);
    float d = v - mean;
    float var = block_sum_256(d * d, red) * (1.0f / CC);
    float o = d * rsqrtf(var + 1e-5f) * g[t] + b[t];
    Y[(size_t)r * CM + 256 + t] = __float2half(o);
    Y[(size_t)r * CM + t] = __float2half(Xin[(size_t)r * CC + t]);
}

__global__ void ln_res_kernel(const float* __restrict__ Cin1, const float* __restrict__ Cin2,
                              const float* __restrict__ Xin1, const float* __restrict__ Xin2,
                              const float* __restrict__ g,
                              const float* __restrict__ b,
                              float* __restrict__ Out1, float* __restrict__ Out2) {
    __shared__ float red[8];
    const float* Cin = blockIdx.y ? Cin2 : Cin1;
    const float* Xin = blockIdx.y ? Xin2 : Xin1;
    float* Out = blockIdx.y ? Out2 : Out1;
    const int r = blockIdx.x;
    const int t = threadIdx.x;
    float v = Cin[(size_t)r * CC + t];
    float mean = block_sum_256(v, red) * (1.0f / CC);
    float d = v - mean;
    float var = block_sum_256(d * d, red) * (1.0f / CC);
    float o = d * rsqrtf(var + 1e-5f) * g[t] + b[t];
    Out[(size_t)r * CC + t] = o + Xin[(size_t)r * CC + t];
}

// ---------------------------------------------------------------------------
// Launch
// ---------------------------------------------------------------------------
extern "C" void kernel_launch(void* const* d_in, const int* in_sizes, int n_in,
                              void* d_out, int out_size) {
    const float* x0 = (const float*)d_in[0];
    const float* x1 = (const float*)d_in[1];
    const float* proj_w = (const float*)d_in[6];
    const float* proj_b = (const float*)d_in[7];
    const float* merge_w = (const float*)d_in[8];
    const float* merge_b = (const float*)d_in[9];
    const float* n0g = (const float*)d_in[10];
    const float* n0b = (const float*)d_in[11];
    const float* lin_w = (const float*)d_in[12];
    const float* lin_b = (const float*)d_in[13];
    const float* conv_w = (const float*)d_in[14];
    const float* conv_b = (const float*)d_in[15];
    const float* n1g = (const float*)d_in[16];
    const float* n1b = (const float*)d_in[17];
    float* out = (float*)d_out;

    void *X0h, *X1h, *PWh, *MWh, *LWh, *P0, *P1, *VT0p, *VT1p, *M0p, *M1p,
         *MM0p, *MM1p, *Y0p, *Y1p, *GP0p, *GP1p, *CV0p, *CV1p;
    cudaGetSymbolAddress(&X0h, g_X0h);
    cudaGetSymbolAddress(&X1h, g_X1h);
    cudaGetSymbolAddress(&PWh, g_PWh);
    cudaGetSymbolAddress(&MWh, g_MWh);
    cudaGetSymbolAddress(&LWh, g_LWh);
    cudaGetSymbolAddress(&P0, g_P0h);
    cudaGetSymbolAddress(&P1, g_P1h);
    cudaGetSymbolAddress(&VT0p, g_VT0);
    cudaGetSymbolAddress(&VT1p, g_VT1);
    cudaGetSymbolAddress(&M0p, g_M0h);
    cudaGetSymbolAddress(&M1p, g_M1h);
    cudaGetSymbolAddress(&MM0p, g_MM0);
    cudaGetSymbolAddress(&MM1p, g_MM1);
    cudaGetSymbolAddress(&Y0p, g_Y0h);
    cudaGetSymbolAddress(&Y1p, g_Y1h);
    cudaGetSymbolAddress(&GP0p, g_GP0);
    cudaGetSymbolAddress(&GP1p, g_GP1);
    cudaGetSymbolAddress(&CV0p, g_CV0);
    cudaGetSymbolAddress(&CV1p, g_CV1);

    cudaFuncSetAttribute(conv3p, cudaFuncAttributeMaxDynamicSharedMemorySize,
                         (int)sizeof(ConvSmem));

    cudaMemsetAsync(GP0p, 0, (size_t)GPW * GPW * CM * 2);
    cudaMemsetAsync(GP1p, 0, (size_t)GPW * GPW * CM * 2);

    repack_kernel<<<(CC * CM * 9) / 256, 256>>>(conv_w);
    pack_misc<<<(PACK_TOTAL + 255) / 256, 256>>>(proj_w, merge_w, lin_w, x0, x1);

    gemm_h<0, 2><<<dim3(CM / 64, LQ / 64, 2), 256>>>(
        (const __half*)X0h, (const __half*)X1h, CC, (const __half*)PWh, CC,
        P0, P1, CM, CC, proj_b);

    vt_pack<<<dim3(LQ / 64, NH, 2), 256>>>(
        (const __half*)P0, (const __half*)P1, (__half*)VT0p, (__half*)VT1p);

    attn_one<<<dim3(LQ / 128, NH, 2), 256>>>(
        (const __half*)P0, (const __half*)P1,
        (const __half*)VT0p, (const __half*)VT1p, (__half*)M0p, (__half*)M1p);

    gemm_h<0, 0><<<dim3(CC / 64, LQ / 64, 2), 256>>>(
        (const __half*)M0p, (const __half*)M1p, CC, (const __half*)MWh, CC,
        MM0p, MM1p, CC, CC, merge_b);

    ln_concat_kernel<<<dim3(LQ, 2), 256>>>(
        (const float*)MM0p, (const float*)MM1p, x0, x1, n0g, n0b,
        (__half*)Y0p, (__half*)Y1p);

    gemm_h<1, 1><<<dim3(CM / 64, LQ / 64, 2), 256>>>(
        (const __half*)Y0p, (const __half*)Y1p, CM, (const __half*)LWh, CM,
        GP0p, GP1p, CM, CM, lin_b);

    conv3p<<<dim3(CC / 64, 64, 2), 256, sizeof(ConvSmem)>>>(
        (const __half*)GP0p, (const __half*)GP1p, conv_b, (float*)CV0p, (float*)CV1p);

    ln_res_kernel<<<dim3(LQ, 2), 256>>>(
        (const float*)CV0p, (const float*)CV1p, x0, x1, n1g, n1b,
        out, out + (size_t)LQ * CC);
}

// round 17
// speedup vs baseline: 14.4644x; 1.0441x over previous
#include <cuda_runtime.h>
#include <cuda_fp16.h>
#include <math.h>
#include <stdint.h>

#define LQ 4096
#define CC 256
#define NH 8
#define HD 32
#define CM 512
#define GPW 66   // padded conv width

// ---------------------------------------------------------------------------
// Scratch
// ---------------------------------------------------------------------------
static __device__ __align__(16) __half g_X0h[LQ * CC];       // x0 fp16
static __device__ __align__(16) __half g_X1h[LQ * CC];       // x1 fp16
static __device__ __align__(16) __half g_PWh[CM * CC];       // proj_w fp16
static __device__ __align__(16) __half g_MWh[CC * CC];       // merge_w fp16
static __device__ __align__(16) __half g_LWh[CM * CM];       // lin_w fp16
static __device__ __align__(16) __half g_P0h[LQ * CM];       // proj(x0), fp16
static __device__ __align__(16) __half g_P1h[LQ * CM];       // proj(x1), fp16
static __device__ __align__(16) __half g_VT0[NH * HD * LQ];  // v0 transposed [f*HD+d][s]
static __device__ __align__(16) __half g_VT1[NH * HD * LQ];  // v1 transposed
static __device__ __align__(16) __half g_M0h[LQ * CC];       // attn out fp16
static __device__ __align__(16) __half g_M1h[LQ * CC];
static __device__ float    g_MM0[LQ * CC];
static __device__ float    g_MM1[LQ * CC];
static __device__ __align__(16) __half g_Y0h[LQ * CM];       // concat fp16
static __device__ __align__(16) __half g_Y1h[LQ * CM];
static __device__ __align__(16) __half g_GP0[GPW * GPW * CM];  // padded gelu(lin), fp16
static __device__ __align__(16) __half g_GP1[GPW * GPW * CM];
static __device__ float    g_CV0[LQ * CC];
static __device__ float    g_CV1[LQ * CC];
static __device__ __align__(16) __half g_WRh[9 * CC * CM];     // conv weights [k9][o][i], fp16

// ---------------------------------------------------------------------------
// helpers
// ---------------------------------------------------------------------------
__device__ __forceinline__ void mma_f16(float4& d, uint32_t a0, uint32_t a1,
                                        uint32_t a2, uint32_t a3,
                                        uint32_t b0, uint32_t b1) {
    asm volatile(
        "mma.sync.aligned.m16n8k16.row.col.f32.f16.f16.f32 "
        "{%0,%1,%2,%3}, {%4,%5,%6,%7}, {%8,%9}, {%0,%1,%2,%3};"
        : "+f"(d.x), "+f"(d.y), "+f"(d.z), "+f"(d.w)
        : "r"(a0), "r"(a1), "r"(a2), "r"(a3), "r"(b0), "r"(b1));
}

__device__ __forceinline__ uint32_t h2u(__half2 h) {
    return *reinterpret_cast<uint32_t*>(&h);
}

__device__ __forceinline__ uint32_t sptr(const void* p) {
    return (uint32_t)__cvta_generic_to_shared(p);
}

__device__ __forceinline__ uint4 ldsm4(uint32_t a) {
    uint4 r;
    asm volatile("ldmatrix.sync.aligned.m8n8.x4.shared.b16 {%0,%1,%2,%3}, [%4];"
                 : "=r"(r.x), "=r"(r.y), "=r"(r.z), "=r"(r.w) : "r"(a));
    return r;
}

#define CP16(dst, src) \
    asm volatile("cp.async.cg.shared.global [%0], [%1], 16;" :: "r"(dst), "l"(src))

// ---------------------------------------------------------------------------
// One-shot fp16 packing of weights + inputs
// ---------------------------------------------------------------------------
__global__ void pack_misc(const float* __restrict__ pw, const float* __restrict__ mw,
                          const float* __restrict__ lw,
                          const float* __restrict__ x0, const float* __restrict__ x1) {
    size_t i = (size_t)blockIdx.x * 256 + threadIdx.x;
    if (i < CM * CC) { g_PWh[i] = __float2half(pw[i]); return; }
    i -= CM * CC;
    if (i < CC * CC) { g_MWh[i] = __float2half(mw[i]); return; }
    i -= CC * CC;
    if (i < CM * CM) { g_LWh[i] = __float2half(lw[i]); return; }
    i -= CM * CM;
    if (i < (size_t)LQ * CC) { g_X0h[i] = __float2half(x0[i]); return; }
    i -= (size_t)LQ * CC;
    g_X1h[i] = __float2half(x1[i]);
}
#define PACK_TOTAL (CM * CC + CC * CC + CM * CM + 2 * LQ * CC)

__global__ void repack_kernel(const float* __restrict__ w) {
    int i = blockIdx.x * 256 + threadIdx.x;
    int o = i / (CM * 9);
    int rem = i % (CM * 9);
    int ci = rem / 9;
    int k9 = rem % 9;
    g_WRh[(size_t)k9 * CC * CM + (size_t)o * CM + ci] = __float2half(w[i]);
}

// ---------------------------------------------------------------------------
// All-fp16 GEMM, cp.async double-buffer. blockIdx.z picks (A,C) pair.
// MODE: 0 = fp32 C, 1 = fp16 C padded conv (+GELU), 2 = fp16 C plain.
// ---------------------------------------------------------------------------
template <int GELU, int MODE>
__global__ void gemm_h(const __half* __restrict__ A1, const __half* __restrict__ A2,
                       int lda,
                       const __half* __restrict__ B, int ldb,
                       void* __restrict__ Cv1, void* __restrict__ Cv2, int ldc,
                       int K, const float* __restrict__ bias) {
    __shared__ __align__(16) __half As[2][64][72];
    __shared__ __align__(16) __half Bs[2][64][72];
    const __half* A = blockIdx.z ? A2 : A1;
    void* Cv = blockIdx.z ? Cv2 : Cv1;
    const int m0 = blockIdx.y * 64;
    const int n0 = blockIdx.x * 64;
    const int t = threadIdx.x;
    const int warp = t >> 5, lane = t & 31;
    const int wm = warp >> 1, wn = warp & 1;
    const int g = lane >> 2, q = lane & 3;
    const int lr = t >> 2, c8 = (t & 3) * 8;
    const int nphase = K >> 5;

    CP16(sptr(&As[0][lr][c8]), A + (size_t)(m0 + lr) * lda + c8);
    CP16(sptr(&Bs[0][lr][c8]), B + (size_t)(n0 + lr) * ldb + c8);
    asm volatile("cp.async.commit_group;");
    asm volatile("cp.async.wait_group 0;" ::: "memory");
    __syncthreads();

    float4 acc[4] = {};
    for (int p = 0; p < nphase; p++) {
        const int cur = p & 1;
        if (p + 1 < nphase) {
            const int k0 = (p + 1) * 32;
            CP16(sptr(&As[cur ^ 1][lr][c8]), A + (size_t)(m0 + lr) * lda + k0 + c8);
            CP16(sptr(&Bs[cur ^ 1][lr][c8]), B + (size_t)(n0 + lr) * ldb + k0 + c8);
            asm volatile("cp.async.commit_group;");
        }
#pragma unroll
        for (int ks = 0; ks < 2; ks++) {
            const int kb = ks * 16;
            uint32_t a0 = *(const uint32_t*)&As[cur][wm * 16 + g][kb + 2 * q];
            uint32_t a1 = *(const uint32_t*)&As[cur][wm * 16 + g + 8][kb + 2 * q];
            uint32_t a2 = *(const uint32_t*)&As[cur][wm * 16 + g][kb + 2 * q + 8];
            uint32_t a3 = *(const uint32_t*)&As[cur][wm * 16 + g + 8][kb + 2 * q + 8];
#pragma unroll
            for (int j = 0; j < 4; j++) {
                uint32_t b0 = *(const uint32_t*)&Bs[cur][wn * 32 + j * 8 + g][kb + 2 * q];
                uint32_t b1 = *(const uint32_t*)&Bs[cur][wn * 32 + j * 8 + g][kb + 2 * q + 8];
                mma_f16(acc[j], a0, a1, a2, a3, b0, b1);
            }
        }
        asm volatile("cp.async.wait_group 0;" ::: "memory");
        __syncthreads();
    }
    const int r0 = m0 + wm * 16 + g, r1 = r0 + 8;
#pragma unroll
    for (int j = 0; j < 4; j++) {
        const int c = n0 + wn * 32 + j * 8 + q * 2;
        float bx = bias ? bias[c] : 0.f, by = bias ? bias[c + 1] : 0.f;
        float v00 = acc[j].x + bx, v01 = acc[j].y + by;
        float v10 = acc[j].z + bx, v11 = acc[j].w + by;
        if (GELU) {
            v00 = 0.5f * v00 * (1.0f + erff(v00 * 0.70710678118f));
            v01 = 0.5f * v01 * (1.0f + erff(v01 * 0.70710678118f));
            v10 = 0.5f * v10 * (1.0f + erff(v10 * 0.70710678118f));
            v11 = 0.5f * v11 * (1.0f + erff(v11 * 0.70710678118f));
        }
        if (MODE == 0) {
            float* C = (float*)Cv;
            *(float2*)&C[(size_t)r0 * ldc + c] = make_float2(v00, v01);
            *(float2*)&C[(size_t)r1 * ldc + c] = make_float2(v10, v11);
        } else if (MODE == 1) {
            __half* C = (__half*)Cv;
            size_t o0 = ((size_t)((r0 >> 6) + 1) * GPW + (r0 & 63) + 1) * CM + c;
            size_t o1 = ((size_t)((r1 >> 6) + 1) * GPW + (r1 & 63) + 1) * CM + c;
            *(__half2*)&C[o0] = __floats2half2_rn(v00, v01);
            *(__half2*)&C[o1] = __floats2half2_rn(v10, v11);
        } else {
            __half* C = (__half*)Cv;
            *(__half2*)&C[(size_t)r0 * ldc + c] = __floats2half2_rn(v00, v01);
            *(__half2*)&C[(size_t)r1 * ldc + c] = __floats2half2_rn(v10, v11);
        }
    }
}

// ---------------------------------------------------------------------------
// VT pack: P's v-half (fp16) -> fp16 transposed VT[f*HD+d][s]; z picks pair.
// ---------------------------------------------------------------------------
__global__ void vt_pack(const __half* __restrict__ Pa, const __half* __restrict__ Pb,
                        __half* __restrict__ VTa, __half* __restrict__ VTb) {
    __shared__ __half Sh[64][33];
    const __half* P = blockIdx.z ? Pb : Pa;
    __half* VT = blockIdx.z ? VTb : VTa;
    const int s0 = blockIdx.x * 64, f = blockIdx.y;
    const int t = threadIdx.x;
    {
        int r = t >> 2, dg = (t & 3) * 8;
        const __half* src = P + (size_t)(s0 + r) * CM + 256 + f * HD + dg;
        uint4 u = *(const uint4*)src;
        const __half* h = (const __half*)&u;
#pragma unroll
        for (int i = 0; i < 8; i++) Sh[r][dg + i] = h[i];
    }
    __syncthreads();
    {
        int d = t >> 3, sg = (t & 7) * 8;
        __half2 p0 = __halves2half2(Sh[sg + 0][d], Sh[sg + 1][d]);
        __half2 p1 = __halves2half2(Sh[sg + 2][d], Sh[sg + 3][d]);
        __half2 p2 = __halves2half2(Sh[sg + 4][d], Sh[sg + 5][d]);
        __half2 p3 = __halves2half2(Sh[sg + 6][d], Sh[sg + 7][d]);
        uint4 u = {h2u(p0), h2u(p1), h2u(p2), h2u(p3)};
        *(uint4*)(VT + (size_t)(f * HD + d) * LQ + s0 + sg) = u;
    }
}

// ---------------------------------------------------------------------------
// One-sided flash attention: fp16, MUFU ex2, 2 l-tiles/block, LDSM B-frags
// shared across the two l-halves. grid (LQ/128, NH, 2), 256 thr.
// ---------------------------------------------------------------------------
#define KBUF (64 * 56 * 2)   // bytes per Kb buffer
#define VBUF (32 * 72 * 2)   // bytes per Vh buffer

__global__ __launch_bounds__(256, 2) void attn_one(
        const __half* __restrict__ P0, const __half* __restrict__ P1,
        const __half* __restrict__ VT0, const __half* __restrict__ VT1,
        __half* __restrict__ M0, __half* __restrict__ M1) {
    __shared__ __align__(16) __half Kb[2][64][56];
    __shared__ __align__(16) __half Vh[2][32][72];
    __shared__ float sRS[2][128];
    __shared__ __align__(8) float redM[4][16][34];
    const int f = blockIdx.y;
    const int l0 = blockIdx.x * 128;
    const int dir = blockIdx.z;
    const __half* A = (dir ? P1 : P0) + f * HD;
    const __half* B = (dir ? P0 : P1) + f * HD;
    const __half* VTf = (dir ? VT0 : VT1) + (size_t)f * HD * LQ;
    __half* OUT = dir ? M1 : M0;
    const int t = threadIdx.x;
    const int warp = t >> 5, lane = t & 31;
    const int wm = warp >> 1, wn = warp & 1;
    const int g = lane >> 2, q = lane & 3;
    const int krow = t >> 2, kc8 = (t & 3) * 8;
    const int vd = t >> 3, vc8 = (t & 7) * 8;
    const int blk = lane >> 3, rowin = lane & 7;

    uint32_t sa[2][2], va[2][2];
#pragma unroll
    for (int ks = 0; ks < 2; ks++)
#pragma unroll
        for (int grp = 0; grp < 2; grp++)
            sa[ks][grp] = sptr(&Kb[0][wn * 32 + grp * 16 + (blk >> 1) * 8 + rowin]
                                    [ks * 16 + (blk & 1) * 8]);
#pragma unroll
    for (int c = 0; c < 2; c++)
#pragma unroll
        for (int grp = 0; grp < 2; grp++)
            va[c][grp] = sptr(&Vh[0][grp * 16 + (blk >> 1) * 8 + rowin]
                                   [wn * 32 + c * 16 + (blk & 1) * 8]);

    CP16(sptr(&Kb[0][krow][kc8]), B + (size_t)krow * CM + kc8);
    CP16(sptr(&Vh[0][vd][vc8]), VTf + (size_t)vd * LQ + vc8);
    asm volatile("cp.async.commit_group;");
    const __half2 scl = __float2half2_rn(0.17677669529663687f * 1.4426950408889634f);
    uint32_t aq[2][2][4];
#pragma unroll
    for (int h = 0; h < 2; h++) {
        *(uint4*)&Kb[1][krow][kc8] =
            *(const uint4*)(A + (size_t)(l0 + h * 64 + krow) * CM + kc8);
        __syncthreads();
#pragma unroll
        for (int ks = 0; ks < 2; ks++) {
            const int kb = ks * 16;
            aq[h][ks][0] = h2u(__hmul2(*(const __half2*)&Kb[1][wm * 16 + g][kb + 2 * q], scl));
            aq[h][ks][1] = h2u(__hmul2(*(const __half2*)&Kb[1][wm * 16 + g + 8][kb + 2 * q], scl));
            aq[h][ks][2] = h2u(__hmul2(*(const __half2*)&Kb[1][wm * 16 + g][kb + 2 * q + 8], scl));
            aq[h][ks][3] = h2u(__hmul2(*(const __half2*)&Kb[1][wm * 16 + g + 8][kb + 2 * q + 8], scl));
        }
        __syncthreads();
    }
    asm volatile("cp.async.wait_group 0;" ::: "memory");
    __syncthreads();

    float4 macc[2][4] = {};
    float rs[2][2] = {};

    for (int it = 0; it < 64; it++) {
        const int cur = it & 1;
        if (it < 63) {
            CP16(sptr(&Kb[cur ^ 1][krow][kc8]),
                 B + (size_t)((it + 1) * 64 + krow) * CM + kc8);
            CP16(sptr(&Vh[cur ^ 1][vd][vc8]),
                 VTf + (size_t)vd * LQ + (it + 1) * 64 + vc8);
            asm volatile("cp.async.commit_group;");
        }
        const uint32_t ko = cur * KBUF, vo = cur * VBUF;
        uint32_t Ef[2][2][4];
#pragma unroll
        for (int h = 0; h < 2; h++) {
            float4 sacc[4] = {};
#pragma unroll
            for (int ks = 0; ks < 2; ks++) {
                uint4 f0 = ldsm4(sa[ks][0] + ko);
                uint4 f1 = ldsm4(sa[ks][1] + ko);
                mma_f16(sacc[0], aq[h][ks][0], aq[h][ks][1], aq[h][ks][2], aq[h][ks][3], f0.x, f0.y);
                mma_f16(sacc[1], aq[h][ks][0], aq[h][ks][1], aq[h][ks][2], aq[h][ks][3], f0.z, f0.w);
                mma_f16(sacc[2], aq[h][ks][0], aq[h][ks][1], aq[h][ks][2], aq[h][ks][3], f1.x, f1.y);
                mma_f16(sacc[3], aq[h][ks][0], aq[h][ks][1], aq[h][ks][2], aq[h][ks][3], f1.z, f1.w);
            }
            __half2 hsg = __float2half2_rn(0.f), hsg8 = __float2half2_rn(0.f);
#pragma unroll
            for (int c = 0; c < 2; c++) {
                const float4 sav = sacc[2 * c], sbv = sacc[2 * c + 1];
                __half2 E0 = h2exp2(__floats2half2_rn(sav.x, sav.y));
                __half2 E1 = h2exp2(__floats2half2_rn(sav.z, sav.w));
                __half2 E2 = h2exp2(__floats2half2_rn(sbv.x, sbv.y));
                __half2 E3 = h2exp2(__floats2half2_rn(sbv.z, sbv.w));
                hsg = __hadd2(hsg, __hadd2(E0, E2));
                hsg8 = __hadd2(hsg8, __hadd2(E1, E3));
                Ef[h][c][0] = h2u(E0); Ef[h][c][1] = h2u(E1);
                Ef[h][c][2] = h2u(E2); Ef[h][c][3] = h2u(E3);
            }
            float2 f0 = __half22float2(hsg);
            float2 f1 = __half22float2(hsg8);
            rs[h][0] += f0.x + f0.y;
            rs[h][1] += f1.x + f1.y;
        }
#pragma unroll
        for (int c = 0; c < 2; c++) {
            uint4 v0 = ldsm4(va[c][0] + vo);
            uint4 v1 = ldsm4(va[c][1] + vo);
#pragma unroll
            for (int h = 0; h < 2; h++) {
                mma_f16(macc[h][0], Ef[h][c][0], Ef[h][c][1], Ef[h][c][2], Ef[h][c][3], v0.x, v0.y);
                mma_f16(macc[h][1], Ef[h][c][0], Ef[h][c][1], Ef[h][c][2], Ef[h][c][3], v0.z, v0.w);
                mma_f16(macc[h][2], Ef[h][c][0], Ef[h][c][1], Ef[h][c][2], Ef[h][c][3], v1.x, v1.y);
                mma_f16(macc[h][3], Ef[h][c][0], Ef[h][c][1], Ef[h][c][2], Ef[h][c][3], v1.z, v1.w);
            }
        }
        asm volatile("cp.async.wait_group 0;" ::: "memory");
        __syncthreads();
    }
#pragma unroll
    for (int h = 0; h < 2; h++) {
        float r0v = rs[h][0], r1v = rs[h][1];
        r0v += __shfl_xor_sync(0xffffffffu, r0v, 1);
        r0v += __shfl_xor_sync(0xffffffffu, r0v, 2);
        r1v += __shfl_xor_sync(0xffffffffu, r1v, 1);
        r1v += __shfl_xor_sync(0xffffffffu, r1v, 2);
        if (q == 0) {
            sRS[wn][h * 64 + wm * 16 + g] = r0v;
            sRS[wn][h * 64 + wm * 16 + g + 8] = r1v;
        }
    }
#pragma unroll
    for (int h = 0; h < 2; h++) {
        if (wn == 0) {
#pragma unroll
            for (int jj = 0; jj < 4; jj++) {
                *(float2*)&redM[wm][g][jj * 8 + 2 * q] = make_float2(macc[h][jj].x, macc[h][jj].y);
                *(float2*)&redM[wm][g + 8][jj * 8 + 2 * q] = make_float2(macc[h][jj].z, macc[h][jj].w);
            }
        }
        __syncthreads();
        if (wn == 1) {
            const int r0 = h * 64 + wm * 16 + g, r1 = r0 + 8;
            const float i0 = __frcp_rn(sRS[0][r0] + sRS[1][r0]);
            const float i1 = __frcp_rn(sRS[0][r1] + sRS[1][r1]);
#pragma unroll
            for (int jj = 0; jj < 4; jj++) {
                float2 p0 = *(float2*)&redM[wm][g][jj * 8 + 2 * q];
                float2 p1 = *(float2*)&redM[wm][g + 8][jj * 8 + 2 * q];
                const int c = f * HD + jj * 8 + 2 * q;
                *(__half2*)&OUT[(size_t)(l0 + r0) * CC + c] =
                    __floats2half2_rn((macc[h][jj].x + p0.x) * i0, (macc[h][jj].y + p0.y) * i0);
                *(__half2*)&OUT[(size_t)(l0 + r1) * CC + c] =
                    __floats2half2_rn((macc[h][jj].z + p1.x) * i1, (macc[h][jj].w + p1.y) * i1);
            }
        }
        __syncthreads();
    }
}

// ---------------------------------------------------------------------------
// 3x3 SAME conv, padded fp16 input, cp.async double-buffered, LDSM fragments.
// grid (CC/64, 64, 2), 256 thr.
// ---------------------------------------------------------------------------
struct ConvSmem {
    __half As[2][66][72];
    __half Bs[2][3][64][72];
};
#define CABUF (66 * 72 * 2)       // bytes per As buffer
#define CBBUF (3 * 64 * 72 * 2)   // bytes per Bs buffer
#define CBKX  (64 * 72 * 2)       // bytes per kx slab in Bs

__global__ void conv3p(const __half* __restrict__ Gp1, const __half* __restrict__ Gp2,
                       const float* __restrict__ bias,
                       float* __restrict__ Out1, float* __restrict__ Out2) {
    extern __shared__ __align__(16) char smem_raw[];
    ConvSmem& S = *reinterpret_cast<ConvSmem*>(smem_raw);
    const __half* Gp = blockIdx.z ? Gp2 : Gp1;
    float* Out = blockIdx.z ? Out2 : Out1;
    const int py = blockIdx.y;
    const int n0 = blockIdx.x * 64;
    const int t = threadIdx.x;
    const int warp = t >> 5, lane = t & 31;
    const int wm = warp >> 1, wn = warp & 1;
    const int g = lane >> 2, q = lane & 3;
    const int blk = lane >> 3, rowin = lane & 7;

    const uint32_t aAddr =
        sptr(&S.As[0][wm * 16 + (blk & 1) * 8 + rowin][(blk >> 1) * 8]);
    const uint32_t bAddr0 =
        sptr(&S.Bs[0][0][wn * 32 + (blk >> 1) * 8 + rowin][(blk & 1) * 8]);

#define CONV_PREFETCH(p, buf)                                                     \
    {                                                                             \
        const int ky = (p) >> 3, kc = (p) & 7, k0 = kc * 64;                      \
        const __half* arow = Gp + (size_t)(py + ky) * GPW * CM;                   \
        const __half* wky = g_WRh + (size_t)(ky * 3) * CC * CM;                   \
        _Pragma("unroll")                                                         \
        for (int i = 0; i < 3; i++) {                                             \
            int idx = t + i * 256;                                                \
            if (idx < 528) {                                                      \
                int row = idx >> 3, c8 = (idx & 7) * 8;                           \
                CP16(sptr(&S.As[buf][row][c8]), arow + (size_t)row * CM + k0 + c8); \
            }                                                                     \
        }                                                                         \
        _Pragma("unroll")                                                         \
        for (int i = 0; i < 6; i++) {                                             \
            int idx = t + i * 256;                                                \
            int kx = idx >> 9, w = idx & 511;                                     \
            int row = w >> 3, c8 = (w & 7) * 8;                                   \
            CP16(sptr(&S.Bs[buf][kx][row][c8]),                                   \
                 wky + (size_t)kx * CC * CM + (size_t)(n0 + row) * CM + k0 + c8); \
        }                                                                         \
    }

    CONV_PREFETCH(0, 0);
    asm volatile("cp.async.commit_group;");
    asm volatile("cp.async.wait_group 0;" ::: "memory");
    __syncthreads();

    float4 acc[4] = {};
    for (int p = 0; p < 24; p++) {
        const int cur = p & 1;
        if (p < 23) {
            CONV_PREFETCH(p + 1, cur ^ 1);
            asm volatile("cp.async.commit_group;");
        }
        const uint32_t ao = aAddr + cur * CABUF;
        const uint32_t bo = bAddr0 + cur * CBBUF;
#pragma unroll
        for (int kx = 0; kx < 3; kx++) {
#pragma unroll
            for (int c = 0; c < 4; c++) {
                uint4 af = ldsm4(ao + kx * 144 + c * 32);
                uint4 bf0 = ldsm4(bo + kx * CBKX + c * 32);
                uint4 bf1 = ldsm4(bo + kx * CBKX + 16 * 144 + c * 32);
                mma_f16(acc[0], af.x, af.y, af.z, af.w, bf0.x, bf0.y);
                mma_f16(acc[1], af.x, af.y, af.z, af.w, bf0.z, bf0.w);
                mma_f16(acc[2], af.x, af.y, af.z, af.w, bf1.x, bf1.y);
                mma_f16(acc[3], af.x, af.y, af.z, af.w, bf1.z, bf1.w);
            }
        }
        asm volatile("cp.async.wait_group 0;" ::: "memory");
        __syncthreads();
    }
    const int p0 = wm * 16 + g, p1 = p0 + 8;
#pragma unroll
    for (int j = 0; j < 4; j++) {
        const int c = n0 + wn * 32 + j * 8 + q * 2;
        float bx = bias[c], by = bias[c + 1];
        *(float2*)&Out[((size_t)py * 64 + p0) * CC + c] =
            make_float2(acc[j].x + bx, acc[j].y + by);
        *(float2*)&Out[((size_t)py * 64 + p1) * CC + c] =
            make_float2(acc[j].z + bx, acc[j].w + by);
    }
}

// ---------------------------------------------------------------------------
// LayerNorm (256 threads = CC, one row per block; blockIdx.y picks pair)
// ---------------------------------------------------------------------------
__device__ __forceinline__ float block_sum_256(float v, volatile float* red) {
#pragma unroll
    for (int o = 16; o > 0; o >>= 1) v += __shfl_xor_sync(0xffffffffu, v, o);
    if ((threadIdx.x & 31) == 0) red[threadIdx.x >> 5] = v;
    __syncthreads();
    float s = red[0] + red[1] + red[2] + red[3] + red[4] + red[5] + red[6] + red[7];
    __syncthreads();
    return s;
}

__global__ void ln_concat_kernel(const float* __restrict__ Min1, const float* __restrict__ Min2,
                                 const float* __restrict__ Xin1, const float* __restrict__ Xin2,
                                 const float* __restrict__ g,
                                 const float* __restrict__ b,
                                 __half* __restrict__ Y1, __half* __restrict__ Y2) {
    __shared__ float red[8];
    const float* Min = blockIdx.y ? Min2 : Min1;
    const float* Xin = blockIdx.y ? Xin2 : Xin1;
    __half* Y = blockIdx.y ? Y2 : Y1;
    const int r = blockIdx.x;
    const int t = threadIdx.x;
    float v = Min[(size_t)r * CC + t];
    float mean = block_sum_256(v, red) * (1.0f / CC);
    float d = v - mean;
    float var = block_sum_256(d * d, red) * (1.0f / CC);
    float o = d * rsqrtf(var + 1e-5f) * g[t] + b[t];
    Y[(size_t)r * CM + 256 + t] = __float2half(o);
    Y[(size_t)r * CM + t] = __float2half(Xin[(size_t)r * CC + t]);
}

__global__ void ln_res_kernel(const float* __restrict__ Cin1, const float* __restrict__ Cin2,
                              const float* __restrict__ Xin1, const float* __restrict__ Xin2,
                              const float* __restrict__ g,
                              const float* __restrict__ b,
                              float* __restrict__ Out1, float* __restrict__ Out2) {
    __shared__ float red[8];
    const float* Cin = blockIdx.y ? Cin2 : Cin1;
    const float* Xin = blockIdx.y ? Xin2 : Xin1;
    float* Out = blockIdx.y ? Out2 : Out1;
    const int r = blockIdx.x;
    const int t = threadIdx.x;
    float v = Cin[(size_t)r * CC + t];
    float mean = block_sum_256(v, red) * (1.0f / CC);
    float d = v - mean;
    float var = block_sum_256(d * d, red) * (1.0f / CC);
    float o = d * rsqrtf(var + 1e-5f) * g[t] + b[t];
    Out[(size_t)r * CC + t] = o + Xin[(size_t)r * CC + t];
}

// ---------------------------------------------------------------------------
// Launch
// ---------------------------------------------------------------------------
extern "C" void kernel_launch(void* const* d_in, const int* in_sizes, int n_in,
                              void* d_out, int out_size) {
    const float* x0 = (const float*)d_in[0];
    const float* x1 = (const float*)d_in[1];
    const float* proj_w = (const float*)d_in[6];
    const float* proj_b = (const float*)d_in[7];
    const float* merge_w = (const float*)d_in[8];
    const float* merge_b = (const float*)d_in[9];
    const float* n0g = (const float*)d_in[10];
    const float* n0b = (const float*)d_in[11];
    const float* lin_w = (const float*)d_in[12];
    const float* lin_b = (const float*)d_in[13];
    const float* conv_w = (const float*)d_in[14];
    const float* conv_b = (const float*)d_in[15];
    const float* n1g = (const float*)d_in[16];
    const float* n1b = (const float*)d_in[17];
    float* out = (float*)d_out;

    void *X0h, *X1h, *PWh, *MWh, *LWh, *P0, *P1, *VT0p, *VT1p, *M0p, *M1p,
         *MM0p, *MM1p, *Y0p, *Y1p, *GP0p, *GP1p, *CV0p, *CV1p;
    cudaGetSymbolAddress(&X0h, g_X0h);
    cudaGetSymbolAddress(&X1h, g_X1h);
    cudaGetSymbolAddress(&PWh, g_PWh);
    cudaGetSymbolAddress(&MWh, g_MWh);
    cudaGetSymbolAddress(&LWh, g_LWh);
    cudaGetSymbolAddress(&P0, g_P0h);
    cudaGetSymbolAddress(&P1, g_P1h);
    cudaGetSymbolAddress(&VT0p, g_VT0);
    cudaGetSymbolAddress(&VT1p, g_VT1);
    cudaGetSymbolAddress(&M0p, g_M0h);
    cudaGetSymbolAddress(&M1p, g_M1h);
    cudaGetSymbolAddress(&MM0p, g_MM0);
    cudaGetSymbolAddress(&MM1p, g_MM1);
    cudaGetSymbolAddress(&Y0p, g_Y0h);
    cudaGetSymbolAddress(&Y1p, g_Y1h);
    cudaGetSymbolAddress(&GP0p, g_GP0);
    cudaGetSymbolAddress(&GP1p, g_GP1);
    cudaGetSymbolAddress(&CV0p, g_CV0);
    cudaGetSymbolAddress(&CV1p, g_CV1);

    cudaFuncSetAttribute(conv3p, cudaFuncAttributeMaxDynamicSharedMemorySize,
                         (int)sizeof(ConvSmem));

    cudaMemsetAsync(GP0p, 0, (size_t)GPW * GPW * CM * 2);
    cudaMemsetAsync(GP1p, 0, (size_t)GPW * GPW * CM * 2);

    repack_kernel<<<(CC * CM * 9) / 256, 256>>>(conv_w);
    pack_misc<<<(PACK_TOTAL + 255) / 256, 256>>>(proj_w, merge_w, lin_w, x0, x1);

    gemm_h<0, 2><<<dim3(CM / 64, LQ / 64, 2), 256>>>(
        (const __half*)X0h, (const __half*)X1h, CC, (const __half*)PWh, CC,
        P0, P1, CM, CC, proj_b);

    vt_pack<<<dim3(LQ / 64, NH, 2), 256>>>(
        (const __half*)P0, (const __half*)P1, (__half*)VT0p, (__half*)VT1p);

    attn_one<<<dim3(LQ / 128, NH, 2), 256>>>(
        (const __half*)P0, (const __half*)P1,
        (const __half*)VT0p, (const __half*)VT1p, (__half*)M0p, (__half*)M1p);

    gemm_h<0, 0><<<dim3(CC / 64, LQ / 64, 2), 256>>>(
        (const __half*)M0p, (const __half*)M1p, CC, (const __half*)MWh, CC,
        MM0p, MM1p, CC, CC, merge_b);

    ln_concat_kernel<<<dim3(LQ, 2), 256>>>(
        (const float*)MM0p, (const float*)MM1p, x0, x1, n0g, n0b,
        (__half*)Y0p, (__half*)Y1p);

    gemm_h<1, 1><<<dim3(CM / 64, LQ / 64, 2), 256>>>(
        (const __half*)Y0p, (const __half*)Y1p, CM, (const __half*)LWh, CM,
        GP0p, GP1p, CM, CM, lin_b);

    conv3p<<<dim3(CC / 64, 64, 2), 256, sizeof(ConvSmem)>>>(
        (const __half*)GP0p, (const __half*)GP1p, conv_b, (float*)CV0p, (float*)CV1p);

    ln_res_kernel<<<dim3(LQ, 2), 256>>>(
        (const float*)CV0p, (const float*)CV1p, x0, x1, n1g, n1b,
        out, out + (size_t)LQ * CC);
}